// round 2
// baseline (speedup 1.0000x reference)
#include <cuda_runtime.h>
#include <cuda_bf16.h>

#define BB 8
#define HH 256
#define WW 256
#define CC 32
#define NPIXTOT (BB*HH*WW)

// ---------------- scratch (device globals; no allocation allowed) ----------
__device__ float g_cat[2ull * NPIXTOT * 64];
__device__ float g_c0[2ull * NPIXTOT * 32];
__device__ float g_flowch[2ull * NPIXTOT * 2];

// ---------------- warp + concat ------------------------------------------
__global__ __launch_bounds__(256) void warpcat_kernel(
    const float* __restrict__ src, const float* __restrict__ other,
    const float* __restrict__ flow, float* __restrict__ cat)
{
    int idx = blockIdx.x * blockDim.x + threadIdx.x;   // NPIXTOT*16 threads
    int q   = idx & 15;
    int pix = idx >> 4;
    if (q < 8) {
        float4 v = ((const float4*)other)[pix * 8 + q];
        ((float4*)cat)[pix * 16 + q] = v;
        return;
    }
    int c4 = q - 8;
    int x = pix & (WW - 1);
    int y = (pix >> 8) & (HH - 1);
    int b = pix >> 16;
    float2 f = ((const float2*)flow)[pix];
    float qy = (float)y - f.x;
    float qx = (float)x - f.y;
    float fy = fminf(fmaxf(floorf(qy), 0.f), (float)(HH - 2));
    float fx = fminf(fmaxf(floorf(qx), 0.f), (float)(WW - 2));
    float ay = fminf(fmaxf(qy - fy, 0.f), 1.f);
    float ax = fminf(fmaxf(qx - fx, 0.f), 1.f);
    int iy = (int)fy, ix = (int)fx;
    const float4* s4 = (const float4*)src;
    int base = ((b * HH + iy) * WW + ix) * 8 + c4;
    float4 tl = s4[base];
    float4 tr = s4[base + 8];
    float4 bl = s4[base + WW * 8];
    float4 br = s4[base + WW * 8 + 8];
    float4 top, bot, r;
    top.x = tl.x + ax * (tr.x - tl.x); top.y = tl.y + ax * (tr.y - tl.y);
    top.z = tl.z + ax * (tr.z - tl.z); top.w = tl.w + ax * (tr.w - tl.w);
    bot.x = bl.x + ax * (br.x - bl.x); bot.y = bl.y + ax * (br.y - bl.y);
    bot.z = bl.z + ax * (br.z - bl.z); bot.w = bl.w + ax * (br.w - bl.w);
    r.x = top.x + ay * (bot.x - top.x); r.y = top.y + ay * (bot.y - top.y);
    r.z = top.z + ay * (bot.z - top.z); r.w = top.w + ay * (bot.w - top.w);
    ((float4*)cat)[pix * 16 + 8 + c4] = r;
}

// ---------------- final warp (32 ch, direct to output) --------------------
__global__ __launch_bounds__(256) void warp_kernel(
    const float* __restrict__ src, const float* __restrict__ flow,
    float* __restrict__ out)
{
    int idx = blockIdx.x * blockDim.x + threadIdx.x;   // NPIXTOT*8 threads
    int c4  = idx & 7;
    int pix = idx >> 3;
    int x = pix & (WW - 1);
    int y = (pix >> 8) & (HH - 1);
    int b = pix >> 16;
    float2 f = ((const float2*)flow)[pix];
    float qy = (float)y - f.x;
    float qx = (float)x - f.y;
    float fy = fminf(fmaxf(floorf(qy), 0.f), (float)(HH - 2));
    float fx = fminf(fmaxf(floorf(qx), 0.f), (float)(WW - 2));
    float ay = fminf(fmaxf(qy - fy, 0.f), 1.f);
    float ax = fminf(fmaxf(qx - fx, 0.f), 1.f);
    int iy = (int)fy, ix = (int)fx;
    const float4* s4 = (const float4*)src;
    int base = ((b * HH + iy) * WW + ix) * 8 + c4;
    float4 tl = s4[base];
    float4 tr = s4[base + 8];
    float4 bl = s4[base + WW * 8];
    float4 br = s4[base + WW * 8 + 8];
    float4 top, bot, r;
    top.x = tl.x + ax * (tr.x - tl.x); top.y = tl.y + ax * (tr.y - tl.y);
    top.z = tl.z + ax * (tr.z - tl.z); top.w = tl.w + ax * (tr.w - tl.w);
    bot.x = bl.x + ax * (br.x - bl.x); bot.y = bl.y + ax * (br.y - bl.y);
    bot.z = bl.z + ax * (br.z - bl.z); bot.w = bl.w + ax * (br.w - bl.w);
    r.x = top.x + ay * (bot.x - top.x); r.y = top.y + ay * (bot.y - top.y);
    r.z = top.z + ay * (bot.z - top.z); r.w = top.w + ay * (bot.w - top.w);
    ((float4*)out)[pix * 8 + c4] = r;
}

// ---------------- 3x3 conv (SAME, relu) -----------------------------------
template<int CIN, int COUT>
__global__ __launch_bounds__(256) void conv3x3_kernel(
    const float* __restrict__ in, const float* __restrict__ wsrc,
    const float* __restrict__ bias, float* __restrict__ out)
{
    constexpr int TX = 16, TY = 8;
    constexpr int TILE_W = TX + 2;
    constexpr int C4 = CIN / 4;
    constexpr int NOC = COUT / 32;

    extern __shared__ float sm[];
    float* stile = sm;                              // (TY+2)*TILE_W*CIN
    float* sw    = sm + (TY + 2) * TILE_W * CIN;    // 9*CIN*COUT
    float* sb    = sw + 9 * CIN * COUT;             // COUT

    const int bx = blockIdx.x * TX;
    const int by = blockIdx.y * TY;
    const int b  = blockIdx.z;
    const int tid = threadIdx.x;

    {
        const float4* w4 = (const float4*)wsrc;
        float4* sw4 = (float4*)sw;
        constexpr int WN = 9 * CIN * COUT / 4;
        for (int i = tid; i < WN; i += 256) sw4[i] = w4[i];
        if (tid < COUT) sb[tid] = bias[tid];
    }
    {
        constexpr int TN = (TY + 2) * TILE_W * C4;
        float4* st4 = (float4*)stile;
        for (int i = tid; i < TN; i += 256) {
            int c4  = i % C4;
            int p   = i / C4;
            int txx = p % TILE_W;
            int tyy = p / TILE_W;
            int gx = bx + txx - 1;
            int gy = by + tyy - 1;
            float4 v = make_float4(0.f, 0.f, 0.f, 0.f);
            if (gx >= 0 && gx < WW && gy >= 0 && gy < HH)
                v = ((const float4*)in)[((b * HH + gy) * WW + gx) * C4 + c4];
            st4[i] = v;
        }
    }
    __syncthreads();

    const int oc = tid & 31;
    const int ty = tid >> 5;

    float acc[NOC][TX];
    #pragma unroll
    for (int n = 0; n < NOC; n++)
        #pragma unroll
        for (int p = 0; p < TX; p++) acc[n][p] = sb[oc + 32 * n];

    #pragma unroll 1
    for (int dy = 0; dy < 3; dy++) {
        #pragma unroll 1
        for (int dx = 0; dx < 3; dx++) {
            const float* trow = stile + ((ty + dy) * TILE_W + dx) * CIN;
            const float* wrow = sw + (dy * 3 + dx) * CIN * COUT;
            #pragma unroll 4
            for (int ic4 = 0; ic4 < C4; ic4++) {
                float w0[NOC][4];
                #pragma unroll
                for (int n = 0; n < NOC; n++)
                    #pragma unroll
                    for (int k = 0; k < 4; k++)
                        w0[n][k] = wrow[(ic4 * 4 + k) * COUT + oc + 32 * n];
                #pragma unroll
                for (int p = 0; p < TX; p++) {
                    float4 v = *(const float4*)(trow + p * CIN + ic4 * 4);
                    #pragma unroll
                    for (int n = 0; n < NOC; n++) {
                        acc[n][p] = fmaf(v.x, w0[n][0], acc[n][p]);
                        acc[n][p] = fmaf(v.y, w0[n][1], acc[n][p]);
                        acc[n][p] = fmaf(v.z, w0[n][2], acc[n][p]);
                        acc[n][p] = fmaf(v.w, w0[n][3], acc[n][p]);
                    }
                }
            }
        }
    }

    const int gy = by + ty;
    #pragma unroll
    for (int p = 0; p < TX; p++) {
        float* o = out + ((size_t)((b * HH + gy) * WW + bx + p)) * COUT;
        #pragma unroll
        for (int n = 0; n < NOC; n++) {
            float v = acc[n][p];
            o[oc + 32 * n] = v > 0.f ? v : 0.f;
        }
    }
}

// ---------------- fused 1x1 chain: 64 ->(relu) 64 ->(relu) 16 -> 2, + flow add
__global__ __launch_bounds__(256) void fused1x1_kernel(
    const float* __restrict__ in, const float* __restrict__ flow,
    const float* __restrict__ w2, const float* __restrict__ b2,
    const float* __restrict__ w3, const float* __restrict__ b3,
    const float* __restrict__ w4, const float* __restrict__ b4,
    float* __restrict__ flowch)
{
    extern __shared__ float sm[];
    float* sin = sm;                 // 256*65
    float* sw2 = sin + 256 * 65;     // 4096
    float* sw3 = sw2 + 4096;         // 1024
    float* sw4 = sw3 + 1024;         // 32
    float* sb2 = sw4 + 32;           // 64
    float* sb3 = sb2 + 64;           // 16
    float* sb4 = sb3 + 16;           // 2

    const int tid = threadIdx.x;
    for (int i = tid; i < 1024; i += 256) ((float4*)sw2)[i] = ((const float4*)w2)[i];
    for (int i = tid; i < 256;  i += 256) ((float4*)sw3)[i] = ((const float4*)w3)[i];
    if (tid < 32) sw4[tid] = w4[tid];
    if (tid < 64) sb2[tid] = b2[tid];
    if (tid < 16) sb3[tid] = b3[tid];
    if (tid < 2)  sb4[tid] = b4[tid];

    const float* gin = in + (size_t)blockIdx.x * 256 * 64;
    for (int i = tid; i < 256 * 64; i += 256)
        sin[(i >> 6) * 65 + (i & 63)] = gin[i];
    __syncthreads();

    float h[64];
    #pragma unroll
    for (int o = 0; o < 64; o++) h[o] = sb2[o];
    const float* myin = sin + tid * 65;
    #pragma unroll 2
    for (int ic = 0; ic < 64; ic++) {
        float v = myin[ic];
        const float4* wrow = (const float4*)(sw2 + ic * 64);
        #pragma unroll
        for (int o4 = 0; o4 < 16; o4++) {
            float4 w = wrow[o4];
            h[4 * o4 + 0] = fmaf(v, w.x, h[4 * o4 + 0]);
            h[4 * o4 + 1] = fmaf(v, w.y, h[4 * o4 + 1]);
            h[4 * o4 + 2] = fmaf(v, w.z, h[4 * o4 + 2]);
            h[4 * o4 + 3] = fmaf(v, w.w, h[4 * o4 + 3]);
        }
    }
    #pragma unroll
    for (int o = 0; o < 64; o++) h[o] = fmaxf(h[o], 0.f);

    float g[16];
    #pragma unroll
    for (int o = 0; o < 16; o++) g[o] = sb3[o];
    #pragma unroll 4
    for (int ic = 0; ic < 64; ic++) {
        float v = h[ic];
        const float4* wrow = (const float4*)(sw3 + ic * 16);
        #pragma unroll
        for (int o4 = 0; o4 < 4; o4++) {
            float4 w = wrow[o4];
            g[4 * o4 + 0] = fmaf(v, w.x, g[4 * o4 + 0]);
            g[4 * o4 + 1] = fmaf(v, w.y, g[4 * o4 + 1]);
            g[4 * o4 + 2] = fmaf(v, w.z, g[4 * o4 + 2]);
            g[4 * o4 + 3] = fmaf(v, w.w, g[4 * o4 + 3]);
        }
    }
    #pragma unroll
    for (int o = 0; o < 16; o++) g[o] = fmaxf(g[o], 0.f);

    float o0 = sb4[0], o1 = sb4[1];
    #pragma unroll
    for (int ic = 0; ic < 16; ic++) {
        o0 = fmaf(g[ic], sw4[2 * ic + 0], o0);
        o1 = fmaf(g[ic], sw4[2 * ic + 1], o1);
    }

    size_t pix = (size_t)blockIdx.x * 256 + tid;
    float2 f = ((const float2*)flow)[pix];
    ((float2*)flowch)[pix] = make_float2(f.x + o0, f.y + o1);
}

// ---------------- 2x bilinear upsample (jax.image.resize semantics) -------
__global__ __launch_bounds__(256) void upsample_kernel(
    const float* __restrict__ src, float* __restrict__ out)
{
    int idx = blockIdx.x * blockDim.x + threadIdx.x;   // B*512*512 threads
    int x = idx & 511;
    int y = (idx >> 9) & 511;
    int b = idx >> 18;
    float sy = 0.5f * (float)y - 0.25f;
    float sx = 0.5f * (float)x - 0.25f;
    float y0f = floorf(sy), x0f = floorf(sx);
    float wy = sy - y0f,    wx = sx - x0f;
    int y0 = (int)y0f, x0 = (int)x0f;
    int ya = max(y0, 0), yb = min(y0 + 1, HH - 1);
    int xa = max(x0, 0), xb = min(x0 + 1, WW - 1);
    const float2* s = (const float2*)src;
    float2 v00 = s[(b * HH + ya) * WW + xa];
    float2 v01 = s[(b * HH + ya) * WW + xb];
    float2 v10 = s[(b * HH + yb) * WW + xa];
    float2 v11 = s[(b * HH + yb) * WW + xb];
    float2 r;
    r.x = (1.f - wy) * ((1.f - wx) * v00.x + wx * v01.x)
        +        wy  * ((1.f - wx) * v10.x + wx * v11.x);
    r.y = (1.f - wy) * ((1.f - wx) * v00.y + wx * v01.y)
        +        wy  * ((1.f - wx) * v10.y + wx * v11.y);
    ((float2*)out)[idx] = r;
}

// ---------------- launch ---------------------------------------------------
extern "C" void kernel_launch(void* const* d_in, const int* in_sizes, int n_in,
                              void* d_out, int out_size)
{
    (void)in_sizes; (void)n_in; (void)out_size;
    const float* input_1 = (const float*)d_in[0];
    const float* input_2 = (const float*)d_in[1];
    const float* flow12  = (const float*)d_in[2];
    const float* flow21  = (const float*)d_in[3];
    float* out = (float*)d_out;

    float *cat, *c0, *flowch;
    cudaGetSymbolAddress((void**)&cat,    g_cat);
    cudaGetSymbolAddress((void**)&c0,     g_c0);
    cudaGetSymbolAddress((void**)&flowch, g_flowch);

    const int SM_CONV0 = (10 * 18 * 64 + 9 * 64 * 32 + 32) * 4;
    const int SM_CONV1 = (10 * 18 * 32 + 9 * 32 * 64 + 64) * 4;
    const int SM_F1    = (256 * 65 + 4096 + 1024 + 32 + 64 + 16 + 2) * 4;
    cudaFuncSetAttribute(conv3x3_kernel<64, 32>,
                         cudaFuncAttributeMaxDynamicSharedMemorySize, SM_CONV0);
    cudaFuncSetAttribute(conv3x3_kernel<32, 64>,
                         cudaFuncAttributeMaxDynamicSharedMemorySize, SM_CONV1);
    cudaFuncSetAttribute(fused1x1_kernel,
                         cudaFuncAttributeMaxDynamicSharedMemorySize, SM_F1);

    const size_t off64 = (size_t)NPIXTOT * 64;
    const size_t off32 = (size_t)NPIXTOT * 32;
    const size_t off2  = (size_t)NPIXTOT * 2;
    const size_t warpOutSz = (size_t)NPIXTOT * 32;
    const size_t upOutSz   = (size_t)BB * 512 * 512 * 2;

    dim3 convGrid(WW / 16, HH / 8, BB);

    for (int dir = 0; dir < 2; dir++) {
        const float* src   = dir ? input_2 : input_1;
        const float* other = dir ? input_1 : input_2;
        const float* flow  = dir ? flow21  : flow12;

        // setup_inputs dict order is INTERLEAVED per layer:
        //   d_in[4 + 4*i + 0] = w12_i, [.. +1] = b12_i, [.. +2] = w21_i, [.. +3] = b21_i
        const float* w[5];
        const float* bw[5];
        for (int i = 0; i < 5; i++) {
            w[i]  = (const float*)d_in[4 + 4 * i + 2 * dir];
            bw[i] = (const float*)d_in[4 + 4 * i + 2 * dir + 1];
        }

        float* catD = cat + (size_t)dir * off64;
        float* c0D  = c0  + (size_t)dir * off32;
        float* fcD  = flowch + (size_t)dir * off2;

        warpcat_kernel<<<NPIXTOT * 16 / 256, 256>>>(src, other, flow, catD);
        conv3x3_kernel<64, 32><<<convGrid, 256, SM_CONV0>>>(catD, w[0], bw[0], c0D);
        conv3x3_kernel<32, 64><<<convGrid, 256, SM_CONV1>>>(c0D, w[1], bw[1], catD);
        fused1x1_kernel<<<NPIXTOT / 256, 256, SM_F1>>>(catD, flow,
                                                       w[2], bw[2], w[3], bw[3],
                                                       w[4], bw[4], fcD);
        warp_kernel<<<NPIXTOT * 8 / 256, 256>>>(src, fcD, out + (size_t)dir * warpOutSz);
        upsample_kernel<<<BB * 512 * 512 / 256, 256>>>(
            fcD, out + 2 * warpOutSz + (size_t)dir * upOutSz);
    }
}

// round 3
// speedup vs baseline: 1.2668x; 1.2668x over previous
#include <cuda_runtime.h>
#include <cuda_bf16.h>

#define BB 8
#define HH 256
#define WW 256
#define NPIXTOT (BB*HH*WW)

typedef unsigned long long ull;

// ---------------- packed f32x2 helpers ------------------------------------
__device__ __forceinline__ ull ffma2(ull a, ull b, ull c) {
    ull d;
    asm("fma.rn.f32x2 %0, %1, %2, %3;" : "=l"(d) : "l"(a), "l"(b), "l"(c));
    return d;
}
__device__ __forceinline__ ull pack2(float lo, float hi) {
    ull d;
    asm("mov.b64 %0, {%1, %2};" : "=l"(d) : "f"(lo), "f"(hi));
    return d;
}
__device__ __forceinline__ float2 unpack2(ull v) {
    float lo, hi;
    asm("mov.b64 {%0, %1}, %2;" : "=f"(lo), "=f"(hi) : "l"(v));
    return make_float2(lo, hi);
}

// ---------------- scratch (device globals; no allocation allowed) ----------
__device__ float g_cat[2ull * NPIXTOT * 64];
__device__ float g_c0[2ull * NPIXTOT * 32];
__device__ float g_flowch[2ull * NPIXTOT * 2];

// ---------------- warp + concat ------------------------------------------
__global__ __launch_bounds__(256) void warpcat_kernel(
    const float* __restrict__ src, const float* __restrict__ other,
    const float* __restrict__ flow, float* __restrict__ cat)
{
    int idx = blockIdx.x * blockDim.x + threadIdx.x;   // NPIXTOT*16 threads
    int q   = idx & 15;
    int pix = idx >> 4;
    if (q < 8) {
        float4 v = ((const float4*)other)[pix * 8 + q];
        ((float4*)cat)[pix * 16 + q] = v;
        return;
    }
    int c4 = q - 8;
    int x = pix & (WW - 1);
    int y = (pix >> 8) & (HH - 1);
    int b = pix >> 16;
    float2 f = ((const float2*)flow)[pix];
    float qy = (float)y - f.x;
    float qx = (float)x - f.y;
    float fy = fminf(fmaxf(floorf(qy), 0.f), (float)(HH - 2));
    float fx = fminf(fmaxf(floorf(qx), 0.f), (float)(WW - 2));
    float ay = fminf(fmaxf(qy - fy, 0.f), 1.f);
    float ax = fminf(fmaxf(qx - fx, 0.f), 1.f);
    int iy = (int)fy, ix = (int)fx;
    const float4* s4 = (const float4*)src;
    int base = ((b * HH + iy) * WW + ix) * 8 + c4;
    float4 tl = s4[base];
    float4 tr = s4[base + 8];
    float4 bl = s4[base + WW * 8];
    float4 br = s4[base + WW * 8 + 8];
    float4 top, bot, r;
    top.x = tl.x + ax * (tr.x - tl.x); top.y = tl.y + ax * (tr.y - tl.y);
    top.z = tl.z + ax * (tr.z - tl.z); top.w = tl.w + ax * (tr.w - tl.w);
    bot.x = bl.x + ax * (br.x - bl.x); bot.y = bl.y + ax * (br.y - bl.y);
    bot.z = bl.z + ax * (br.z - bl.z); bot.w = bl.w + ax * (br.w - bl.w);
    r.x = top.x + ay * (bot.x - top.x); r.y = top.y + ay * (bot.y - top.y);
    r.z = top.z + ay * (bot.z - top.z); r.w = top.w + ay * (bot.w - top.w);
    ((float4*)cat)[pix * 16 + 8 + c4] = r;
}

// ---------------- final warp (32 ch, direct to output) --------------------
__global__ __launch_bounds__(256) void warp_kernel(
    const float* __restrict__ src, const float* __restrict__ flow,
    float* __restrict__ out)
{
    int idx = blockIdx.x * blockDim.x + threadIdx.x;   // NPIXTOT*8 threads
    int c4  = idx & 7;
    int pix = idx >> 3;
    int x = pix & (WW - 1);
    int y = (pix >> 8) & (HH - 1);
    int b = pix >> 16;
    float2 f = ((const float2*)flow)[pix];
    float qy = (float)y - f.x;
    float qx = (float)x - f.y;
    float fy = fminf(fmaxf(floorf(qy), 0.f), (float)(HH - 2));
    float fx = fminf(fmaxf(floorf(qx), 0.f), (float)(WW - 2));
    float ay = fminf(fmaxf(qy - fy, 0.f), 1.f);
    float ax = fminf(fmaxf(qx - fx, 0.f), 1.f);
    int iy = (int)fy, ix = (int)fx;
    const float4* s4 = (const float4*)src;
    int base = ((b * HH + iy) * WW + ix) * 8 + c4;
    float4 tl = s4[base];
    float4 tr = s4[base + 8];
    float4 bl = s4[base + WW * 8];
    float4 br = s4[base + WW * 8 + 8];
    float4 top, bot, r;
    top.x = tl.x + ax * (tr.x - tl.x); top.y = tl.y + ax * (tr.y - tl.y);
    top.z = tl.z + ax * (tr.z - tl.z); top.w = tl.w + ax * (tr.w - tl.w);
    bot.x = bl.x + ax * (br.x - bl.x); bot.y = bl.y + ax * (br.y - bl.y);
    bot.z = bl.z + ax * (br.z - bl.z); bot.w = bl.w + ax * (br.w - bl.w);
    r.x = top.x + ay * (bot.x - top.x); r.y = top.y + ay * (bot.y - top.y);
    r.z = top.z + ay * (bot.z - top.z); r.w = top.w + ay * (bot.w - top.w);
    ((float4*)out)[pix * 8 + c4] = r;
}

// ---------------- 3x3 conv (SAME, relu) — f32x2 packed over ic parity ------
// tile 16x8 pixels, halo 1. 256 threads: lane = oc, row = tid>>5.
// Weights staged in smem as [tap][ic4][oc] float4 (the 4 ic values for given
// oc contiguous) -> lane-consecutive ulonglong2 loads, conflict-free.
template<int CIN, int COUT>
__global__ __launch_bounds__(256) void conv3x3_kernel(
    const float* __restrict__ in, const float* __restrict__ wsrc,
    const float* __restrict__ bias, float* __restrict__ out)
{
    constexpr int TX = 16, TY = 8;
    constexpr int TILE_W = TX + 2;
    constexpr int C4 = CIN / 4;
    constexpr int NOC = COUT / 32;

    extern __shared__ float sm[];
    float* stile = sm;                              // (TY+2)*TILE_W*CIN
    float* swq   = sm + (TY + 2) * TILE_W * CIN;    // 9*CIN*COUT (reshaped)
    float* sb    = swq + 9 * CIN * COUT;            // COUT

    const int bx = blockIdx.x * TX;
    const int by = blockIdx.y * TY;
    const int b  = blockIdx.z;
    const int tid = threadIdx.x;

    // stage weights reshaped: swq[((tap*C4 + ic/4)*COUT + oc)*4 + ic%4] = w[tap][ic][oc]
    for (int i = tid; i < 9 * CIN * COUT; i += 256) {
        int tap = i / (CIN * COUT);
        int r   = i % (CIN * COUT);
        int ic  = r / COUT;
        int oc  = r % COUT;
        swq[((tap * C4 + (ic >> 2)) * COUT + oc) * 4 + (ic & 3)] = wsrc[i];
    }
    if (tid < COUT) sb[tid] = bias[tid];

    // stage input tile (zero-padded)
    {
        constexpr int TN = (TY + 2) * TILE_W * C4;
        float4* st4 = (float4*)stile;
        for (int i = tid; i < TN; i += 256) {
            int c4  = i % C4;
            int p   = i / C4;
            int txx = p % TILE_W;
            int tyy = p / TILE_W;
            int gx = bx + txx - 1;
            int gy = by + tyy - 1;
            float4 v = make_float4(0.f, 0.f, 0.f, 0.f);
            if (gx >= 0 && gx < WW && gy >= 0 && gy < HH)
                v = ((const float4*)in)[((b * HH + gy) * WW + gx) * C4 + c4];
            st4[i] = v;
        }
    }
    __syncthreads();

    const int oc = tid & 31;
    const int ty = tid >> 5;

    // packed accumulators: lo = even-ic partial, hi = odd-ic partial
    ull acc[NOC][TX];
    #pragma unroll
    for (int n = 0; n < NOC; n++) {
        ull b0 = pack2(sb[oc + 32 * n], 0.f);
        #pragma unroll
        for (int p = 0; p < TX; p++) acc[n][p] = b0;
    }

    const ulonglong2* wul = (const ulonglong2*)swq;

    #pragma unroll 1
    for (int tap = 0; tap < 9; tap++) {
        const int dy = tap / 3, dx = tap % 3;
        const float* trow = stile + ((ty + dy) * TILE_W + dx) * CIN;
        #pragma unroll 2
        for (int ic4 = 0; ic4 < C4; ic4++) {
            ulonglong2 wq[NOC];
            #pragma unroll
            for (int n = 0; n < NOC; n++)
                wq[n] = wul[(tap * C4 + ic4) * COUT + oc + 32 * n];
            #pragma unroll
            for (int p = 0; p < TX; p++) {
                ulonglong2 vq = *(const ulonglong2*)(trow + p * CIN + ic4 * 4);
                #pragma unroll
                for (int n = 0; n < NOC; n++) {
                    acc[n][p] = ffma2(vq.x, wq[n].x, acc[n][p]);
                    acc[n][p] = ffma2(vq.y, wq[n].y, acc[n][p]);
                }
            }
        }
    }

    const int gy = by + ty;
    #pragma unroll
    for (int p = 0; p < TX; p++) {
        float* o = out + ((size_t)((b * HH + gy) * WW + bx + p)) * COUT;
        #pragma unroll
        for (int n = 0; n < NOC; n++) {
            float2 t = unpack2(acc[n][p]);
            float v = t.x + t.y;
            o[oc + 32 * n] = v > 0.f ? v : 0.f;
        }
    }
}

// ---------------- fused 1x1 chain: 64 ->(relu) 64 ->(relu) 16 -> 2, + flow
// f32x2 packed over oc pairs; input read directly from gmem (L1-friendly);
// only ~21KB static smem -> 2 blocks/SM.
__global__ __launch_bounds__(256) void fused1x1_kernel(
    const float* __restrict__ in, const float* __restrict__ flow,
    const float* __restrict__ w2, const float* __restrict__ b2,
    const float* __restrict__ w3, const float* __restrict__ b3,
    const float* __restrict__ w4, const float* __restrict__ b4,
    float* __restrict__ flowch)
{
    __shared__ float sw2[64 * 64];
    __shared__ float sw3[64 * 16];
    __shared__ float sw4[32];
    __shared__ float sb2[64];
    __shared__ float sb3[16];
    __shared__ float sb4[2];

    const int tid = threadIdx.x;
    for (int i = tid; i < 1024; i += 256) ((float4*)sw2)[i] = ((const float4*)w2)[i];
    for (int i = tid; i < 256;  i += 256) ((float4*)sw3)[i] = ((const float4*)w3)[i];
    if (tid < 32) sw4[tid] = w4[tid];
    if (tid < 64) sb2[tid] = b2[tid];
    if (tid < 16) sb3[tid] = b3[tid];
    if (tid < 2)  sb4[tid] = b4[tid];
    __syncthreads();

    size_t pix = (size_t)blockIdx.x * 256 + tid;
    const float4* vin = (const float4*)(in + pix * 64);

    // ---- layer2: 64 -> 64, oc packed in pairs --------------------------
    ull h2[32];
    #pragma unroll
    for (int m = 0; m < 32; m++) h2[m] = ((const ull*)sb2)[m];

    #pragma unroll 4
    for (int ic4 = 0; ic4 < 16; ic4++) {
        float4 vq = __ldg(vin + ic4);
        float vk[4] = {vq.x, vq.y, vq.z, vq.w};
        #pragma unroll
        for (int k = 0; k < 4; k++) {
            ull vv = pack2(vk[k], vk[k]);
            const ulonglong2* wrow = (const ulonglong2*)(sw2 + (ic4 * 4 + k) * 64);
            #pragma unroll
            for (int j = 0; j < 16; j++) {
                ulonglong2 wq = wrow[j];
                h2[2 * j]     = ffma2(vv, wq.x, h2[2 * j]);
                h2[2 * j + 1] = ffma2(vv, wq.y, h2[2 * j + 1]);
            }
        }
    }
    float h[64];
    #pragma unroll
    for (int m = 0; m < 32; m++) {
        float2 t = unpack2(h2[m]);
        h[2 * m]     = fmaxf(t.x, 0.f);
        h[2 * m + 1] = fmaxf(t.y, 0.f);
    }

    // ---- layer3: 64 -> 16, oc packed in pairs --------------------------
    ull g2[8];
    #pragma unroll
    for (int m = 0; m < 8; m++) g2[m] = ((const ull*)sb3)[m];
    #pragma unroll 4
    for (int ic = 0; ic < 64; ic++) {
        ull vv = pack2(h[ic], h[ic]);
        const ulonglong2* wrow = (const ulonglong2*)(sw3 + ic * 16);
        #pragma unroll
        for (int j = 0; j < 4; j++) {
            ulonglong2 wq = wrow[j];
            g2[2 * j]     = ffma2(vv, wq.x, g2[2 * j]);
            g2[2 * j + 1] = ffma2(vv, wq.y, g2[2 * j + 1]);
        }
    }
    float g[16];
    #pragma unroll
    for (int m = 0; m < 8; m++) {
        float2 t = unpack2(g2[m]);
        g[2 * m]     = fmaxf(t.x, 0.f);
        g[2 * m + 1] = fmaxf(t.y, 0.f);
    }

    // ---- layer4: 16 -> 2 ------------------------------------------------
    float o0 = sb4[0], o1 = sb4[1];
    #pragma unroll
    for (int ic = 0; ic < 16; ic++) {
        o0 = fmaf(g[ic], sw4[2 * ic + 0], o0);
        o1 = fmaf(g[ic], sw4[2 * ic + 1], o1);
    }

    float2 f = ((const float2*)flow)[pix];
    ((float2*)flowch)[pix] = make_float2(f.x + o0, f.y + o1);
}

// ---------------- 2x bilinear upsample (jax.image.resize semantics) -------
__global__ __launch_bounds__(256) void upsample_kernel(
    const float* __restrict__ src, float* __restrict__ out)
{
    int idx = blockIdx.x * blockDim.x + threadIdx.x;   // B*512*512 threads
    int x = idx & 511;
    int y = (idx >> 9) & 511;
    int b = idx >> 18;
    float sy = 0.5f * (float)y - 0.25f;
    float sx = 0.5f * (float)x - 0.25f;
    float y0f = floorf(sy), x0f = floorf(sx);
    float wy = sy - y0f,    wx = sx - x0f;
    int y0 = (int)y0f, x0 = (int)x0f;
    int ya = max(y0, 0), yb = min(y0 + 1, HH - 1);
    int xa = max(x0, 0), xb = min(x0 + 1, WW - 1);
    const float2* s = (const float2*)src;
    float2 v00 = s[(b * HH + ya) * WW + xa];
    float2 v01 = s[(b * HH + ya) * WW + xb];
    float2 v10 = s[(b * HH + yb) * WW + xa];
    float2 v11 = s[(b * HH + yb) * WW + xb];
    float2 r;
    r.x = (1.f - wy) * ((1.f - wx) * v00.x + wx * v01.x)
        +        wy  * ((1.f - wx) * v10.x + wx * v11.x);
    r.y = (1.f - wy) * ((1.f - wx) * v00.y + wx * v01.y)
        +        wy  * ((1.f - wx) * v10.y + wx * v11.y);
    ((float2*)out)[idx] = r;
}

// ---------------- launch ---------------------------------------------------
extern "C" void kernel_launch(void* const* d_in, const int* in_sizes, int n_in,
                              void* d_out, int out_size)
{
    (void)in_sizes; (void)n_in; (void)out_size;
    const float* input_1 = (const float*)d_in[0];
    const float* input_2 = (const float*)d_in[1];
    const float* flow12  = (const float*)d_in[2];
    const float* flow21  = (const float*)d_in[3];
    float* out = (float*)d_out;

    float *cat, *c0, *flowch;
    cudaGetSymbolAddress((void**)&cat,    g_cat);
    cudaGetSymbolAddress((void**)&c0,     g_c0);
    cudaGetSymbolAddress((void**)&flowch, g_flowch);

    const int SM_CONV0 = (10 * 18 * 64 + 9 * 64 * 32 + 32) * 4;
    const int SM_CONV1 = (10 * 18 * 32 + 9 * 32 * 64 + 64) * 4;
    cudaFuncSetAttribute(conv3x3_kernel<64, 32>,
                         cudaFuncAttributeMaxDynamicSharedMemorySize, SM_CONV0);
    cudaFuncSetAttribute(conv3x3_kernel<32, 64>,
                         cudaFuncAttributeMaxDynamicSharedMemorySize, SM_CONV1);

    const size_t off64 = (size_t)NPIXTOT * 64;
    const size_t off32 = (size_t)NPIXTOT * 32;
    const size_t off2  = (size_t)NPIXTOT * 2;
    const size_t warpOutSz = (size_t)NPIXTOT * 32;
    const size_t upOutSz   = (size_t)BB * 512 * 512 * 2;

    dim3 convGrid(WW / 16, HH / 8, BB);

    for (int dir = 0; dir < 2; dir++) {
        const float* src   = dir ? input_2 : input_1;
        const float* other = dir ? input_1 : input_2;
        const float* flow  = dir ? flow21  : flow12;

        // dict order is interleaved per layer:
        //   d_in[4 + 4*i + 0]=w12_i, +1=b12_i, +2=w21_i, +3=b21_i
        const float* w[5];
        const float* bw[5];
        for (int i = 0; i < 5; i++) {
            w[i]  = (const float*)d_in[4 + 4 * i + 2 * dir];
            bw[i] = (const float*)d_in[4 + 4 * i + 2 * dir + 1];
        }

        float* catD = cat + (size_t)dir * off64;
        float* c0D  = c0  + (size_t)dir * off32;
        float* fcD  = flowch + (size_t)dir * off2;

        warpcat_kernel<<<NPIXTOT * 16 / 256, 256>>>(src, other, flow, catD);
        conv3x3_kernel<64, 32><<<convGrid, 256, SM_CONV0>>>(catD, w[0], bw[0], c0D);
        conv3x3_kernel<32, 64><<<convGrid, 256, SM_CONV1>>>(c0D, w[1], bw[1], catD);
        fused1x1_kernel<<<NPIXTOT / 256, 256>>>(catD, flow,
                                                w[2], bw[2], w[3], bw[3],
                                                w[4], bw[4], fcD);
        warp_kernel<<<NPIXTOT * 8 / 256, 256>>>(src, fcD, out + (size_t)dir * warpOutSz);
        upsample_kernel<<<BB * 512 * 512 / 256, 256>>>(
            fcD, out + 2 * warpOutSz + (size_t)dir * upOutSz);
    }
}

// round 4
// speedup vs baseline: 2.2390x; 1.7675x over previous
#include <cuda_runtime.h>
#include <cuda_bf16.h>

#define BB 8
#define HH 256
#define WW 256
#define NPIXTOT (BB*HH*WW)

typedef unsigned long long ull;

// ---------------- packed f32x2 helpers ------------------------------------
__device__ __forceinline__ ull ffma2(ull a, ull b, ull c) {
    ull d;
    asm("fma.rn.f32x2 %0, %1, %2, %3;" : "=l"(d) : "l"(a), "l"(b), "l"(c));
    return d;
}
__device__ __forceinline__ ull pack2(float lo, float hi) {
    ull d;
    asm("mov.b64 %0, {%1, %2};" : "=l"(d) : "f"(lo), "f"(hi));
    return d;
}
__device__ __forceinline__ float2 unpack2(ull v) {
    float lo, hi;
    asm("mov.b64 {%0, %1}, %2;" : "=f"(lo), "=f"(hi) : "l"(v));
    return make_float2(lo, hi);
}

// ---------------- tf32 helpers ---------------------------------------------
__device__ __forceinline__ float to_tf32(float x) {
    unsigned r;
    asm("cvt.rna.tf32.f32 %0, %1;" : "=r"(r) : "f"(x));
    return __uint_as_float(r);
}
// D(16x8) += A(16x8) * B(8x8), tf32 inputs, fp32 accum
__device__ __forceinline__ void mma_tf32(float* c,
    unsigned a0, unsigned a1, unsigned a2, unsigned a3,
    unsigned b0, unsigned b1)
{
    asm("mma.sync.aligned.m16n8k8.row.col.f32.tf32.tf32.f32 "
        "{%0,%1,%2,%3}, {%4,%5,%6,%7}, {%8,%9}, {%0,%1,%2,%3};"
        : "+f"(c[0]), "+f"(c[1]), "+f"(c[2]), "+f"(c[3])
        : "r"(a0), "r"(a1), "r"(a2), "r"(a3), "r"(b0), "r"(b1));
}

// ---------------- scratch (device globals; no allocation allowed) ----------
__device__ float g_cat[2ull * NPIXTOT * 64];
__device__ float g_c0[2ull * NPIXTOT * 32];
__device__ float g_flowch[2ull * NPIXTOT * 2];

// ---------------- warp (32 ch bilinear sample) -----------------------------
__global__ __launch_bounds__(256) void warp_kernel(
    const float* __restrict__ src, const float* __restrict__ flow,
    float* __restrict__ out)
{
    int idx = blockIdx.x * blockDim.x + threadIdx.x;   // NPIXTOT*8 threads
    int c4  = idx & 7;
    int pix = idx >> 3;
    int x = pix & (WW - 1);
    int y = (pix >> 8) & (HH - 1);
    int b = pix >> 16;
    float2 f = ((const float2*)flow)[pix];
    float qy = (float)y - f.x;
    float qx = (float)x - f.y;
    float fy = fminf(fmaxf(floorf(qy), 0.f), (float)(HH - 2));
    float fx = fminf(fmaxf(floorf(qx), 0.f), (float)(WW - 2));
    float ay = fminf(fmaxf(qy - fy, 0.f), 1.f);
    float ax = fminf(fmaxf(qx - fx, 0.f), 1.f);
    int iy = (int)fy, ix = (int)fx;
    const float4* s4 = (const float4*)src;
    int base = ((b * HH + iy) * WW + ix) * 8 + c4;
    float4 tl = s4[base];
    float4 tr = s4[base + 8];
    float4 bl = s4[base + WW * 8];
    float4 br = s4[base + WW * 8 + 8];
    float4 top, bot, r;
    top.x = tl.x + ax * (tr.x - tl.x); top.y = tl.y + ax * (tr.y - tl.y);
    top.z = tl.z + ax * (tr.z - tl.z); top.w = tl.w + ax * (tr.w - tl.w);
    bot.x = bl.x + ax * (br.x - bl.x); bot.y = bl.y + ax * (br.y - bl.y);
    bot.z = bl.z + ax * (br.z - bl.z); bot.w = bl.w + ax * (br.w - bl.w);
    r.x = top.x + ay * (bot.x - top.x); r.y = top.y + ay * (bot.y - top.y);
    r.z = top.z + ay * (bot.z - top.z); r.w = top.w + ay * (bot.w - top.w);
    ((float4*)out)[pix * 8 + c4] = r;
}

// ---------------- 3x3 conv (SAME, relu) via tf32 tensor-core MMA -----------
// Block: 16x8 pixel tile, 8 warps; warp ty handles 16 pixels (one row) x COUT.
// A = pixels x CIN (per-tap shifted window from smem tile, pitch CIN+4),
// B = weights [tap][oc][ic] (pitch CIN+4). All operands pre-cvt'd to tf32.
// If SPLIT: channels 0-31 from inA, 32-63 from inB (fused concat).
template<int CIN, int COUT, bool SPLIT>
__global__ __launch_bounds__(256, 2) void conv3x3_tc_kernel(
    const float* __restrict__ inA, const float* __restrict__ inB,
    const float* __restrict__ wsrc, const float* __restrict__ bias,
    float* __restrict__ out)
{
    constexpr int TX = 16, TY = 8;
    constexpr int TW = TX + 2, TH = TY + 2;
    constexpr int PITCH = CIN + 4;
    constexpr int NT = COUT / 8;   // n-tiles of 8
    constexpr int KC = CIN / 8;    // k-chunks of 8
    constexpr int C4 = CIN / 4;

    extern __shared__ float sm[];
    float* stile = sm;                         // TH*TW*PITCH
    float* sw    = sm + TH * TW * PITCH;       // 9*COUT*PITCH
    float* sb    = sw + 9 * COUT * PITCH;      // COUT

    const int bx = blockIdx.x * TX;
    const int by = blockIdx.y * TY;
    const int b  = blockIdx.z;
    const int tid = threadIdx.x;

    // stage weights: sw[(tap*COUT + oc)*PITCH + ic] = tf32(w[tap][ic][oc])
    for (int i = tid; i < 9 * CIN * COUT; i += 256) {
        int tap = i / (CIN * COUT);
        int r   = i % (CIN * COUT);
        int ic  = r / COUT;
        int oc  = r % COUT;
        sw[(tap * COUT + oc) * PITCH + ic] = to_tf32(wsrc[i]);
    }
    if (tid < COUT) sb[tid] = bias[tid];

    // stage input tile (zero-padded halo), converted to tf32
    for (int i = tid; i < TH * TW * C4; i += 256) {
        int c4 = i % C4;
        int p  = i / C4;
        int xx = p % TW;
        int yy = p / TW;
        int gx = bx + xx - 1;
        int gy = by + yy - 1;
        float4 v = make_float4(0.f, 0.f, 0.f, 0.f);
        if (gx >= 0 && gx < WW && gy >= 0 && gy < HH) {
            int pix = (b * HH + gy) * WW + gx;
            if (!SPLIT)
                v = ((const float4*)inA)[pix * C4 + c4];
            else
                v = (c4 < 8) ? ((const float4*)inA)[pix * 8 + c4]
                             : ((const float4*)inB)[pix * 8 + (c4 - 8)];
        }
        float* d = stile + p * PITCH + c4 * 4;
        d[0] = to_tf32(v.x);
        d[1] = to_tf32(v.y);
        d[2] = to_tf32(v.z);
        d[3] = to_tf32(v.w);
    }
    __syncthreads();

    const int lane = tid & 31;
    const int ty   = tid >> 5;       // warp's output row within tile
    const int g = lane >> 2;         // groupID  (0..7)
    const int t = lane & 3;          // threadID_in_group (0..3)

    float acc[NT][4];
    #pragma unroll
    for (int nt = 0; nt < NT; nt++)
        #pragma unroll
        for (int k = 0; k < 4; k++) acc[nt][k] = 0.f;

    #pragma unroll 1
    for (int tap = 0; tap < 9; tap++) {
        const int dy = tap / 3, dx = tap % 3;
        const float* abase = stile + ((ty + dy) * TW + dx) * PITCH;
        const float* wbase = sw + tap * COUT * PITCH;
        #pragma unroll
        for (int kc = 0; kc < KC; kc++) {
            const int ic = kc * 8 + t;
            // A fragment (m16 x k8): a0=(g,ic) a1=(g+8,ic) a2=(g,ic+4) a3=(g+8,ic+4)
            unsigned a0 = __float_as_uint(abase[g * PITCH + ic]);
            unsigned a1 = __float_as_uint(abase[(g + 8) * PITCH + ic]);
            unsigned a2 = __float_as_uint(abase[g * PITCH + ic + 4]);
            unsigned a3 = __float_as_uint(abase[(g + 8) * PITCH + ic + 4]);
            #pragma unroll
            for (int nt = 0; nt < NT; nt++) {
                // B fragment (k8 x n8): b0=(ic, oc=g) b1=(ic+4, oc=g)
                const float* wrow = wbase + (nt * 8 + g) * PITCH;
                unsigned b0 = __float_as_uint(wrow[ic]);
                unsigned b1 = __float_as_uint(wrow[ic + 4]);
                mma_tf32(acc[nt], a0, a1, a2, a3, b0, b1);
            }
        }
    }

    // epilogue: D c0=(g,2t) c1=(g,2t+1) c2=(g+8,2t) c3=(g+8,2t+1)
    const int gy = by + ty;
    float* orow0 = out + ((size_t)((b * HH + gy) * WW + bx + g)) * COUT;
    float* orow1 = orow0 + 8 * COUT;    // pixel g+8
    #pragma unroll
    for (int nt = 0; nt < NT; nt++) {
        int oc = nt * 8 + 2 * t;
        float bi0 = sb[oc], bi1 = sb[oc + 1];
        float2 v0 = make_float2(fmaxf(acc[nt][0] + bi0, 0.f),
                                fmaxf(acc[nt][1] + bi1, 0.f));
        float2 v1 = make_float2(fmaxf(acc[nt][2] + bi0, 0.f),
                                fmaxf(acc[nt][3] + bi1, 0.f));
        *(float2*)(orow0 + oc) = v0;
        *(float2*)(orow1 + oc) = v1;
    }
}

// ---------------- fused 1x1 chain: 64 ->(relu) 64 ->(relu) 16 -> 2, + flow
__global__ __launch_bounds__(256) void fused1x1_kernel(
    const float* __restrict__ in, const float* __restrict__ flow,
    const float* __restrict__ w2, const float* __restrict__ b2,
    const float* __restrict__ w3, const float* __restrict__ b3,
    const float* __restrict__ w4, const float* __restrict__ b4,
    float* __restrict__ flowch)
{
    __shared__ float sw2[64 * 64];
    __shared__ float sw3[64 * 16];
    __shared__ float sw4[32];
    __shared__ float sb2[64];
    __shared__ float sb3[16];
    __shared__ float sb4[2];

    const int tid = threadIdx.x;
    for (int i = tid; i < 1024; i += 256) ((float4*)sw2)[i] = ((const float4*)w2)[i];
    for (int i = tid; i < 256;  i += 256) ((float4*)sw3)[i] = ((const float4*)w3)[i];
    if (tid < 32) sw4[tid] = w4[tid];
    if (tid < 64) sb2[tid] = b2[tid];
    if (tid < 16) sb3[tid] = b3[tid];
    if (tid < 2)  sb4[tid] = b4[tid];
    __syncthreads();

    size_t pix = (size_t)blockIdx.x * 256 + tid;
    const float4* vin = (const float4*)(in + pix * 64);

    ull h2[32];
    #pragma unroll
    for (int m = 0; m < 32; m++) h2[m] = ((const ull*)sb2)[m];

    #pragma unroll 4
    for (int ic4 = 0; ic4 < 16; ic4++) {
        float4 vq = __ldg(vin + ic4);
        float vk[4] = {vq.x, vq.y, vq.z, vq.w};
        #pragma unroll
        for (int k = 0; k < 4; k++) {
            ull vv = pack2(vk[k], vk[k]);
            const ulonglong2* wrow = (const ulonglong2*)(sw2 + (ic4 * 4 + k) * 64);
            #pragma unroll
            for (int j = 0; j < 16; j++) {
                ulonglong2 wq = wrow[j];
                h2[2 * j]     = ffma2(vv, wq.x, h2[2 * j]);
                h2[2 * j + 1] = ffma2(vv, wq.y, h2[2 * j + 1]);
            }
        }
    }
    float h[64];
    #pragma unroll
    for (int m = 0; m < 32; m++) {
        float2 tt = unpack2(h2[m]);
        h[2 * m]     = fmaxf(tt.x, 0.f);
        h[2 * m + 1] = fmaxf(tt.y, 0.f);
    }

    ull g2[8];
    #pragma unroll
    for (int m = 0; m < 8; m++) g2[m] = ((const ull*)sb3)[m];
    #pragma unroll 4
    for (int ic = 0; ic < 64; ic++) {
        ull vv = pack2(h[ic], h[ic]);
        const ulonglong2* wrow = (const ulonglong2*)(sw3 + ic * 16);
        #pragma unroll
        for (int j = 0; j < 4; j++) {
            ulonglong2 wq = wrow[j];
            g2[2 * j]     = ffma2(vv, wq.x, g2[2 * j]);
            g2[2 * j + 1] = ffma2(vv, wq.y, g2[2 * j + 1]);
        }
    }
    float g[16];
    #pragma unroll
    for (int m = 0; m < 8; m++) {
        float2 tt = unpack2(g2[m]);
        g[2 * m]     = fmaxf(tt.x, 0.f);
        g[2 * m + 1] = fmaxf(tt.y, 0.f);
    }

    float o0 = sb4[0], o1 = sb4[1];
    #pragma unroll
    for (int ic = 0; ic < 16; ic++) {
        o0 = fmaf(g[ic], sw4[2 * ic + 0], o0);
        o1 = fmaf(g[ic], sw4[2 * ic + 1], o1);
    }

    float2 f = ((const float2*)flow)[pix];
    ((float2*)flowch)[pix] = make_float2(f.x + o0, f.y + o1);
}

// ---------------- 2x bilinear upsample (jax.image.resize semantics) -------
__global__ __launch_bounds__(256) void upsample_kernel(
    const float* __restrict__ src, float* __restrict__ out)
{
    int idx = blockIdx.x * blockDim.x + threadIdx.x;   // B*512*512 threads
    int x = idx & 511;
    int y = (idx >> 9) & 511;
    int b = idx >> 18;
    float sy = 0.5f * (float)y - 0.25f;
    float sx = 0.5f * (float)x - 0.25f;
    float y0f = floorf(sy), x0f = floorf(sx);
    float wy = sy - y0f,    wx = sx - x0f;
    int y0 = (int)y0f, x0 = (int)x0f;
    int ya = max(y0, 0), yb = min(y0 + 1, HH - 1);
    int xa = max(x0, 0), xb = min(x0 + 1, WW - 1);
    const float2* s = (const float2*)src;
    float2 v00 = s[(b * HH + ya) * WW + xa];
    float2 v01 = s[(b * HH + ya) * WW + xb];
    float2 v10 = s[(b * HH + yb) * WW + xa];
    float2 v11 = s[(b * HH + yb) * WW + xb];
    float2 r;
    r.x = (1.f - wy) * ((1.f - wx) * v00.x + wx * v01.x)
        +        wy  * ((1.f - wx) * v10.x + wx * v11.x);
    r.y = (1.f - wy) * ((1.f - wx) * v00.y + wx * v01.y)
        +        wy  * ((1.f - wx) * v10.y + wx * v11.y);
    ((float2*)out)[idx] = r;
}

// ---------------- launch ---------------------------------------------------
extern "C" void kernel_launch(void* const* d_in, const int* in_sizes, int n_in,
                              void* d_out, int out_size)
{
    (void)in_sizes; (void)n_in; (void)out_size;
    const float* input_1 = (const float*)d_in[0];
    const float* input_2 = (const float*)d_in[1];
    const float* flow12  = (const float*)d_in[2];
    const float* flow21  = (const float*)d_in[3];
    float* out = (float*)d_out;

    float *cat, *c0, *flowch;
    cudaGetSymbolAddress((void**)&cat,    g_cat);
    cudaGetSymbolAddress((void**)&c0,     g_c0);
    cudaGetSymbolAddress((void**)&flowch, g_flowch);

    const int SM_CONV0 = (10 * 18 * 68 + 9 * 32 * 68 + 32) * 4;   // ~127.5 KB
    const int SM_CONV1 = (10 * 18 * 36 + 9 * 64 * 36 + 64) * 4;   // ~109 KB
    cudaFuncSetAttribute(conv3x3_tc_kernel<64, 32, true>,
                         cudaFuncAttributeMaxDynamicSharedMemorySize, SM_CONV0);
    cudaFuncSetAttribute(conv3x3_tc_kernel<32, 64, false>,
                         cudaFuncAttributeMaxDynamicSharedMemorySize, SM_CONV1);

    const size_t off64 = (size_t)NPIXTOT * 64;
    const size_t off32 = (size_t)NPIXTOT * 32;
    const size_t off2  = (size_t)NPIXTOT * 2;
    const size_t warpOutSz = (size_t)NPIXTOT * 32;
    const size_t upOutSz   = (size_t)BB * 512 * 512 * 2;

    dim3 convGrid(WW / 16, HH / 8, BB);

    for (int dir = 0; dir < 2; dir++) {
        const float* src   = dir ? input_2 : input_1;
        const float* other = dir ? input_1 : input_2;
        const float* flow  = dir ? flow21  : flow12;

        // dict order is interleaved per layer:
        //   d_in[4 + 4*i + 0]=w12_i, +1=b12_i, +2=w21_i, +3=b21_i
        const float* w[5];
        const float* bw[5];
        for (int i = 0; i < 5; i++) {
            w[i]  = (const float*)d_in[4 + 4 * i + 2 * dir];
            bw[i] = (const float*)d_in[4 + 4 * i + 2 * dir + 1];
        }

        float* catD = cat + (size_t)dir * off64;   // also holds warped-32ch first
        float* c0D  = c0  + (size_t)dir * off32;
        float* fcD  = flowch + (size_t)dir * off2;

        // warped(src, flow) -> catD (first 32ch region, consumed by conv0)
        warp_kernel<<<NPIXTOT * 8 / 256, 256>>>(src, flow, catD);
        // conv0: concat(other, warped) fused via SPLIT staging
        conv3x3_tc_kernel<64, 32, true><<<convGrid, 256, SM_CONV0>>>(
            other, catD, w[0], bw[0], c0D);
        // conv1: 32 -> 64 (overwrites catD; warped already consumed)
        conv3x3_tc_kernel<32, 64, false><<<convGrid, 256, SM_CONV1>>>(
            c0D, nullptr, w[1], bw[1], catD);
        fused1x1_kernel<<<NPIXTOT / 256, 256>>>(catD, flow,
                                                w[2], bw[2], w[3], bw[3],
                                                w[4], bw[4], fcD);
        warp_kernel<<<NPIXTOT * 8 / 256, 256>>>(src, fcD, out + (size_t)dir * warpOutSz);
        upsample_kernel<<<BB * 512 * 512 / 256, 256>>>(
            fcD, out + 2 * warpOutSz + (size_t)dir * upOutSz);
    }
}

// round 5
// speedup vs baseline: 3.2278x; 1.4416x over previous
#include <cuda_runtime.h>
#include <cuda_bf16.h>

#define BB 8
#define HH 256
#define WW 256
#define NPIXTOT (BB*HH*WW)

typedef unsigned long long ull;

// ---------------- tf32 helpers ---------------------------------------------
__device__ __forceinline__ float to_tf32(float x) {
    unsigned r;
    asm("cvt.rna.tf32.f32 %0, %1;" : "=r"(r) : "f"(x));
    return __uint_as_float(r);
}
// D(16x8) += A(16x8) * B(8x8), tf32 inputs, fp32 accum
__device__ __forceinline__ void mma_tf32(float* c,
    unsigned a0, unsigned a1, unsigned a2, unsigned a3,
    unsigned b0, unsigned b1)
{
    asm("mma.sync.aligned.m16n8k8.row.col.f32.tf32.tf32.f32 "
        "{%0,%1,%2,%3}, {%4,%5,%6,%7}, {%8,%9}, {%0,%1,%2,%3};"
        : "+f"(c[0]), "+f"(c[1]), "+f"(c[2]), "+f"(c[3])
        : "r"(a0), "r"(a1), "r"(a2), "r"(a3), "r"(b0), "r"(b1));
}

// ---------------- scratch (device globals; no allocation allowed) ----------
__device__ float g_cat[2ull * NPIXTOT * 64];
__device__ float g_c0[2ull * NPIXTOT * 32];
__device__ float g_flowch[2ull * NPIXTOT * 2];
// prepacked tf32 conv weights: [dir0 conv0 | dir0 conv1 | dir1 conv0 | dir1 conv1]
#define WP_N0 (9*32*68)
#define WP_N1 (9*64*36)
__device__ float g_wpack[2 * (WP_N0 + WP_N1)];

// ---------------- weight prepack (tf32, [tap][oc][ic] pitch-padded) --------
__global__ void prepack_kernel(
    const float* __restrict__ c0d0, const float* __restrict__ c1d0,
    const float* __restrict__ c0d1, const float* __restrict__ c1d1,
    float* __restrict__ dst)
{
    int i = blockIdx.x * blockDim.x + threadIdx.x;
    const int PER = WP_N0 + WP_N1;
    if (i >= 2 * PER) return;
    int dir = (i >= PER);
    int j = i - dir * PER;
    const float* w;
    int CIN, COUT, PITCH;
    if (j < WP_N0) { w = dir ? c0d1 : c0d0; CIN = 64; COUT = 32; PITCH = 68; }
    else { j -= WP_N0; w = dir ? c1d1 : c1d0; CIN = 32; COUT = 64; PITCH = 36; }
    int ic  = j % PITCH;
    int r   = j / PITCH;
    int oc  = r % COUT;
    int tap = r / COUT;
    float v = 0.f;
    if (ic < CIN) v = w[(tap * CIN + ic) * COUT + oc];
    dst[i] = to_tf32(v);
}

// ---------------- warp (32 ch bilinear sample) -----------------------------
__global__ __launch_bounds__(256) void warp_kernel(
    const float* __restrict__ src, const float* __restrict__ flow,
    float* __restrict__ out)
{
    int idx = blockIdx.x * blockDim.x + threadIdx.x;   // NPIXTOT*8 threads
    int c4  = idx & 7;
    int pix = idx >> 3;
    int x = pix & (WW - 1);
    int y = (pix >> 8) & (HH - 1);
    int b = pix >> 16;
    float2 f = ((const float2*)flow)[pix];
    float qy = (float)y - f.x;
    float qx = (float)x - f.y;
    float fy = fminf(fmaxf(floorf(qy), 0.f), (float)(HH - 2));
    float fx = fminf(fmaxf(floorf(qx), 0.f), (float)(WW - 2));
    float ay = fminf(fmaxf(qy - fy, 0.f), 1.f);
    float ax = fminf(fmaxf(qx - fx, 0.f), 1.f);
    int iy = (int)fy, ix = (int)fx;
    const float4* s4 = (const float4*)src;
    int base = ((b * HH + iy) * WW + ix) * 8 + c4;
    float4 tl = s4[base];
    float4 tr = s4[base + 8];
    float4 bl = s4[base + WW * 8];
    float4 br = s4[base + WW * 8 + 8];
    float4 top, bot, r;
    top.x = tl.x + ax * (tr.x - tl.x); top.y = tl.y + ax * (tr.y - tl.y);
    top.z = tl.z + ax * (tr.z - tl.z); top.w = tl.w + ax * (tr.w - tl.w);
    bot.x = bl.x + ax * (br.x - bl.x); bot.y = bl.y + ax * (br.y - bl.y);
    bot.z = bl.z + ax * (br.z - bl.z); bot.w = bl.w + ax * (br.w - bl.w);
    r.x = top.x + ay * (bot.x - top.x); r.y = top.y + ay * (bot.y - top.y);
    r.z = top.z + ay * (bot.z - top.z); r.w = top.w + ay * (bot.w - top.w);
    ((float4*)out)[pix * 8 + c4] = r;
}

// ---------------- 3x3 conv (SAME, relu) via tf32 MMA, M=32/warp ------------
// Block: 16x16 pixel tile, 8 warps; warp wy handles rows 2wy, 2wy+1 (two m16
// tiles of 16 x-pixels each). Weights prepacked tf32 [tap][oc][PITCH].
// If SPLIT: channels 0-31 from inA, 32-63 from inB (fused concat).
template<int CIN, int COUT, bool SPLIT>
__global__ __launch_bounds__(256) void conv3x3_tc_kernel(
    const float* __restrict__ inA, const float* __restrict__ inB,
    const float* __restrict__ wpack, const float* __restrict__ bias,
    float* __restrict__ out)
{
    constexpr int TX = 16, TY = 16;
    constexpr int TW = TX + 2, TH = TY + 2;
    constexpr int PITCH = CIN + 4;
    constexpr int NT = COUT / 8;
    constexpr int KC = CIN / 8;
    constexpr int C4 = CIN / 4;
    constexpr int WN = 9 * COUT * PITCH;

    extern __shared__ float sm[];
    float* stile = sm;                         // TH*TW*PITCH
    float* sw    = sm + TH * TW * PITCH;       // WN
    float* sb    = sw + WN;                    // COUT

    const int bx = blockIdx.x * TX;
    const int by = blockIdx.y * TY;
    const int b  = blockIdx.z;
    const int tid = threadIdx.x;

    // weights: straight float4 copy (already tf32, final layout)
    {
        const float4* src4 = (const float4*)wpack;
        float4* dst4 = (float4*)sw;
        #pragma unroll 4
        for (int i = tid; i < WN / 4; i += 256) dst4[i] = src4[i];
        if (tid < COUT) sb[tid] = bias[tid];
    }
    // input tile (zero-padded halo), converted to tf32
    for (int i = tid; i < TH * TW * C4; i += 256) {
        int c4 = i % C4;
        int p  = i / C4;
        int xx = p % TW;
        int yy = p / TW;
        int gx = bx + xx - 1;
        int gy = by + yy - 1;
        float4 v = make_float4(0.f, 0.f, 0.f, 0.f);
        if (gx >= 0 && gx < WW && gy >= 0 && gy < HH) {
            int pix = (b * HH + gy) * WW + gx;
            if (!SPLIT)
                v = ((const float4*)inA)[pix * C4 + c4];
            else
                v = (c4 < 8) ? ((const float4*)inA)[pix * 8 + c4]
                             : ((const float4*)inB)[pix * 8 + (c4 - 8)];
        }
        float* d = stile + p * PITCH + c4 * 4;
        d[0] = to_tf32(v.x);
        d[1] = to_tf32(v.y);
        d[2] = to_tf32(v.z);
        d[3] = to_tf32(v.w);
    }
    __syncthreads();

    const int lane = tid & 31;
    const int wy   = tid >> 5;       // warp's row pair: rows 2wy, 2wy+1
    const int g = lane >> 2;
    const int t = lane & 3;

    float acc0[NT][4], acc1[NT][4];
    #pragma unroll
    for (int nt = 0; nt < NT; nt++)
        #pragma unroll
        for (int k = 0; k < 4; k++) { acc0[nt][k] = 0.f; acc1[nt][k] = 0.f; }

    #pragma unroll 1
    for (int tap = 0; tap < 9; tap++) {
        const int dy = tap / 3, dx = tap % 3;
        const float* a0b = stile + ((2 * wy + dy) * TW + dx) * PITCH;
        const float* a1b = a0b + TW * PITCH;
        const float* wbase = sw + tap * COUT * PITCH;
        #pragma unroll
        for (int kc = 0; kc < KC; kc++) {
            const int ic = kc * 8 + t;
            unsigned p00 = __float_as_uint(a0b[g * PITCH + ic]);
            unsigned p01 = __float_as_uint(a0b[(g + 8) * PITCH + ic]);
            unsigned p02 = __float_as_uint(a0b[g * PITCH + ic + 4]);
            unsigned p03 = __float_as_uint(a0b[(g + 8) * PITCH + ic + 4]);
            unsigned p10 = __float_as_uint(a1b[g * PITCH + ic]);
            unsigned p11 = __float_as_uint(a1b[(g + 8) * PITCH + ic]);
            unsigned p12 = __float_as_uint(a1b[g * PITCH + ic + 4]);
            unsigned p13 = __float_as_uint(a1b[(g + 8) * PITCH + ic + 4]);
            #pragma unroll
            for (int nt = 0; nt < NT; nt++) {
                const float* wrow = wbase + (nt * 8 + g) * PITCH;
                unsigned b0 = __float_as_uint(wrow[ic]);
                unsigned b1 = __float_as_uint(wrow[ic + 4]);
                mma_tf32(acc0[nt], p00, p01, p02, p03, b0, b1);
                mma_tf32(acc1[nt], p10, p11, p12, p13, b0, b1);
            }
        }
    }

    // epilogue (rows 2wy and 2wy+1)
    #pragma unroll
    for (int rr = 0; rr < 2; rr++) {
        const int gy = by + 2 * wy + rr;
        float (*acc)[4] = rr ? acc1 : acc0;
        float* orow0 = out + ((size_t)((b * HH + gy) * WW + bx + g)) * COUT;
        float* orow1 = orow0 + 8 * COUT;
        #pragma unroll
        for (int nt = 0; nt < NT; nt++) {
            int oc = nt * 8 + 2 * t;
            float bi0 = sb[oc], bi1 = sb[oc + 1];
            float2 v0 = make_float2(fmaxf(acc[nt][0] + bi0, 0.f),
                                    fmaxf(acc[nt][1] + bi1, 0.f));
            float2 v1 = make_float2(fmaxf(acc[nt][2] + bi0, 0.f),
                                    fmaxf(acc[nt][3] + bi1, 0.f));
            *(float2*)(orow0 + oc) = v0;
            *(float2*)(orow1 + oc) = v1;
        }
    }
}

// ---------------- fused 1x1 chain via tf32 MMA -----------------------------
// 64 ->(relu) 64 ->(relu) 16 -> 2, + flow add. Block = 128 pixels, 8 warps,
// warp w owns pixels 16w..16w+15. h written back in-place into the staging
// buffer (tf32, post-relu); layer4 via 4-lane shfl reduction.
__global__ __launch_bounds__(256) void fused1x1_tc_kernel(
    const float* __restrict__ in, const float* __restrict__ flow,
    const float* __restrict__ w2, const float* __restrict__ b2,
    const float* __restrict__ w3, const float* __restrict__ b3,
    const float* __restrict__ w4, const float* __restrict__ b4,
    float* __restrict__ flowch)
{
    extern __shared__ float sm[];
    float* sin  = sm;                 // 128*68
    float* sw2s = sin + 128 * 68;     // 64*68
    float* sw3s = sw2s + 64 * 68;     // 16*68
    float* sb2  = sw3s + 16 * 68;     // 64
    float* sb3  = sb2 + 64;           // 16
    float* sw4s = sb3 + 16;           // 32
    float* sb4  = sw4s + 32;          // 2

    const int tid = threadIdx.x;

    // stage input 128 pix x 64 ch (tf32, pitch 68)
    {
        const float4* gin4 = (const float4*)(in + (size_t)blockIdx.x * 128 * 64);
        #pragma unroll 4
        for (int i = tid; i < 128 * 16; i += 256) {
            int pix = i >> 4, c4 = i & 15;
            float4 v = gin4[i];
            float* d = sin + pix * 68 + c4 * 4;
            d[0] = to_tf32(v.x); d[1] = to_tf32(v.y);
            d[2] = to_tf32(v.z); d[3] = to_tf32(v.w);
        }
    }
    // stage w2 transposed [oc][ic] (tf32)
    for (int i = tid; i < 4096; i += 256) {
        int oc = i & 63, ic = i >> 6;
        sw2s[oc * 68 + ic] = to_tf32(w2[i]);
    }
    // stage w3 transposed [oc][ic] (tf32)
    for (int i = tid; i < 1024; i += 256) {
        int oc = i & 15, ic = i >> 4;
        sw3s[oc * 68 + ic] = to_tf32(w3[i]);
    }
    if (tid < 64) sb2[tid] = b2[tid];
    if (tid < 16) sb3[tid] = b3[tid];
    if (tid < 32) sw4s[tid] = w4[tid];
    if (tid < 2)  sb4[tid] = b4[tid];
    __syncthreads();

    const int lane = tid & 31;
    const int w = tid >> 5;
    const int g = lane >> 2;
    const int t = lane & 3;
    float* arow = sin + (w * 16) * 68;

    // ---- layer2: K=64, N=64 --------------------------------------------
    float acc[8][4];
    #pragma unroll
    for (int nt = 0; nt < 8; nt++)
        #pragma unroll
        for (int k = 0; k < 4; k++) acc[nt][k] = 0.f;

    #pragma unroll
    for (int kc = 0; kc < 8; kc++) {
        const int ic = kc * 8 + t;
        unsigned a0 = __float_as_uint(arow[g * 68 + ic]);
        unsigned a1 = __float_as_uint(arow[(g + 8) * 68 + ic]);
        unsigned a2 = __float_as_uint(arow[g * 68 + ic + 4]);
        unsigned a3 = __float_as_uint(arow[(g + 8) * 68 + ic + 4]);
        #pragma unroll
        for (int nt = 0; nt < 8; nt++) {
            const float* wrow = sw2s + (nt * 8 + g) * 68;
            unsigned b0 = __float_as_uint(wrow[ic]);
            unsigned b1 = __float_as_uint(wrow[ic + 4]);
            mma_tf32(acc[nt], a0, a1, a2, a3, b0, b1);
        }
    }
    // bias + relu + cvt tf32, write h in-place (warp owns its 16 rows)
    #pragma unroll
    for (int nt = 0; nt < 8; nt++) {
        int oc = nt * 8 + 2 * t;
        float bi0 = sb2[oc], bi1 = sb2[oc + 1];
        float2 h0 = make_float2(to_tf32(fmaxf(acc[nt][0] + bi0, 0.f)),
                                to_tf32(fmaxf(acc[nt][1] + bi1, 0.f)));
        float2 h1 = make_float2(to_tf32(fmaxf(acc[nt][2] + bi0, 0.f)),
                                to_tf32(fmaxf(acc[nt][3] + bi1, 0.f)));
        *(float2*)(arow + g * 68 + oc)       = h0;
        *(float2*)(arow + (g + 8) * 68 + oc) = h1;
    }
    __syncwarp();

    // ---- layer3: K=64, N=16 --------------------------------------------
    float acc3[2][4];
    #pragma unroll
    for (int nt = 0; nt < 2; nt++)
        #pragma unroll
        for (int k = 0; k < 4; k++) acc3[nt][k] = 0.f;

    #pragma unroll
    for (int kc = 0; kc < 8; kc++) {
        const int ic = kc * 8 + t;
        unsigned a0 = __float_as_uint(arow[g * 68 + ic]);
        unsigned a1 = __float_as_uint(arow[(g + 8) * 68 + ic]);
        unsigned a2 = __float_as_uint(arow[g * 68 + ic + 4]);
        unsigned a3 = __float_as_uint(arow[(g + 8) * 68 + ic + 4]);
        #pragma unroll
        for (int nt = 0; nt < 2; nt++) {
            const float* wrow = sw3s + (nt * 8 + g) * 68;
            unsigned b0 = __float_as_uint(wrow[ic]);
            unsigned b1 = __float_as_uint(wrow[ic + 4]);
            mma_tf32(acc3[nt], a0, a1, a2, a3, b0, b1);
        }
    }

    // ---- layer4: 16 -> 2 (relu(g)·w4, reduce across t-group) -----------
    float o0a = 0.f, o1a = 0.f, o0b = 0.f, o1b = 0.f;
    #pragma unroll
    for (int nt = 0; nt < 2; nt++) {
        #pragma unroll
        for (int p = 0; p < 2; p++) {
            int col = nt * 8 + 2 * t + p;
            float bi = sb3[col];
            float w0 = sw4s[col * 2], w1 = sw4s[col * 2 + 1];
            float va = fmaxf(acc3[nt][p] + bi, 0.f);       // row g
            float vb = fmaxf(acc3[nt][2 + p] + bi, 0.f);   // row g+8
            o0a = fmaf(va, w0, o0a); o1a = fmaf(va, w1, o1a);
            o0b = fmaf(vb, w0, o0b); o1b = fmaf(vb, w1, o1b);
        }
    }
    #pragma unroll
    for (int m = 1; m <= 2; m <<= 1) {
        o0a += __shfl_xor_sync(0xffffffffu, o0a, m);
        o1a += __shfl_xor_sync(0xffffffffu, o1a, m);
        o0b += __shfl_xor_sync(0xffffffffu, o0b, m);
        o1b += __shfl_xor_sync(0xffffffffu, o1b, m);
    }
    if (t == 0) {
        size_t pix0 = (size_t)blockIdx.x * 128 + w * 16 + g;
        float2 f0 = ((const float2*)flow)[pix0];
        float2 f1 = ((const float2*)flow)[pix0 + 8];
        ((float2*)flowch)[pix0]     = make_float2(f0.x + o0a + sb4[0], f0.y + o1a + sb4[1]);
        ((float2*)flowch)[pix0 + 8] = make_float2(f1.x + o0b + sb4[0], f1.y + o1b + sb4[1]);
    }
}

// ---------------- 2x bilinear upsample (jax.image.resize semantics) -------
__global__ __launch_bounds__(256) void upsample_kernel(
    const float* __restrict__ src, float* __restrict__ out)
{
    int idx = blockIdx.x * blockDim.x + threadIdx.x;   // B*512*512 threads
    int x = idx & 511;
    int y = (idx >> 9) & 511;
    int b = idx >> 18;
    float sy = 0.5f * (float)y - 0.25f;
    float sx = 0.5f * (float)x - 0.25f;
    float y0f = floorf(sy), x0f = floorf(sx);
    float wy = sy - y0f,    wx = sx - x0f;
    int y0 = (int)y0f, x0 = (int)x0f;
    int ya = max(y0, 0), yb = min(y0 + 1, HH - 1);
    int xa = max(x0, 0), xb = min(x0 + 1, WW - 1);
    const float2* s = (const float2*)src;
    float2 v00 = s[(b * HH + ya) * WW + xa];
    float2 v01 = s[(b * HH + ya) * WW + xb];
    float2 v10 = s[(b * HH + yb) * WW + xa];
    float2 v11 = s[(b * HH + yb) * WW + xb];
    float2 r;
    r.x = (1.f - wy) * ((1.f - wx) * v00.x + wx * v01.x)
        +        wy  * ((1.f - wx) * v10.x + wx * v11.x);
    r.y = (1.f - wy) * ((1.f - wx) * v00.y + wx * v01.y)
        +        wy  * ((1.f - wx) * v10.y + wx * v11.y);
    ((float2*)out)[idx] = r;
}

// ---------------- launch ---------------------------------------------------
extern "C" void kernel_launch(void* const* d_in, const int* in_sizes, int n_in,
                              void* d_out, int out_size)
{
    (void)in_sizes; (void)n_in; (void)out_size;
    const float* input_1 = (const float*)d_in[0];
    const float* input_2 = (const float*)d_in[1];
    const float* flow12  = (const float*)d_in[2];
    const float* flow21  = (const float*)d_in[3];
    float* out = (float*)d_out;

    float *cat, *c0, *flowch, *wpack;
    cudaGetSymbolAddress((void**)&cat,    g_cat);
    cudaGetSymbolAddress((void**)&c0,     g_c0);
    cudaGetSymbolAddress((void**)&flowch, g_flowch);
    cudaGetSymbolAddress((void**)&wpack,  g_wpack);

    const int SM_CONV0 = (18 * 18 * 68 + WP_N0 + 32) * 4;   // ~166.6 KB
    const int SM_CONV1 = (18 * 18 * 36 + WP_N1 + 64) * 4;   // ~129.9 KB
    const int SM_F1    = (128 * 68 + 64 * 68 + 16 * 68 + 64 + 16 + 32 + 2) * 4;
    cudaFuncSetAttribute(conv3x3_tc_kernel<64, 32, true>,
                         cudaFuncAttributeMaxDynamicSharedMemorySize, SM_CONV0);
    cudaFuncSetAttribute(conv3x3_tc_kernel<32, 64, false>,
                         cudaFuncAttributeMaxDynamicSharedMemorySize, SM_CONV1);
    cudaFuncSetAttribute(fused1x1_tc_kernel,
                         cudaFuncAttributeMaxDynamicSharedMemorySize, SM_F1);

    // weight pointers (dict order interleaved per layer):
    //   d_in[4 + 4*i + 0]=w12_i, +1=b12_i, +2=w21_i, +3=b21_i
    const float* w[2][5];
    const float* bw[2][5];
    for (int dir = 0; dir < 2; dir++)
        for (int i = 0; i < 5; i++) {
            w[dir][i]  = (const float*)d_in[4 + 4 * i + 2 * dir];
            bw[dir][i] = (const float*)d_in[4 + 4 * i + 2 * dir + 1];
        }

    // prepack conv weights (tf32, final smem layout)
    {
        const int total = 2 * (WP_N0 + WP_N1);
        prepack_kernel<<<(total + 255) / 256, 256>>>(
            w[0][0], w[0][1], w[1][0], w[1][1], wpack);
    }

    const size_t off64 = (size_t)NPIXTOT * 64;
    const size_t off32 = (size_t)NPIXTOT * 32;
    const size_t off2  = (size_t)NPIXTOT * 2;
    const size_t warpOutSz = (size_t)NPIXTOT * 32;
    const size_t upOutSz   = (size_t)BB * 512 * 512 * 2;

    dim3 convGrid(WW / 16, HH / 16, BB);

    for (int dir = 0; dir < 2; dir++) {
        const float* src   = dir ? input_2 : input_1;
        const float* other = dir ? input_1 : input_2;
        const float* flow  = dir ? flow21  : flow12;

        float* catD = cat + (size_t)dir * off64;   // holds warped-32ch first
        float* c0D  = c0  + (size_t)dir * off32;
        float* fcD  = flowch + (size_t)dir * off2;
        const float* wp0 = wpack + (size_t)dir * (WP_N0 + WP_N1);
        const float* wp1 = wp0 + WP_N0;

        warp_kernel<<<NPIXTOT * 8 / 256, 256>>>(src, flow, catD);
        conv3x3_tc_kernel<64, 32, true><<<convGrid, 256, SM_CONV0>>>(
            other, catD, wp0, bw[dir][0], c0D);
        conv3x3_tc_kernel<32, 64, false><<<convGrid, 256, SM_CONV1>>>(
            c0D, nullptr, wp1, bw[dir][1], catD);
        fused1x1_tc_kernel<<<NPIXTOT / 128, 256, SM_F1>>>(
            catD, flow, w[dir][2], bw[dir][2], w[dir][3], bw[dir][3],
            w[dir][4], bw[dir][4], fcD);
        warp_kernel<<<NPIXTOT * 8 / 256, 256>>>(src, fcD, out + (size_t)dir * warpOutSz);
        upsample_kernel<<<BB * 512 * 512 / 256, 256>>>(
            fcD, out + 2 * warpOutSz + (size_t)dir * upOutSz);
    }
}

// round 6
// speedup vs baseline: 4.1448x; 1.2841x over previous
#include <cuda_runtime.h>
#include <cuda_bf16.h>

#define BB 8
#define HH 256
#define WW 256
#define NPIXTOT (BB*HH*WW)

typedef unsigned long long ull;

// ---------------- tf32 helpers ---------------------------------------------
__device__ __forceinline__ float to_tf32(float x) {
    unsigned r;
    asm("cvt.rna.tf32.f32 %0, %1;" : "=r"(r) : "f"(x));
    return __uint_as_float(r);
}
__device__ __forceinline__ void mma_tf32(float* c,
    unsigned a0, unsigned a1, unsigned a2, unsigned a3,
    unsigned b0, unsigned b1)
{
    asm("mma.sync.aligned.m16n8k8.row.col.f32.tf32.tf32.f32 "
        "{%0,%1,%2,%3}, {%4,%5,%6,%7}, {%8,%9}, {%0,%1,%2,%3};"
        : "+f"(c[0]), "+f"(c[1]), "+f"(c[2]), "+f"(c[3])
        : "r"(a0), "r"(a1), "r"(a2), "r"(a3), "r"(b0), "r"(b1));
}

// pos of channel ic within its 8-block after k-pairing: pairs (j, j+4) adjacent
__host__ __device__ __forceinline__ int kpair_pos(int ic) {
    int j = ic & 7;
    return (ic & ~7) + ((j & 3) * 2 + (j >> 2));
}

// ---------------- scratch (device globals; no allocation allowed) ----------
__device__ float g_cat[2ull * NPIXTOT * 64];
__device__ float g_c0[2ull * NPIXTOT * 32];
__device__ float g_flowch[2ull * NPIXTOT * 2];
// prepacked tf32 conv weights, paired-k, padded pitch:
// conv0: [tap][oc<32][72], conv1: [tap][oc<64][40]
#define PITCH0 72
#define PITCH1 40
#define WP_N0 (9*32*PITCH0)
#define WP_N1 (9*64*PITCH1)
__device__ float g_wpack[2 * (WP_N0 + WP_N1)];

// ---------------- weight prepack ------------------------------------------
__global__ void prepack_kernel(
    const float* __restrict__ c0d0, const float* __restrict__ c1d0,
    const float* __restrict__ c0d1, const float* __restrict__ c1d1,
    float* __restrict__ dst)
{
    int i = blockIdx.x * blockDim.x + threadIdx.x;
    const int PER = WP_N0 + WP_N1;
    if (i >= 2 * PER) return;
    int dir = (i >= PER);
    int j = i - dir * PER;
    const float* w;
    int CIN, COUT, PITCH;
    if (j < WP_N0) { w = dir ? c0d1 : c0d0; CIN = 64; COUT = 32; PITCH = PITCH0; }
    else { j -= WP_N0; w = dir ? c1d1 : c1d0; CIN = 32; COUT = 64; PITCH = PITCH1; }
    int pos = j % PITCH;
    int r   = j / PITCH;
    int oc  = r % COUT;
    int tap = r / COUT;
    float v = 0.f;
    if (pos < CIN) {
        // invert pairing: pos -> ic
        int pj = pos & 7;
        int ic = (pos & ~7) + ((pj & 1) * 4 + (pj >> 1));
        v = w[(tap * CIN + ic) * COUT + oc];
    }
    dst[i] = to_tf32(v);
}

// ---------------- warp (32 ch bilinear sample) -----------------------------
__global__ __launch_bounds__(256) void warp_kernel(
    const float* __restrict__ src, const float* __restrict__ flow,
    float* __restrict__ out)
{
    int idx = blockIdx.x * blockDim.x + threadIdx.x;   // NPIXTOT*8 threads
    int c4  = idx & 7;
    int pix = idx >> 3;
    int x = pix & (WW - 1);
    int y = (pix >> 8) & (HH - 1);
    int b = pix >> 16;
    float2 f = ((const float2*)flow)[pix];
    float qy = (float)y - f.x;
    float qx = (float)x - f.y;
    float fy = fminf(fmaxf(floorf(qy), 0.f), (float)(HH - 2));
    float fx = fminf(fmaxf(floorf(qx), 0.f), (float)(WW - 2));
    float ay = fminf(fmaxf(qy - fy, 0.f), 1.f);
    float ax = fminf(fmaxf(qx - fx, 0.f), 1.f);
    int iy = (int)fy, ix = (int)fx;
    const float4* s4 = (const float4*)src;
    int base = ((b * HH + iy) * WW + ix) * 8 + c4;
    float4 tl = s4[base];
    float4 tr = s4[base + 8];
    float4 bl = s4[base + WW * 8];
    float4 br = s4[base + WW * 8 + 8];
    float4 top, bot, r;
    top.x = tl.x + ax * (tr.x - tl.x); top.y = tl.y + ax * (tr.y - tl.y);
    top.z = tl.z + ax * (tr.z - tl.z); top.w = tl.w + ax * (tr.w - tl.w);
    bot.x = bl.x + ax * (br.x - bl.x); bot.y = bl.y + ax * (br.y - bl.y);
    bot.z = bl.z + ax * (br.z - bl.z); bot.w = bl.w + ax * (br.w - bl.w);
    r.x = top.x + ay * (bot.x - top.x); r.y = top.y + ay * (bot.y - top.y);
    r.z = top.z + ay * (bot.z - top.z); r.w = top.w + ay * (bot.w - top.w);
    ((float4*)out)[pix * 8 + c4] = r;
}

// ---------------- conv staging helper: tile to paired-k tf32 ---------------
template<int CIN, bool SPLIT>
__device__ __forceinline__ void stage_tile(
    float* stile, int PITCH, int TW, int TH, int bx, int by, int b,
    const float* inA, const float* inB, int tid, int nthreads)
{
    constexpr int C4 = CIN / 4;
    constexpr int KB = CIN / 8;
    for (int i = tid; i < TH * TW * KB; i += nthreads) {
        int kb = i % KB;
        int p  = i / KB;
        int xx = p % TW;
        int yy = p / TW;
        int gx = bx + xx - 1;
        int gy = by + yy - 1;
        float4 v0 = make_float4(0.f, 0.f, 0.f, 0.f);
        float4 v1 = v0;
        if (gx >= 0 && gx < WW && gy >= 0 && gy < HH) {
            int pix = (b * HH + gy) * WW + gx;
            if (!SPLIT) {
                v0 = ((const float4*)inA)[pix * C4 + 2 * kb];
                v1 = ((const float4*)inA)[pix * C4 + 2 * kb + 1];
            } else if (kb < 4) {
                v0 = ((const float4*)inA)[pix * 8 + 2 * kb];
                v1 = ((const float4*)inA)[pix * 8 + 2 * kb + 1];
            } else {
                v0 = ((const float4*)inB)[pix * 8 + 2 * kb - 8];
                v1 = ((const float4*)inB)[pix * 8 + 2 * kb - 7];
            }
        }
        float2* d = (float2*)(stile + p * PITCH + kb * 8);
        d[0] = make_float2(to_tf32(v0.x), to_tf32(v1.x));
        d[1] = make_float2(to_tf32(v0.y), to_tf32(v1.y));
        d[2] = make_float2(to_tf32(v0.z), to_tf32(v1.z));
        d[3] = make_float2(to_tf32(v0.w), to_tf32(v1.w));
    }
}

// ---------------- conv0: 64->32, tile 16x16, 16 warps, M=16/warp -----------
__global__ __launch_bounds__(512) void conv0_tc_kernel(
    const float* __restrict__ inA, const float* __restrict__ inB,
    const float* __restrict__ wpack, const float* __restrict__ bias,
    float* __restrict__ out)
{
    constexpr int CIN = 64, COUT = 32;
    constexpr int TX = 16, TY = 16;
    constexpr int TW = TX + 2, TH = TY + 2;
    constexpr int PITCH = PITCH0;
    constexpr int NT = COUT / 8;   // 4
    constexpr int KC = CIN / 8;    // 8
    constexpr int WN = WP_N0;

    extern __shared__ float sm[];
    float* stile = sm;                       // TH*TW*PITCH
    float* sw    = sm + TH * TW * PITCH;     // WN
    float* sb    = sw + WN;                  // COUT

    const int bx = blockIdx.x * TX;
    const int by = blockIdx.y * TY;
    const int b  = blockIdx.z;
    const int tid = threadIdx.x;

    {
        const float4* src4 = (const float4*)wpack;
        float4* dst4 = (float4*)sw;
        #pragma unroll 4
        for (int i = tid; i < WN / 4; i += 512) dst4[i] = src4[i];
        if (tid < COUT) sb[tid] = bias[tid];
    }
    stage_tile<CIN, true>(stile, PITCH, TW, TH, bx, by, b, inA, inB, tid, 512);
    __syncthreads();

    const int lane = tid & 31;
    const int w    = tid >> 5;     // warp = output row w
    const int g = lane >> 2;
    const int t = lane & 3;

    float acc[NT][4];
    #pragma unroll
    for (int nt = 0; nt < NT; nt++)
        #pragma unroll
        for (int k = 0; k < 4; k++) acc[nt][k] = 0.f;

    #pragma unroll 1
    for (int tap = 0; tap < 9; tap++) {
        const int dy = tap / 3, dx = tap % 3;
        const float* ab = stile + ((w + dy) * TW + dx) * PITCH;
        const float* wbase = sw + tap * COUT * PITCH;
        #pragma unroll
        for (int kc = 0; kc < KC; kc++) {
            const int ko = kc * 8 + 2 * t;
            float2 pa = *(const float2*)(ab + g * PITCH + ko);
            float2 pb = *(const float2*)(ab + (g + 8) * PITCH + ko);
            unsigned a0 = __float_as_uint(pa.x), a2 = __float_as_uint(pa.y);
            unsigned a1 = __float_as_uint(pb.x), a3 = __float_as_uint(pb.y);
            #pragma unroll
            for (int nt = 0; nt < NT; nt++) {
                float2 pw = *(const float2*)(wbase + (nt * 8 + g) * PITCH + ko);
                mma_tf32(acc[nt], a0, a1, a2, a3,
                         __float_as_uint(pw.x), __float_as_uint(pw.y));
            }
        }
    }

    const int gy = by + w;
    float* orow0 = out + ((size_t)((b * HH + gy) * WW + bx + g)) * COUT;
    float* orow1 = orow0 + 8 * COUT;
    #pragma unroll
    for (int nt = 0; nt < NT; nt++) {
        int oc = nt * 8 + 2 * t;
        float bi0 = sb[oc], bi1 = sb[oc + 1];
        *(float2*)(orow0 + oc) = make_float2(fmaxf(acc[nt][0] + bi0, 0.f),
                                             fmaxf(acc[nt][1] + bi1, 0.f));
        *(float2*)(orow1 + oc) = make_float2(fmaxf(acc[nt][2] + bi0, 0.f),
                                             fmaxf(acc[nt][3] + bi1, 0.f));
    }
}

// ---------------- conv1: 32->64, tile 16x32, 16 warps, M=32/warp -----------
__global__ __launch_bounds__(512) void conv1_tc_kernel(
    const float* __restrict__ in,
    const float* __restrict__ wpack, const float* __restrict__ bias,
    float* __restrict__ out)
{
    constexpr int CIN = 32, COUT = 64;
    constexpr int TX = 16, TY = 32;
    constexpr int TW = TX + 2, TH = TY + 2;
    constexpr int PITCH = PITCH1;
    constexpr int NT = COUT / 8;   // 8
    constexpr int KC = CIN / 8;    // 4
    constexpr int WN = WP_N1;

    extern __shared__ float sm[];
    float* stile = sm;                       // TH*TW*PITCH
    float* sw    = sm + TH * TW * PITCH;     // WN
    float* sb    = sw + WN;                  // COUT

    const int bx = blockIdx.x * TX;
    const int by = blockIdx.y * TY;
    const int b  = blockIdx.z;
    const int tid = threadIdx.x;

    {
        const float4* src4 = (const float4*)wpack;
        float4* dst4 = (float4*)sw;
        #pragma unroll 4
        for (int i = tid; i < WN / 4; i += 512) dst4[i] = src4[i];
        if (tid < COUT) sb[tid] = bias[tid];
    }
    stage_tile<CIN, false>(stile, PITCH, TW, TH, bx, by, b, in, nullptr, tid, 512);
    __syncthreads();

    const int lane = tid & 31;
    const int w    = tid >> 5;     // warp = rows 2w, 2w+1
    const int g = lane >> 2;
    const int t = lane & 3;

    float acc0[NT][4], acc1[NT][4];
    #pragma unroll
    for (int nt = 0; nt < NT; nt++)
        #pragma unroll
        for (int k = 0; k < 4; k++) { acc0[nt][k] = 0.f; acc1[nt][k] = 0.f; }

    #pragma unroll 1
    for (int tap = 0; tap < 9; tap++) {
        const int dy = tap / 3, dx = tap % 3;
        const float* a0b = stile + ((2 * w + dy) * TW + dx) * PITCH;
        const float* a1b = a0b + TW * PITCH;
        const float* wbase = sw + tap * COUT * PITCH;
        #pragma unroll
        for (int kc = 0; kc < KC; kc++) {
            const int ko = kc * 8 + 2 * t;
            float2 pa0 = *(const float2*)(a0b + g * PITCH + ko);
            float2 pb0 = *(const float2*)(a0b + (g + 8) * PITCH + ko);
            float2 pa1 = *(const float2*)(a1b + g * PITCH + ko);
            float2 pb1 = *(const float2*)(a1b + (g + 8) * PITCH + ko);
            unsigned q00 = __float_as_uint(pa0.x), q02 = __float_as_uint(pa0.y);
            unsigned q01 = __float_as_uint(pb0.x), q03 = __float_as_uint(pb0.y);
            unsigned q10 = __float_as_uint(pa1.x), q12 = __float_as_uint(pa1.y);
            unsigned q11 = __float_as_uint(pb1.x), q13 = __float_as_uint(pb1.y);
            #pragma unroll
            for (int nt = 0; nt < NT; nt++) {
                float2 pw = *(const float2*)(wbase + (nt * 8 + g) * PITCH + ko);
                unsigned b0 = __float_as_uint(pw.x), b1 = __float_as_uint(pw.y);
                mma_tf32(acc0[nt], q00, q01, q02, q03, b0, b1);
                mma_tf32(acc1[nt], q10, q11, q12, q13, b0, b1);
            }
        }
    }

    #pragma unroll
    for (int rr = 0; rr < 2; rr++) {
        const int gy = by + 2 * w + rr;
        float (*acc)[4] = rr ? acc1 : acc0;
        float* orow0 = out + ((size_t)((b * HH + gy) * WW + bx + g)) * COUT;
        float* orow1 = orow0 + 8 * COUT;
        #pragma unroll
        for (int nt = 0; nt < NT; nt++) {
            int oc = nt * 8 + 2 * t;
            float bi0 = sb[oc], bi1 = sb[oc + 1];
            *(float2*)(orow0 + oc) = make_float2(fmaxf(acc[nt][0] + bi0, 0.f),
                                                 fmaxf(acc[nt][1] + bi1, 0.f));
            *(float2*)(orow1 + oc) = make_float2(fmaxf(acc[nt][2] + bi0, 0.f),
                                                 fmaxf(acc[nt][3] + bi1, 0.f));
        }
    }
}

// ---------------- fused 1x1 chain via tf32 MMA -----------------------------
__global__ __launch_bounds__(256) void fused1x1_tc_kernel(
    const float* __restrict__ in, const float* __restrict__ flow,
    const float* __restrict__ w2, const float* __restrict__ b2,
    const float* __restrict__ w3, const float* __restrict__ b3,
    const float* __restrict__ w4, const float* __restrict__ b4,
    float* __restrict__ flowch)
{
    extern __shared__ float sm[];
    float* sin  = sm;                 // 128*68
    float* sw2s = sin + 128 * 68;     // 64*68
    float* sw3s = sw2s + 64 * 68;     // 16*68
    float* sb2  = sw3s + 16 * 68;     // 64
    float* sb3  = sb2 + 64;           // 16
    float* sw4s = sb3 + 16;           // 32
    float* sb4  = sw4s + 32;          // 2

    const int tid = threadIdx.x;

    {
        const float4* gin4 = (const float4*)(in + (size_t)blockIdx.x * 128 * 64);
        #pragma unroll 4
        for (int i = tid; i < 128 * 16; i += 256) {
            int pix = i >> 4, c4 = i & 15;
            float4 v = gin4[i];
            float* d = sin + pix * 68 + c4 * 4;
            d[0] = to_tf32(v.x); d[1] = to_tf32(v.y);
            d[2] = to_tf32(v.z); d[3] = to_tf32(v.w);
        }
    }
    for (int i = tid; i < 4096; i += 256) {
        int oc = i & 63, ic = i >> 6;
        sw2s[oc * 68 + ic] = to_tf32(w2[i]);
    }
    for (int i = tid; i < 1024; i += 256) {
        int oc = i & 15, ic = i >> 4;
        sw3s[oc * 68 + ic] = to_tf32(w3[i]);
    }
    if (tid < 64) sb2[tid] = b2[tid];
    if (tid < 16) sb3[tid] = b3[tid];
    if (tid < 32) sw4s[tid] = w4[tid];
    if (tid < 2)  sb4[tid] = b4[tid];
    __syncthreads();

    const int lane = tid & 31;
    const int w = tid >> 5;
    const int g = lane >> 2;
    const int t = lane & 3;
    float* arow = sin + (w * 16) * 68;

    float acc[8][4];
    #pragma unroll
    for (int nt = 0; nt < 8; nt++)
        #pragma unroll
        for (int k = 0; k < 4; k++) acc[nt][k] = 0.f;

    #pragma unroll
    for (int kc = 0; kc < 8; kc++) {
        const int ic = kc * 8 + t;
        unsigned a0 = __float_as_uint(arow[g * 68 + ic]);
        unsigned a1 = __float_as_uint(arow[(g + 8) * 68 + ic]);
        unsigned a2 = __float_as_uint(arow[g * 68 + ic + 4]);
        unsigned a3 = __float_as_uint(arow[(g + 8) * 68 + ic + 4]);
        #pragma unroll
        for (int nt = 0; nt < 8; nt++) {
            const float* wrow = sw2s + (nt * 8 + g) * 68;
            unsigned b0 = __float_as_uint(wrow[ic]);
            unsigned b1 = __float_as_uint(wrow[ic + 4]);
            mma_tf32(acc[nt], a0, a1, a2, a3, b0, b1);
        }
    }
    #pragma unroll
    for (int nt = 0; nt < 8; nt++) {
        int oc = nt * 8 + 2 * t;
        float bi0 = sb2[oc], bi1 = sb2[oc + 1];
        float2 h0 = make_float2(to_tf32(fmaxf(acc[nt][0] + bi0, 0.f)),
                                to_tf32(fmaxf(acc[nt][1] + bi1, 0.f)));
        float2 h1 = make_float2(to_tf32(fmaxf(acc[nt][2] + bi0, 0.f)),
                                to_tf32(fmaxf(acc[nt][3] + bi1, 0.f)));
        *(float2*)(arow + g * 68 + oc)       = h0;
        *(float2*)(arow + (g + 8) * 68 + oc) = h1;
    }
    __syncwarp();

    float acc3[2][4];
    #pragma unroll
    for (int nt = 0; nt < 2; nt++)
        #pragma unroll
        for (int k = 0; k < 4; k++) acc3[nt][k] = 0.f;

    #pragma unroll
    for (int kc = 0; kc < 8; kc++) {
        const int ic = kc * 8 + t;
        unsigned a0 = __float_as_uint(arow[g * 68 + ic]);
        unsigned a1 = __float_as_uint(arow[(g + 8) * 68 + ic]);
        unsigned a2 = __float_as_uint(arow[g * 68 + ic + 4]);
        unsigned a3 = __float_as_uint(arow[(g + 8) * 68 + ic + 4]);
        #pragma unroll
        for (int nt = 0; nt < 2; nt++) {
            const float* wrow = sw3s + (nt * 8 + g) * 68;
            unsigned b0 = __float_as_uint(wrow[ic]);
            unsigned b1 = __float_as_uint(wrow[ic + 4]);
            mma_tf32(acc3[nt], a0, a1, a2, a3, b0, b1);
        }
    }

    float o0a = 0.f, o1a = 0.f, o0b = 0.f, o1b = 0.f;
    #pragma unroll
    for (int nt = 0; nt < 2; nt++) {
        #pragma unroll
        for (int p = 0; p < 2; p++) {
            int col = nt * 8 + 2 * t + p;
            float bi = sb3[col];
            float w0 = sw4s[col * 2], w1 = sw4s[col * 2 + 1];
            float va = fmaxf(acc3[nt][p] + bi, 0.f);
            float vb = fmaxf(acc3[nt][2 + p] + bi, 0.f);
            o0a = fmaf(va, w0, o0a); o1a = fmaf(va, w1, o1a);
            o0b = fmaf(vb, w0, o0b); o1b = fmaf(vb, w1, o1b);
        }
    }
    #pragma unroll
    for (int m = 1; m <= 2; m <<= 1) {
        o0a += __shfl_xor_sync(0xffffffffu, o0a, m);
        o1a += __shfl_xor_sync(0xffffffffu, o1a, m);
        o0b += __shfl_xor_sync(0xffffffffu, o0b, m);
        o1b += __shfl_xor_sync(0xffffffffu, o1b, m);
    }
    if (t == 0) {
        size_t pix0 = (size_t)blockIdx.x * 128 + w * 16 + g;
        float2 f0 = ((const float2*)flow)[pix0];
        float2 f1 = ((const float2*)flow)[pix0 + 8];
        ((float2*)flowch)[pix0]     = make_float2(f0.x + o0a + sb4[0], f0.y + o1a + sb4[1]);
        ((float2*)flowch)[pix0 + 8] = make_float2(f1.x + o0b + sb4[0], f1.y + o1b + sb4[1]);
    }
}

// ---------------- 2x bilinear upsample (jax.image.resize semantics) -------
__global__ __launch_bounds__(256) void upsample_kernel(
    const float* __restrict__ src, float* __restrict__ out)
{
    int idx = blockIdx.x * blockDim.x + threadIdx.x;
    int x = idx & 511;
    int y = (idx >> 9) & 511;
    int b = idx >> 18;
    float sy = 0.5f * (float)y - 0.25f;
    float sx = 0.5f * (float)x - 0.25f;
    float y0f = floorf(sy), x0f = floorf(sx);
    float wy = sy - y0f,    wx = sx - x0f;
    int y0 = (int)y0f, x0 = (int)x0f;
    int ya = max(y0, 0), yb = min(y0 + 1, HH - 1);
    int xa = max(x0, 0), xb = min(x0 + 1, WW - 1);
    const float2* s = (const float2*)src;
    float2 v00 = s[(b * HH + ya) * WW + xa];
    float2 v01 = s[(b * HH + ya) * WW + xb];
    float2 v10 = s[(b * HH + yb) * WW + xa];
    float2 v11 = s[(b * HH + yb) * WW + xb];
    float2 r;
    r.x = (1.f - wy) * ((1.f - wx) * v00.x + wx * v01.x)
        +        wy  * ((1.f - wx) * v10.x + wx * v11.x);
    r.y = (1.f - wy) * ((1.f - wx) * v00.y + wx * v01.y)
        +        wy  * ((1.f - wx) * v10.y + wx * v11.y);
    ((float2*)out)[idx] = r;
}

// ---------------- launch ---------------------------------------------------
extern "C" void kernel_launch(void* const* d_in, const int* in_sizes, int n_in,
                              void* d_out, int out_size)
{
    (void)in_sizes; (void)n_in; (void)out_size;
    const float* input_1 = (const float*)d_in[0];
    const float* input_2 = (const float*)d_in[1];
    const float* flow12  = (const float*)d_in[2];
    const float* flow21  = (const float*)d_in[3];
    float* out = (float*)d_out;

    float *cat, *c0, *flowch, *wpack;
    cudaGetSymbolAddress((void**)&cat,    g_cat);
    cudaGetSymbolAddress((void**)&c0,     g_c0);
    cudaGetSymbolAddress((void**)&flowch, g_flowch);
    cudaGetSymbolAddress((void**)&wpack,  g_wpack);

    const int SM_CONV0 = (18 * 18 * PITCH0 + WP_N0 + 32) * 4;  // ~176 KB
    const int SM_CONV1 = (34 * 18 * PITCH1 + WP_N1 + 64) * 4;  // ~190 KB
    const int SM_F1    = (128 * 68 + 64 * 68 + 16 * 68 + 64 + 16 + 32 + 2) * 4;
    cudaFuncSetAttribute(conv0_tc_kernel,
                         cudaFuncAttributeMaxDynamicSharedMemorySize, SM_CONV0);
    cudaFuncSetAttribute(conv1_tc_kernel,
                         cudaFuncAttributeMaxDynamicSharedMemorySize, SM_CONV1);
    cudaFuncSetAttribute(fused1x1_tc_kernel,
                         cudaFuncAttributeMaxDynamicSharedMemorySize, SM_F1);

    const float* w[2][5];
    const float* bw[2][5];
    for (int dir = 0; dir < 2; dir++)
        for (int i = 0; i < 5; i++) {
            w[dir][i]  = (const float*)d_in[4 + 4 * i + 2 * dir];
            bw[dir][i] = (const float*)d_in[4 + 4 * i + 2 * dir + 1];
        }

    {
        const int total = 2 * (WP_N0 + WP_N1);
        prepack_kernel<<<(total + 255) / 256, 256>>>(
            w[0][0], w[0][1], w[1][0], w[1][1], wpack);
    }

    const size_t off64 = (size_t)NPIXTOT * 64;
    const size_t off32 = (size_t)NPIXTOT * 32;
    const size_t off2  = (size_t)NPIXTOT * 2;
    const size_t warpOutSz = (size_t)NPIXTOT * 32;
    const size_t upOutSz   = (size_t)BB * 512 * 512 * 2;

    dim3 grid0(WW / 16, HH / 16, BB);
    dim3 grid1(WW / 16, HH / 32, BB);

    for (int dir = 0; dir < 2; dir++) {
        const float* src   = dir ? input_2 : input_1;
        const float* other = dir ? input_1 : input_2;
        const float* flow  = dir ? flow21  : flow12;

        float* catD = cat + (size_t)dir * off64;
        float* c0D  = c0  + (size_t)dir * off32;
        float* fcD  = flowch + (size_t)dir * off2;
        const float* wp0 = wpack + (size_t)dir * (WP_N0 + WP_N1);
        const float* wp1 = wp0 + WP_N0;

        warp_kernel<<<NPIXTOT * 8 / 256, 256>>>(src, flow, catD);
        conv0_tc_kernel<<<grid0, 512, SM_CONV0>>>(other, catD, wp0, bw[dir][0], c0D);
        conv1_tc_kernel<<<grid1, 512, SM_CONV1>>>(c0D, wp1, bw[dir][1], catD);
        fused1x1_tc_kernel<<<NPIXTOT / 128, 256, SM_F1>>>(
            catD, flow, w[dir][2], bw[dir][2], w[dir][3], bw[dir][3],
            w[dir][4], bw[dir][4], fcD);
        warp_kernel<<<NPIXTOT * 8 / 256, 256>>>(src, fcD, out + (size_t)dir * warpOutSz);
        upsample_kernel<<<BB * 512 * 512 / 256, 256>>>(
            fcD, out + 2 * warpOutSz + (size_t)dir * upOutSz);
    }
}

// round 7
// speedup vs baseline: 5.2010x; 1.2548x over previous
#include <cuda_runtime.h>
#include <cuda_bf16.h>

#define BB 8
#define HH 256
#define WW 256
#define NPIXTOT (BB*HH*WW)

typedef unsigned long long ull;

// ---------------- tf32 helpers (fused1x1) ----------------------------------
__device__ __forceinline__ float to_tf32(float x) {
    unsigned r;
    asm("cvt.rna.tf32.f32 %0, %1;" : "=r"(r) : "f"(x));
    return __uint_as_float(r);
}
__device__ __forceinline__ void mma_tf32(float* c,
    unsigned a0, unsigned a1, unsigned a2, unsigned a3,
    unsigned b0, unsigned b1)
{
    asm("mma.sync.aligned.m16n8k8.row.col.f32.tf32.tf32.f32 "
        "{%0,%1,%2,%3}, {%4,%5,%6,%7}, {%8,%9}, {%0,%1,%2,%3};"
        : "+f"(c[0]), "+f"(c[1]), "+f"(c[2]), "+f"(c[3])
        : "r"(a0), "r"(a1), "r"(a2), "r"(a3), "r"(b0), "r"(b1));
}

// ---------------- bf16 helpers ---------------------------------------------
__device__ __forceinline__ unsigned bf2(float lo, float hi) {
    __nv_bfloat162 h = __floats2bfloat162_rn(lo, hi);
    return *(unsigned*)&h;
}
// D(16x8) += A(16x16) * B(16x8), bf16 inputs, fp32 accum
__device__ __forceinline__ void mma_bf16(float* c,
    unsigned a0, unsigned a1, unsigned a2, unsigned a3,
    unsigned b0, unsigned b1)
{
    asm("mma.sync.aligned.m16n8k16.row.col.f32.bf16.bf16.f32 "
        "{%0,%1,%2,%3}, {%4,%5,%6,%7}, {%8,%9}, {%0,%1,%2,%3};"
        : "+f"(c[0]), "+f"(c[1]), "+f"(c[2]), "+f"(c[3])
        : "r"(a0), "r"(a1), "r"(a2), "r"(a3), "r"(b0), "r"(b1));
}

// ---------------- scratch (device globals; no allocation allowed) ----------
__device__ float g_cat[2ull * NPIXTOT * 64];
__device__ float g_c0[2ull * NPIXTOT * 32];
__device__ float g_flowch[2ull * NPIXTOT * 2];

// prepacked bf16 conv weights, pair-interleaved k, padded row pitch (words):
//   conv0: rows [tap*32+oc], PW0=36 words (72 bf16)
//   conv1: rows [tap*64+oc], PW1=20 words (40 bf16)
#define PW0 36
#define PW1 20
#define WPW_N0 (9*32*PW0)   /* words */
#define WPW_N1 (9*64*PW1)
__device__ unsigned g_wpack[2 * (WPW_N0 + WPW_N1)];

// word w (0..7) within a 16-channel block holds channel pair q = (w>>1)+(w&1)*4
// (pairs laid out [p0,p4,p1,p5,p2,p6,p3,p7] so thread t LDS.64s words 2t,2t+1
//  = channels {2t,2t+1, 2t+8,2t+9} = exactly the m16n8k16 fragment k-slices)

// ---------------- weight prepack (bf16 pairs, final smem image) ------------
__global__ void prepack_kernel(
    const float* __restrict__ c0d0, const float* __restrict__ c1d0,
    const float* __restrict__ c0d1, const float* __restrict__ c1d1,
    unsigned* __restrict__ dst)
{
    int i = blockIdx.x * blockDim.x + threadIdx.x;   // word index
    const int PER = WPW_N0 + WPW_N1;
    if (i >= 2 * PER) return;
    int dir = (i >= PER);
    int j = i - dir * PER;
    const float* w;
    int CIN, COUT, PW;
    if (j < WPW_N0) { w = dir ? c0d1 : c0d0; CIN = 64; COUT = 32; PW = PW0; }
    else { j -= WPW_N0; w = dir ? c1d1 : c1d0; CIN = 32; COUT = 64; PW = PW1; }
    int word = j % PW;
    int r    = j / PW;
    int oc   = r % COUT;
    int tap  = r / COUT;
    float lo = 0.f, hi = 0.f;
    int block = word >> 3, ww = word & 7;
    int q  = (ww >> 1) + (ww & 1) * 4;
    int ch = block * 16 + 2 * q;
    if (ch < CIN) {
        lo = w[(tap * CIN + ch) * COUT + oc];
        hi = w[(tap * CIN + ch + 1) * COUT + oc];
    }
    dst[i] = bf2(lo, hi);
}

// ---------------- warp (32 ch bilinear sample) -----------------------------
__global__ __launch_bounds__(256) void warp_kernel(
    const float* __restrict__ src, const float* __restrict__ flow,
    float* __restrict__ out)
{
    int idx = blockIdx.x * blockDim.x + threadIdx.x;   // NPIXTOT*8 threads
    int c4  = idx & 7;
    int pix = idx >> 3;
    int x = pix & (WW - 1);
    int y = (pix >> 8) & (HH - 1);
    int b = pix >> 16;
    float2 f = ((const float2*)flow)[pix];
    float qy = (float)y - f.x;
    float qx = (float)x - f.y;
    float fy = fminf(fmaxf(floorf(qy), 0.f), (float)(HH - 2));
    float fx = fminf(fmaxf(floorf(qx), 0.f), (float)(WW - 2));
    float ay = fminf(fmaxf(qy - fy, 0.f), 1.f);
    float ax = fminf(fmaxf(qx - fx, 0.f), 1.f);
    int iy = (int)fy, ix = (int)fx;
    const float4* s4 = (const float4*)src;
    int base = ((b * HH + iy) * WW + ix) * 8 + c4;
    float4 tl = s4[base];
    float4 tr = s4[base + 8];
    float4 bl = s4[base + WW * 8];
    float4 br = s4[base + WW * 8 + 8];
    float4 top, bot, r;
    top.x = tl.x + ax * (tr.x - tl.x); top.y = tl.y + ax * (tr.y - tl.y);
    top.z = tl.z + ax * (tr.z - tl.z); top.w = tl.w + ax * (tr.w - tl.w);
    bot.x = bl.x + ax * (br.x - bl.x); bot.y = bl.y + ax * (br.y - bl.y);
    bot.z = bl.z + ax * (br.z - bl.z); bot.w = bl.w + ax * (br.w - bl.w);
    r.x = top.x + ay * (bot.x - top.x); r.y = top.y + ay * (bot.y - top.y);
    r.z = top.z + ay * (bot.z - top.z); r.w = top.w + ay * (bot.w - top.w);
    ((float4*)out)[pix * 8 + c4] = r;
}

// ---------------- conv staging: tile -> bf16 pair-interleaved --------------
template<int CIN, bool SPLIT>
__device__ __forceinline__ void stage_tile_bf16(
    unsigned* tile, int PW, int TW, int TH, int bx, int by, int b,
    const float* inA, const float* inB, int tid, int nthreads)
{
    constexpr int C4 = CIN / 4;
    constexpr int KB = CIN / 16;
    for (int i = tid; i < TH * TW * KB; i += nthreads) {
        int kb = i % KB;
        int p  = i / KB;
        int xx = p % TW;
        int yy = p / TW;
        int gx = bx + xx - 1;
        int gy = by + yy - 1;
        float4 v0 = make_float4(0.f,0.f,0.f,0.f), v1 = v0, v2 = v0, v3 = v0;
        if (gx >= 0 && gx < WW && gy >= 0 && gy < HH) {
            int pix = (b * HH + gy) * WW + gx;
            int c4 = kb * 4;
            if (!SPLIT) {
                const float4* s = (const float4*)inA + (size_t)pix * C4 + c4;
                v0 = s[0]; v1 = s[1]; v2 = s[2]; v3 = s[3];
            } else if (c4 < 8) {
                const float4* s = (const float4*)inA + (size_t)pix * 8 + c4;
                v0 = s[0]; v1 = s[1]; v2 = s[2]; v3 = s[3];
            } else {
                const float4* s = (const float4*)inB + (size_t)pix * 8 + (c4 - 8);
                v0 = s[0]; v1 = s[1]; v2 = s[2]; v3 = s[3];
            }
        }
        // pairs: v0.xy=p0 v0.zw=p1 v1.xy=p2 v1.zw=p3 v2.xy=p4 v2.zw=p5 v3.xy=p6 v3.zw=p7
        uint4 wlo, whi;
        wlo.x = bf2(v0.x, v0.y);  // p0
        wlo.y = bf2(v2.x, v2.y);  // p4
        wlo.z = bf2(v0.z, v0.w);  // p1
        wlo.w = bf2(v2.z, v2.w);  // p5
        whi.x = bf2(v1.x, v1.y);  // p2
        whi.y = bf2(v3.x, v3.y);  // p6
        whi.z = bf2(v1.z, v1.w);  // p3
        whi.w = bf2(v3.z, v3.w);  // p7
        uint4* d = (uint4*)(tile + p * PW + kb * 8);
        d[0] = wlo;
        d[1] = whi;
    }
}

// ---------------- conv0: 64->32, tile 16x16, 16 warps, M=16/warp -----------
__global__ __launch_bounds__(512) void conv0_tc_kernel(
    const float* __restrict__ inA, const float* __restrict__ inB,
    const unsigned* __restrict__ wpack, const float* __restrict__ bias,
    float* __restrict__ out)
{
    constexpr int CIN = 64, COUT = 32;
    constexpr int TX = 16, TY = 16;
    constexpr int TW = TX + 2, TH = TY + 2;
    constexpr int PW = PW0;
    constexpr int NT = COUT / 8;     // 4
    constexpr int KC = CIN / 16;     // 4
    constexpr int TILE_W = TH * TW * PW;
    constexpr int WN = WPW_N0;

    extern __shared__ unsigned smw[];
    unsigned* tile = smw;
    unsigned* sw   = smw + TILE_W;
    float*    sb   = (float*)(sw + WN);

    const int bx = blockIdx.x * TX;
    const int by = blockIdx.y * TY;
    const int b  = blockIdx.z;
    const int tid = threadIdx.x;

    {
        const uint4* s4 = (const uint4*)wpack;
        uint4* d4 = (uint4*)sw;
        #pragma unroll 4
        for (int i = tid; i < WN / 4; i += 512) d4[i] = s4[i];
        if (tid < COUT) sb[tid] = bias[tid];
    }
    stage_tile_bf16<CIN, true>(tile, PW, TW, TH, bx, by, b, inA, inB, tid, 512);
    __syncthreads();

    const int lane = tid & 31;
    const int w    = tid >> 5;     // warp = output row w
    const int g = lane >> 2;
    const int t = lane & 3;

    float acc[NT][4];
    #pragma unroll
    for (int nt = 0; nt < NT; nt++)
        #pragma unroll
        for (int k = 0; k < 4; k++) acc[nt][k] = 0.f;

    #pragma unroll 1
    for (int tap = 0; tap < 9; tap++) {
        const int dy = tap / 3, dx = tap % 3;
        const unsigned* ab = tile + ((w + dy) * TW + dx) * PW;
        const unsigned* wb = sw + tap * COUT * PW;
        #pragma unroll
        for (int kb = 0; kb < KC; kb++) {
            const int ko = kb * 8 + 2 * t;
            uint2 ra = *(const uint2*)(ab + g * PW + ko);
            uint2 rb = *(const uint2*)(ab + (g + 8) * PW + ko);
            #pragma unroll
            for (int nt = 0; nt < NT; nt++) {
                uint2 wv = *(const uint2*)(wb + (nt * 8 + g) * PW + ko);
                mma_bf16(acc[nt], ra.x, rb.x, ra.y, rb.y, wv.x, wv.y);
            }
        }
    }

    const int gy = by + w;
    float* orow0 = out + ((size_t)((b * HH + gy) * WW + bx + g)) * COUT;
    float* orow1 = orow0 + 8 * COUT;
    #pragma unroll
    for (int nt = 0; nt < NT; nt++) {
        int oc = nt * 8 + 2 * t;
        float bi0 = sb[oc], bi1 = sb[oc + 1];
        *(float2*)(orow0 + oc) = make_float2(fmaxf(acc[nt][0] + bi0, 0.f),
                                             fmaxf(acc[nt][1] + bi1, 0.f));
        *(float2*)(orow1 + oc) = make_float2(fmaxf(acc[nt][2] + bi0, 0.f),
                                             fmaxf(acc[nt][3] + bi1, 0.f));
    }
}

// ---------------- conv1: 32->64, tile 16x32, 16 warps, M=32/warp -----------
__global__ __launch_bounds__(512) void conv1_tc_kernel(
    const float* __restrict__ in,
    const unsigned* __restrict__ wpack, const float* __restrict__ bias,
    float* __restrict__ out)
{
    constexpr int CIN = 32, COUT = 64;
    constexpr int TX = 16, TY = 32;
    constexpr int TW = TX + 2, TH = TY + 2;
    constexpr int PW = PW1;
    constexpr int NT = COUT / 8;     // 8
    constexpr int KC = CIN / 16;     // 2
    constexpr int TILE_W = TH * TW * PW;
    constexpr int WN = WPW_N1;

    extern __shared__ unsigned smw[];
    unsigned* tile = smw;
    unsigned* sw   = smw + TILE_W;
    float*    sb   = (float*)(sw + WN);

    const int bx = blockIdx.x * TX;
    const int by = blockIdx.y * TY;
    const int b  = blockIdx.z;
    const int tid = threadIdx.x;

    {
        const uint4* s4 = (const uint4*)wpack;
        uint4* d4 = (uint4*)sw;
        #pragma unroll 4
        for (int i = tid; i < WN / 4; i += 512) d4[i] = s4[i];
        if (tid < COUT) sb[tid] = bias[tid];
    }
    stage_tile_bf16<CIN, false>(tile, PW, TW, TH, bx, by, b, in, nullptr, tid, 512);
    __syncthreads();

    const int lane = tid & 31;
    const int w    = tid >> 5;     // warp = rows 2w, 2w+1
    const int g = lane >> 2;
    const int t = lane & 3;

    float acc0[NT][4], acc1[NT][4];
    #pragma unroll
    for (int nt = 0; nt < NT; nt++)
        #pragma unroll
        for (int k = 0; k < 4; k++) { acc0[nt][k] = 0.f; acc1[nt][k] = 0.f; }

    #pragma unroll 1
    for (int tap = 0; tap < 9; tap++) {
        const int dy = tap / 3, dx = tap % 3;
        const unsigned* a0b = tile + ((2 * w + dy) * TW + dx) * PW;
        const unsigned* a1b = a0b + TW * PW;
        const unsigned* wb  = sw + tap * COUT * PW;
        #pragma unroll
        for (int kb = 0; kb < KC; kb++) {
            const int ko = kb * 8 + 2 * t;
            uint2 ra0 = *(const uint2*)(a0b + g * PW + ko);
            uint2 rb0 = *(const uint2*)(a0b + (g + 8) * PW + ko);
            uint2 ra1 = *(const uint2*)(a1b + g * PW + ko);
            uint2 rb1 = *(const uint2*)(a1b + (g + 8) * PW + ko);
            #pragma unroll
            for (int nt = 0; nt < NT; nt++) {
                uint2 wv = *(const uint2*)(wb + (nt * 8 + g) * PW + ko);
                mma_bf16(acc0[nt], ra0.x, rb0.x, ra0.y, rb0.y, wv.x, wv.y);
                mma_bf16(acc1[nt], ra1.x, rb1.x, ra1.y, rb1.y, wv.x, wv.y);
            }
        }
    }

    #pragma unroll
    for (int rr = 0; rr < 2; rr++) {
        const int gy = by + 2 * w + rr;
        float (*acc)[4] = rr ? acc1 : acc0;
        float* orow0 = out + ((size_t)((b * HH + gy) * WW + bx + g)) * COUT;
        float* orow1 = orow0 + 8 * COUT;
        #pragma unroll
        for (int nt = 0; nt < NT; nt++) {
            int oc = nt * 8 + 2 * t;
            float bi0 = sb[oc], bi1 = sb[oc + 1];
            *(float2*)(orow0 + oc) = make_float2(fmaxf(acc[nt][0] + bi0, 0.f),
                                                 fmaxf(acc[nt][1] + bi1, 0.f));
            *(float2*)(orow1 + oc) = make_float2(fmaxf(acc[nt][2] + bi0, 0.f),
                                                 fmaxf(acc[nt][3] + bi1, 0.f));
        }
    }
}

// ---------------- fused 1x1 chain via tf32 MMA -----------------------------
__global__ __launch_bounds__(256) void fused1x1_tc_kernel(
    const float* __restrict__ in, const float* __restrict__ flow,
    const float* __restrict__ w2, const float* __restrict__ b2,
    const float* __restrict__ w3, const float* __restrict__ b3,
    const float* __restrict__ w4, const float* __restrict__ b4,
    float* __restrict__ flowch)
{
    extern __shared__ float sm[];
    float* sin  = sm;                 // 128*68
    float* sw2s = sin + 128 * 68;     // 64*68
    float* sw3s = sw2s + 64 * 68;     // 16*68
    float* sb2  = sw3s + 16 * 68;     // 64
    float* sb3  = sb2 + 64;           // 16
    float* sw4s = sb3 + 16;           // 32
    float* sb4  = sw4s + 32;          // 2

    const int tid = threadIdx.x;

    {
        const float4* gin4 = (const float4*)(in + (size_t)blockIdx.x * 128 * 64);
        #pragma unroll 4
        for (int i = tid; i < 128 * 16; i += 256) {
            int pix = i >> 4, c4 = i & 15;
            float4 v = gin4[i];
            float* d = sin + pix * 68 + c4 * 4;
            d[0] = to_tf32(v.x); d[1] = to_tf32(v.y);
            d[2] = to_tf32(v.z); d[3] = to_tf32(v.w);
        }
    }
    for (int i = tid; i < 4096; i += 256) {
        int oc = i & 63, ic = i >> 6;
        sw2s[oc * 68 + ic] = to_tf32(w2[i]);
    }
    for (int i = tid; i < 1024; i += 256) {
        int oc = i & 15, ic = i >> 4;
        sw3s[oc * 68 + ic] = to_tf32(w3[i]);
    }
    if (tid < 64) sb2[tid] = b2[tid];
    if (tid < 16) sb3[tid] = b3[tid];
    if (tid < 32) sw4s[tid] = w4[tid];
    if (tid < 2)  sb4[tid] = b4[tid];
    __syncthreads();

    const int lane = tid & 31;
    const int w = tid >> 5;
    const int g = lane >> 2;
    const int t = lane & 3;
    float* arow = sin + (w * 16) * 68;

    float acc[8][4];
    #pragma unroll
    for (int nt = 0; nt < 8; nt++)
        #pragma unroll
        for (int k = 0; k < 4; k++) acc[nt][k] = 0.f;

    #pragma unroll
    for (int kc = 0; kc < 8; kc++) {
        const int ic = kc * 8 + t;
        unsigned a0 = __float_as_uint(arow[g * 68 + ic]);
        unsigned a1 = __float_as_uint(arow[(g + 8) * 68 + ic]);
        unsigned a2 = __float_as_uint(arow[g * 68 + ic + 4]);
        unsigned a3 = __float_as_uint(arow[(g + 8) * 68 + ic + 4]);
        #pragma unroll
        for (int nt = 0; nt < 8; nt++) {
            const float* wrow = sw2s + (nt * 8 + g) * 68;
            unsigned b0 = __float_as_uint(wrow[ic]);
            unsigned b1 = __float_as_uint(wrow[ic + 4]);
            mma_tf32(acc[nt], a0, a1, a2, a3, b0, b1);
        }
    }
    #pragma unroll
    for (int nt = 0; nt < 8; nt++) {
        int oc = nt * 8 + 2 * t;
        float bi0 = sb2[oc], bi1 = sb2[oc + 1];
        float2 h0 = make_float2(to_tf32(fmaxf(acc[nt][0] + bi0, 0.f)),
                                to_tf32(fmaxf(acc[nt][1] + bi1, 0.f)));
        float2 h1 = make_float2(to_tf32(fmaxf(acc[nt][2] + bi0, 0.f)),
                                to_tf32(fmaxf(acc[nt][3] + bi1, 0.f)));
        *(float2*)(arow + g * 68 + oc)       = h0;
        *(float2*)(arow + (g + 8) * 68 + oc) = h1;
    }
    __syncwarp();

    float acc3[2][4];
    #pragma unroll
    for (int nt = 0; nt < 2; nt++)
        #pragma unroll
        for (int k = 0; k < 4; k++) acc3[nt][k] = 0.f;

    #pragma unroll
    for (int kc = 0; kc < 8; kc++) {
        const int ic = kc * 8 + t;
        unsigned a0 = __float_as_uint(arow[g * 68 + ic]);
        unsigned a1 = __float_as_uint(arow[(g + 8) * 68 + ic]);
        unsigned a2 = __float_as_uint(arow[g * 68 + ic + 4]);
        unsigned a3 = __float_as_uint(arow[(g + 8) * 68 + ic + 4]);
        #pragma unroll
        for (int nt = 0; nt < 2; nt++) {
            const float* wrow = sw3s + (nt * 8 + g) * 68;
            unsigned b0 = __float_as_uint(wrow[ic]);
            unsigned b1 = __float_as_uint(wrow[ic + 4]);
            mma_tf32(acc3[nt], a0, a1, a2, a3, b0, b1);
        }
    }

    float o0a = 0.f, o1a = 0.f, o0b = 0.f, o1b = 0.f;
    #pragma unroll
    for (int nt = 0; nt < 2; nt++) {
        #pragma unroll
        for (int p = 0; p < 2; p++) {
            int col = nt * 8 + 2 * t + p;
            float bi = sb3[col];
            float w0 = sw4s[col * 2], w1 = sw4s[col * 2 + 1];
            float va = fmaxf(acc3[nt][p] + bi, 0.f);
            float vb = fmaxf(acc3[nt][2 + p] + bi, 0.f);
            o0a = fmaf(va, w0, o0a); o1a = fmaf(va, w1, o1a);
            o0b = fmaf(vb, w0, o0b); o1b = fmaf(vb, w1, o1b);
        }
    }
    #pragma unroll
    for (int m = 1; m <= 2; m <<= 1) {
        o0a += __shfl_xor_sync(0xffffffffu, o0a, m);
        o1a += __shfl_xor_sync(0xffffffffu, o1a, m);
        o0b += __shfl_xor_sync(0xffffffffu, o0b, m);
        o1b += __shfl_xor_sync(0xffffffffu, o1b, m);
    }
    if (t == 0) {
        size_t pix0 = (size_t)blockIdx.x * 128 + w * 16 + g;
        float2 f0 = ((const float2*)flow)[pix0];
        float2 f1 = ((const float2*)flow)[pix0 + 8];
        ((float2*)flowch)[pix0]     = make_float2(f0.x + o0a + sb4[0], f0.y + o1a + sb4[1]);
        ((float2*)flowch)[pix0 + 8] = make_float2(f1.x + o0b + sb4[0], f1.y + o1b + sb4[1]);
    }
}

// ---------------- 2x bilinear upsample (jax.image.resize semantics) -------
__global__ __launch_bounds__(256) void upsample_kernel(
    const float* __restrict__ src, float* __restrict__ out)
{
    int idx = blockIdx.x * blockDim.x + threadIdx.x;
    int x = idx & 511;
    int y = (idx >> 9) & 511;
    int b = idx >> 18;
    float sy = 0.5f * (float)y - 0.25f;
    float sx = 0.5f * (float)x - 0.25f;
    float y0f = floorf(sy), x0f = floorf(sx);
    float wy = sy - y0f,    wx = sx - x0f;
    int y0 = (int)y0f, x0 = (int)x0f;
    int ya = max(y0, 0), yb = min(y0 + 1, HH - 1);
    int xa = max(x0, 0), xb = min(x0 + 1, WW - 1);
    const float2* s = (const float2*)src;
    float2 v00 = s[(b * HH + ya) * WW + xa];
    float2 v01 = s[(b * HH + ya) * WW + xb];
    float2 v10 = s[(b * HH + yb) * WW + xa];
    float2 v11 = s[(b * HH + yb) * WW + xb];
    float2 r;
    r.x = (1.f - wy) * ((1.f - wx) * v00.x + wx * v01.x)
        +        wy  * ((1.f - wx) * v10.x + wx * v11.x);
    r.y = (1.f - wy) * ((1.f - wx) * v00.y + wx * v01.y)
        +        wy  * ((1.f - wx) * v10.y + wx * v11.y);
    ((float2*)out)[idx] = r;
}

// ---------------- launch ---------------------------------------------------
extern "C" void kernel_launch(void* const* d_in, const int* in_sizes, int n_in,
                              void* d_out, int out_size)
{
    (void)in_sizes; (void)n_in; (void)out_size;
    const float* input_1 = (const float*)d_in[0];
    const float* input_2 = (const float*)d_in[1];
    const float* flow12  = (const float*)d_in[2];
    const float* flow21  = (const float*)d_in[3];
    float* out = (float*)d_out;

    float *cat, *c0, *flowch;
    unsigned* wpack;
    cudaGetSymbolAddress((void**)&cat,    g_cat);
    cudaGetSymbolAddress((void**)&c0,     g_c0);
    cudaGetSymbolAddress((void**)&flowch, g_flowch);
    cudaGetSymbolAddress((void**)&wpack,  g_wpack);

    const int SM_CONV0 = (18 * 18 * PW0 + WPW_N0 + 32) * 4;   // ~88 KB
    const int SM_CONV1 = (34 * 18 * PW1 + WPW_N1 + 64) * 4;   // ~95 KB
    const int SM_F1    = (128 * 68 + 64 * 68 + 16 * 68 + 64 + 16 + 32 + 2) * 4;
    cudaFuncSetAttribute(conv0_tc_kernel,
                         cudaFuncAttributeMaxDynamicSharedMemorySize, SM_CONV0);
    cudaFuncSetAttribute(conv1_tc_kernel,
                         cudaFuncAttributeMaxDynamicSharedMemorySize, SM_CONV1);
    cudaFuncSetAttribute(fused1x1_tc_kernel,
                         cudaFuncAttributeMaxDynamicSharedMemorySize, SM_F1);

    const float* w[2][5];
    const float* bw[2][5];
    for (int dir = 0; dir < 2; dir++)
        for (int i = 0; i < 5; i++) {
            w[dir][i]  = (const float*)d_in[4 + 4 * i + 2 * dir];
            bw[dir][i] = (const float*)d_in[4 + 4 * i + 2 * dir + 1];
        }

    {
        const int total = 2 * (WPW_N0 + WPW_N1);
        prepack_kernel<<<(total + 255) / 256, 256>>>(
            w[0][0], w[0][1], w[1][0], w[1][1], wpack);
    }

    const size_t off64 = (size_t)NPIXTOT * 64;
    const size_t off32 = (size_t)NPIXTOT * 32;
    const size_t off2  = (size_t)NPIXTOT * 2;
    const size_t warpOutSz = (size_t)NPIXTOT * 32;
    const size_t upOutSz   = (size_t)BB * 512 * 512 * 2;

    dim3 grid0(WW / 16, HH / 16, BB);
    dim3 grid1(WW / 16, HH / 32, BB);

    for (int dir = 0; dir < 2; dir++) {
        const float* src   = dir ? input_2 : input_1;
        const float* other = dir ? input_1 : input_2;
        const float* flow  = dir ? flow21  : flow12;

        float* catD = cat + (size_t)dir * off64;
        float* c0D  = c0  + (size_t)dir * off32;
        float* fcD  = flowch + (size_t)dir * off2;
        const unsigned* wp0 = wpack + (size_t)dir * (WPW_N0 + WPW_N1);
        const unsigned* wp1 = wp0 + WPW_N0;

        warp_kernel<<<NPIXTOT * 8 / 256, 256>>>(src, flow, catD);
        conv0_tc_kernel<<<grid0, 512, SM_CONV0>>>(other, catD, wp0, bw[dir][0], c0D);
        conv1_tc_kernel<<<grid1, 512, SM_CONV1>>>(c0D, wp1, bw[dir][1], catD);
        fused1x1_tc_kernel<<<NPIXTOT / 128, 256, SM_F1>>>(
            catD, flow, w[dir][2], bw[dir][2], w[dir][3], bw[dir][3],
            w[dir][4], bw[dir][4], fcD);
        warp_kernel<<<NPIXTOT * 8 / 256, 256>>>(src, fcD, out + (size_t)dir * warpOutSz);
        upsample_kernel<<<BB * 512 * 512 / 256, 256>>>(
            fcD, out + 2 * warpOutSz + (size_t)dir * upOutSz);
    }
}

// round 8
// speedup vs baseline: 5.8488x; 1.1246x over previous
#include <cuda_runtime.h>
#include <cuda_bf16.h>

#define BB 8
#define HH 256
#define WW 256
#define NPIXTOT (BB*HH*WW)

// ---------------- tf32 helpers (fused1x1) ----------------------------------
__device__ __forceinline__ float to_tf32(float x) {
    unsigned r;
    asm("cvt.rna.tf32.f32 %0, %1;" : "=r"(r) : "f"(x));
    return __uint_as_float(r);
}
__device__ __forceinline__ void mma_tf32(float* c,
    unsigned a0, unsigned a1, unsigned a2, unsigned a3,
    unsigned b0, unsigned b1)
{
    asm("mma.sync.aligned.m16n8k8.row.col.f32.tf32.tf32.f32 "
        "{%0,%1,%2,%3}, {%4,%5,%6,%7}, {%8,%9}, {%0,%1,%2,%3};"
        : "+f"(c[0]), "+f"(c[1]), "+f"(c[2]), "+f"(c[3])
        : "r"(a0), "r"(a1), "r"(a2), "r"(a3), "r"(b0), "r"(b1));
}

// ---------------- bf16 helpers ---------------------------------------------
__device__ __forceinline__ unsigned bf2(float lo, float hi) {
    __nv_bfloat162 h = __floats2bfloat162_rn(lo, hi);
    return *(unsigned*)&h;
}
__device__ __forceinline__ void mma_bf16(float* c,
    unsigned a0, unsigned a1, unsigned a2, unsigned a3,
    unsigned b0, unsigned b1)
{
    asm("mma.sync.aligned.m16n8k16.row.col.f32.bf16.bf16.f32 "
        "{%0,%1,%2,%3}, {%4,%5,%6,%7}, {%8,%9}, {%0,%1,%2,%3};"
        : "+f"(c[0]), "+f"(c[1]), "+f"(c[2]), "+f"(c[3])
        : "r"(a0), "r"(a1), "r"(a2), "r"(a3), "r"(b0), "r"(b1));
}

// ---------------- scratch (device globals; no allocation allowed) ----------
__device__ float g_cat[2ull * NPIXTOT * 64];
__device__ float g_c0[2ull * NPIXTOT * 32];
__device__ float g_flowch[2ull * NPIXTOT * 2];

// prepacked bf16 conv weights, pair-interleaved k, CONFLICT-FREE pitches:
//  PW*g mod 32 must be {0,8,16,24} for g=0..3  ->  PW0=40, PW1=24 (words)
#define PW0 40
#define PW1 24
#define WPW_N0 (9*32*PW0)   /* words */
#define WPW_N1 (9*64*PW1)
__device__ unsigned g_wpack[2 * (WPW_N0 + WPW_N1)];

// word w (0..7) within a 16-channel block holds channel pair q = (w>>1)+(w&1)*4

// ---------------- weight prepack (bf16 pairs, final smem image) ------------
__global__ void prepack_kernel(
    const float* __restrict__ c0d0, const float* __restrict__ c1d0,
    const float* __restrict__ c0d1, const float* __restrict__ c1d1,
    unsigned* __restrict__ dst)
{
    int i = blockIdx.x * blockDim.x + threadIdx.x;   // word index
    const int PER = WPW_N0 + WPW_N1;
    if (i >= 2 * PER) return;
    int dir = (i >= PER);
    int j = i - dir * PER;
    const float* w;
    int CIN, COUT, PW;
    if (j < WPW_N0) { w = dir ? c0d1 : c0d0; CIN = 64; COUT = 32; PW = PW0; }
    else { j -= WPW_N0; w = dir ? c1d1 : c1d0; CIN = 32; COUT = 64; PW = PW1; }
    int word = j % PW;
    int r    = j / PW;
    int oc   = r % COUT;
    int tap  = r / COUT;
    float lo = 0.f, hi = 0.f;
    int block = word >> 3, ww = word & 7;
    int q  = (ww >> 1) + (ww & 1) * 4;
    int ch = block * 16 + 2 * q;
    if (ch < CIN) {
        lo = w[(tap * CIN + ch) * COUT + oc];
        hi = w[(tap * CIN + ch + 1) * COUT + oc];
    }
    dst[i] = bf2(lo, hi);
}

// ---------------- warp (32 ch bilinear sample) — final output only ---------
__global__ __launch_bounds__(256) void warp_kernel(
    const float* __restrict__ src, const float* __restrict__ flow,
    float* __restrict__ out)
{
    int idx = blockIdx.x * blockDim.x + threadIdx.x;   // NPIXTOT*8 threads
    int c4  = idx & 7;
    int pix = idx >> 3;
    int x = pix & (WW - 1);
    int y = (pix >> 8) & (HH - 1);
    int b = pix >> 16;
    float2 f = ((const float2*)flow)[pix];
    float qy = (float)y - f.x;
    float qx = (float)x - f.y;
    float fy = fminf(fmaxf(floorf(qy), 0.f), (float)(HH - 2));
    float fx = fminf(fmaxf(floorf(qx), 0.f), (float)(WW - 2));
    float ay = fminf(fmaxf(qy - fy, 0.f), 1.f);
    float ax = fminf(fmaxf(qx - fx, 0.f), 1.f);
    int iy = (int)fy, ix = (int)fx;
    const float4* s4 = (const float4*)src;
    int base = ((b * HH + iy) * WW + ix) * 8 + c4;
    float4 tl = s4[base];
    float4 tr = s4[base + 8];
    float4 bl = s4[base + WW * 8];
    float4 br = s4[base + WW * 8 + 8];
    float4 top, bot, r;
    top.x = tl.x + ax * (tr.x - tl.x); top.y = tl.y + ax * (tr.y - tl.y);
    top.z = tl.z + ax * (tr.z - tl.z); top.w = tl.w + ax * (tr.w - tl.w);
    bot.x = bl.x + ax * (br.x - bl.x); bot.y = bl.y + ax * (br.y - bl.y);
    bot.z = bl.z + ax * (br.z - bl.z); bot.w = bl.w + ax * (br.w - bl.w);
    r.x = top.x + ay * (bot.x - top.x); r.y = top.y + ay * (bot.y - top.y);
    r.z = top.z + ay * (bot.z - top.z); r.w = top.w + ay * (bot.w - top.w);
    ((float4*)out)[pix * 8 + c4] = r;
}

// ---------------- conv0: 64->32, tile 16x16, fused warp+concat staging -----
// channels 0-31 = other image; channels 32-63 = bilinear(src, flow) inline.
__global__ __launch_bounds__(512) void conv0_tc_kernel(
    const float* __restrict__ other, const float* __restrict__ srcimg,
    const float* __restrict__ flow,
    const unsigned* __restrict__ wpack, const float* __restrict__ bias,
    float* __restrict__ out)
{
    constexpr int CIN = 64, COUT = 32;
    constexpr int TX = 16, TY = 16;
    constexpr int TW = TX + 2, TH = TY + 2;
    constexpr int PW = PW0;
    constexpr int NT = COUT / 8;     // 4
    constexpr int KC = CIN / 16;     // 4
    constexpr int TILE_W = TH * TW * PW;
    constexpr int WN = WPW_N0;

    extern __shared__ unsigned smw[];
    unsigned* tile = smw;
    unsigned* sw   = smw + TILE_W;
    float*    sb   = (float*)(sw + WN);

    const int bx = blockIdx.x * TX;
    const int by = blockIdx.y * TY;
    const int b  = blockIdx.z;
    const int tid = threadIdx.x;

    {
        const uint4* s4 = (const uint4*)wpack;
        uint4* d4 = (uint4*)sw;
        #pragma unroll 4
        for (int i = tid; i < WN / 4; i += 512) d4[i] = s4[i];
        if (tid < COUT) sb[tid] = bias[tid];
    }
    // staging: items (p, kb); kb<2 copies 'other', kb>=2 bilinear-samples src
    for (int i = tid; i < TH * TW * KC; i += 512) {
        int kb = i & 3;
        int p  = i >> 2;
        int xx = p % TW;
        int yy = p / TW;
        int gx = bx + xx - 1;
        int gy = by + yy - 1;
        float4 v[4];
        v[0] = v[1] = v[2] = v[3] = make_float4(0.f, 0.f, 0.f, 0.f);
        if (gx >= 0 && gx < WW && gy >= 0 && gy < HH) {
            int pix = (b * HH + gy) * WW + gx;
            if (kb < 2) {
                const float4* s = (const float4*)other + (size_t)pix * 8 + kb * 4;
                v[0] = s[0]; v[1] = s[1]; v[2] = s[2]; v[3] = s[3];
            } else {
                float2 f = ((const float2*)flow)[pix];
                float qy = (float)gy - f.x;
                float qx = (float)gx - f.y;
                float fy = fminf(fmaxf(floorf(qy), 0.f), (float)(HH - 2));
                float fx = fminf(fmaxf(floorf(qx), 0.f), (float)(WW - 2));
                float ay = fminf(fmaxf(qy - fy, 0.f), 1.f);
                float ax = fminf(fmaxf(qx - fx, 0.f), 1.f);
                int iy = (int)fy, ix = (int)fx;
                const float4* s4 = (const float4*)srcimg;
                int base = ((b * HH + iy) * WW + ix) * 8 + (kb - 2) * 4;
                #pragma unroll
                for (int j = 0; j < 4; j++) {
                    float4 tl = s4[base + j];
                    float4 tr = s4[base + 8 + j];
                    float4 bl = s4[base + WW * 8 + j];
                    float4 br = s4[base + WW * 8 + 8 + j];
                    float4 top, bot, r;
                    top.x = tl.x + ax * (tr.x - tl.x); top.y = tl.y + ax * (tr.y - tl.y);
                    top.z = tl.z + ax * (tr.z - tl.z); top.w = tl.w + ax * (tr.w - tl.w);
                    bot.x = bl.x + ax * (br.x - bl.x); bot.y = bl.y + ax * (br.y - bl.y);
                    bot.z = bl.z + ax * (br.z - bl.z); bot.w = bl.w + ax * (br.w - bl.w);
                    r.x = top.x + ay * (bot.x - top.x); r.y = top.y + ay * (bot.y - top.y);
                    r.z = top.z + ay * (bot.z - top.z); r.w = top.w + ay * (bot.w - top.w);
                    v[j] = r;
                }
            }
        }
        uint4 wlo, whi;
        wlo.x = bf2(v[0].x, v[0].y);  // p0
        wlo.y = bf2(v[2].x, v[2].y);  // p4
        wlo.z = bf2(v[0].z, v[0].w);  // p1
        wlo.w = bf2(v[2].z, v[2].w);  // p5
        whi.x = bf2(v[1].x, v[1].y);  // p2
        whi.y = bf2(v[3].x, v[3].y);  // p6
        whi.z = bf2(v[1].z, v[1].w);  // p3
        whi.w = bf2(v[3].z, v[3].w);  // p7
        uint4* d = (uint4*)(tile + p * PW + kb * 8);
        d[0] = wlo;
        d[1] = whi;
    }
    __syncthreads();

    const int lane = tid & 31;
    const int w    = tid >> 5;
    const int g = lane >> 2;
    const int t = lane & 3;

    float acc[NT][4];
    #pragma unroll
    for (int nt = 0; nt < NT; nt++)
        #pragma unroll
        for (int k = 0; k < 4; k++) acc[nt][k] = 0.f;

    #pragma unroll 1
    for (int tap = 0; tap < 9; tap++) {
        const int dy = tap / 3, dx = tap % 3;
        const unsigned* ab = tile + ((w + dy) * TW + dx) * PW;
        const unsigned* wb = sw + tap * COUT * PW;
        #pragma unroll
        for (int kb = 0; kb < KC; kb++) {
            const int ko = kb * 8 + 2 * t;
            uint2 ra = *(const uint2*)(ab + g * PW + ko);
            uint2 rb = *(const uint2*)(ab + (g + 8) * PW + ko);
            #pragma unroll
            for (int nt = 0; nt < NT; nt++) {
                uint2 wv = *(const uint2*)(wb + (nt * 8 + g) * PW + ko);
                mma_bf16(acc[nt], ra.x, rb.x, ra.y, rb.y, wv.x, wv.y);
            }
        }
    }

    const int gy = by + w;
    float* orow0 = out + ((size_t)((b * HH + gy) * WW + bx + g)) * COUT;
    float* orow1 = orow0 + 8 * COUT;
    #pragma unroll
    for (int nt = 0; nt < NT; nt++) {
        int oc = nt * 8 + 2 * t;
        float bi0 = sb[oc], bi1 = sb[oc + 1];
        *(float2*)(orow0 + oc) = make_float2(fmaxf(acc[nt][0] + bi0, 0.f),
                                             fmaxf(acc[nt][1] + bi1, 0.f));
        *(float2*)(orow1 + oc) = make_float2(fmaxf(acc[nt][2] + bi0, 0.f),
                                             fmaxf(acc[nt][3] + bi1, 0.f));
    }
}

// ---------------- conv1: 32->64, tile 16x32, 16 warps, M=32/warp -----------
__global__ __launch_bounds__(512) void conv1_tc_kernel(
    const float* __restrict__ in,
    const unsigned* __restrict__ wpack, const float* __restrict__ bias,
    float* __restrict__ out)
{
    constexpr int CIN = 32, COUT = 64;
    constexpr int TX = 16, TY = 32;
    constexpr int TW = TX + 2, TH = TY + 2;
    constexpr int PW = PW1;
    constexpr int NT = COUT / 8;     // 8
    constexpr int KC = CIN / 16;     // 2
    constexpr int TILE_W = TH * TW * PW;
    constexpr int WN = WPW_N1;

    extern __shared__ unsigned smw[];
    unsigned* tile = smw;
    unsigned* sw   = smw + TILE_W;
    float*    sb   = (float*)(sw + WN);

    const int bx = blockIdx.x * TX;
    const int by = blockIdx.y * TY;
    const int b  = blockIdx.z;
    const int tid = threadIdx.x;

    {
        const uint4* s4 = (const uint4*)wpack;
        uint4* d4 = (uint4*)sw;
        #pragma unroll 4
        for (int i = tid; i < WN / 4; i += 512) d4[i] = s4[i];
        if (tid < COUT) sb[tid] = bias[tid];
    }
    for (int i = tid; i < TH * TW * KC; i += 512) {
        int kb = i & 1;
        int p  = i >> 1;
        int xx = p % TW;
        int yy = p / TW;
        int gx = bx + xx - 1;
        int gy = by + yy - 1;
        float4 v0 = make_float4(0.f,0.f,0.f,0.f), v1 = v0, v2 = v0, v3 = v0;
        if (gx >= 0 && gx < WW && gy >= 0 && gy < HH) {
            int pix = (b * HH + gy) * WW + gx;
            const float4* s = (const float4*)in + (size_t)pix * 8 + kb * 4;
            v0 = s[0]; v1 = s[1]; v2 = s[2]; v3 = s[3];
        }
        uint4 wlo, whi;
        wlo.x = bf2(v0.x, v0.y);
        wlo.y = bf2(v2.x, v2.y);
        wlo.z = bf2(v0.z, v0.w);
        wlo.w = bf2(v2.z, v2.w);
        whi.x = bf2(v1.x, v1.y);
        whi.y = bf2(v3.x, v3.y);
        whi.z = bf2(v1.z, v1.w);
        whi.w = bf2(v3.z, v3.w);
        uint4* d = (uint4*)(tile + p * PW + kb * 8);
        d[0] = wlo;
        d[1] = whi;
    }
    __syncthreads();

    const int lane = tid & 31;
    const int w    = tid >> 5;
    const int g = lane >> 2;
    const int t = lane & 3;

    float acc0[NT][4], acc1[NT][4];
    #pragma unroll
    for (int nt = 0; nt < NT; nt++)
        #pragma unroll
        for (int k = 0; k < 4; k++) { acc0[nt][k] = 0.f; acc1[nt][k] = 0.f; }

    #pragma unroll 1
    for (int tap = 0; tap < 9; tap++) {
        const int dy = tap / 3, dx = tap % 3;
        const unsigned* a0b = tile + ((2 * w + dy) * TW + dx) * PW;
        const unsigned* a1b = a0b + TW * PW;
        const unsigned* wb  = sw + tap * COUT * PW;
        #pragma unroll
        for (int kb = 0; kb < KC; kb++) {
            const int ko = kb * 8 + 2 * t;
            uint2 ra0 = *(const uint2*)(a0b + g * PW + ko);
            uint2 rb0 = *(const uint2*)(a0b + (g + 8) * PW + ko);
            uint2 ra1 = *(const uint2*)(a1b + g * PW + ko);
            uint2 rb1 = *(const uint2*)(a1b + (g + 8) * PW + ko);
            #pragma unroll
            for (int nt = 0; nt < NT; nt++) {
                uint2 wv = *(const uint2*)(wb + (nt * 8 + g) * PW + ko);
                mma_bf16(acc0[nt], ra0.x, rb0.x, ra0.y, rb0.y, wv.x, wv.y);
                mma_bf16(acc1[nt], ra1.x, rb1.x, ra1.y, rb1.y, wv.x, wv.y);
            }
        }
    }

    #pragma unroll
    for (int rr = 0; rr < 2; rr++) {
        const int gy = by + 2 * w + rr;
        float (*acc)[4] = rr ? acc1 : acc0;
        float* orow0 = out + ((size_t)((b * HH + gy) * WW + bx + g)) * COUT;
        float* orow1 = orow0 + 8 * COUT;
        #pragma unroll
        for (int nt = 0; nt < NT; nt++) {
            int oc = nt * 8 + 2 * t;
            float bi0 = sb[oc], bi1 = sb[oc + 1];
            *(float2*)(orow0 + oc) = make_float2(fmaxf(acc[nt][0] + bi0, 0.f),
                                                 fmaxf(acc[nt][1] + bi1, 0.f));
            *(float2*)(orow1 + oc) = make_float2(fmaxf(acc[nt][2] + bi0, 0.f),
                                                 fmaxf(acc[nt][3] + bi1, 0.f));
        }
    }
}

// ---------------- fused 1x1 chain via tf32 MMA -----------------------------
__global__ __launch_bounds__(256) void fused1x1_tc_kernel(
    const float* __restrict__ in, const float* __restrict__ flow,
    const float* __restrict__ w2, const float* __restrict__ b2,
    const float* __restrict__ w3, const float* __restrict__ b3,
    const float* __restrict__ w4, const float* __restrict__ b4,
    float* __restrict__ flowch)
{
    extern __shared__ float sm[];
    float* sin  = sm;                 // 128*68
    float* sw2s = sin + 128 * 68;     // 64*68
    float* sw3s = sw2s + 64 * 68;     // 16*68
    float* sb2  = sw3s + 16 * 68;     // 64
    float* sb3  = sb2 + 64;           // 16
    float* sw4s = sb3 + 16;           // 32
    float* sb4  = sw4s + 32;          // 2

    const int tid = threadIdx.x;

    {
        const float4* gin4 = (const float4*)(in + (size_t)blockIdx.x * 128 * 64);
        #pragma unroll 4
        for (int i = tid; i < 128 * 16; i += 256) {
            int pix = i >> 4, c4 = i & 15;
            float4 v = gin4[i];
            float* d = sin + pix * 68 + c4 * 4;
            d[0] = to_tf32(v.x); d[1] = to_tf32(v.y);
            d[2] = to_tf32(v.z); d[3] = to_tf32(v.w);
        }
    }
    for (int i = tid; i < 4096; i += 256) {
        int oc = i & 63, ic = i >> 6;
        sw2s[oc * 68 + ic] = to_tf32(w2[i]);
    }
    for (int i = tid; i < 1024; i += 256) {
        int oc = i & 15, ic = i >> 4;
        sw3s[oc * 68 + ic] = to_tf32(w3[i]);
    }
    if (tid < 64) sb2[tid] = b2[tid];
    if (tid < 16) sb3[tid] = b3[tid];
    if (tid < 32) sw4s[tid] = w4[tid];
    if (tid < 2)  sb4[tid] = b4[tid];
    __syncthreads();

    const int lane = tid & 31;
    const int w = tid >> 5;
    const int g = lane >> 2;
    const int t = lane & 3;
    float* arow = sin + (w * 16) * 68;

    float acc[8][4];
    #pragma unroll
    for (int nt = 0; nt < 8; nt++)
        #pragma unroll
        for (int k = 0; k < 4; k++) acc[nt][k] = 0.f;

    #pragma unroll
    for (int kc = 0; kc < 8; kc++) {
        const int ic = kc * 8 + t;
        unsigned a0 = __float_as_uint(arow[g * 68 + ic]);
        unsigned a1 = __float_as_uint(arow[(g + 8) * 68 + ic]);
        unsigned a2 = __float_as_uint(arow[g * 68 + ic + 4]);
        unsigned a3 = __float_as_uint(arow[(g + 8) * 68 + ic + 4]);
        #pragma unroll
        for (int nt = 0; nt < 8; nt++) {
            const float* wrow = sw2s + (nt * 8 + g) * 68;
            unsigned b0 = __float_as_uint(wrow[ic]);
            unsigned b1 = __float_as_uint(wrow[ic + 4]);
            mma_tf32(acc[nt], a0, a1, a2, a3, b0, b1);
        }
    }
    #pragma unroll
    for (int nt = 0; nt < 8; nt++) {
        int oc = nt * 8 + 2 * t;
        float bi0 = sb2[oc], bi1 = sb2[oc + 1];
        float2 h0 = make_float2(to_tf32(fmaxf(acc[nt][0] + bi0, 0.f)),
                                to_tf32(fmaxf(acc[nt][1] + bi1, 0.f)));
        float2 h1 = make_float2(to_tf32(fmaxf(acc[nt][2] + bi0, 0.f)),
                                to_tf32(fmaxf(acc[nt][3] + bi1, 0.f)));
        *(float2*)(arow + g * 68 + oc)       = h0;
        *(float2*)(arow + (g + 8) * 68 + oc) = h1;
    }
    __syncwarp();

    float acc3[2][4];
    #pragma unroll
    for (int nt = 0; nt < 2; nt++)
        #pragma unroll
        for (int k = 0; k < 4; k++) acc3[nt][k] = 0.f;

    #pragma unroll
    for (int kc = 0; kc < 8; kc++) {
        const int ic = kc * 8 + t;
        unsigned a0 = __float_as_uint(arow[g * 68 + ic]);
        unsigned a1 = __float_as_uint(arow[(g + 8) * 68 + ic]);
        unsigned a2 = __float_as_uint(arow[g * 68 + ic + 4]);
        unsigned a3 = __float_as_uint(arow[(g + 8) * 68 + ic + 4]);
        #pragma unroll
        for (int nt = 0; nt < 2; nt++) {
            const float* wrow = sw3s + (nt * 8 + g) * 68;
            unsigned b0 = __float_as_uint(wrow[ic]);
            unsigned b1 = __float_as_uint(wrow[ic + 4]);
            mma_tf32(acc3[nt], a0, a1, a2, a3, b0, b1);
        }
    }

    float o0a = 0.f, o1a = 0.f, o0b = 0.f, o1b = 0.f;
    #pragma unroll
    for (int nt = 0; nt < 2; nt++) {
        #pragma unroll
        for (int p = 0; p < 2; p++) {
            int col = nt * 8 + 2 * t + p;
            float bi = sb3[col];
            float w0 = sw4s[col * 2], w1 = sw4s[col * 2 + 1];
            float va = fmaxf(acc3[nt][p] + bi, 0.f);
            float vb = fmaxf(acc3[nt][2 + p] + bi, 0.f);
            o0a = fmaf(va, w0, o0a); o1a = fmaf(va, w1, o1a);
            o0b = fmaf(vb, w0, o0b); o1b = fmaf(vb, w1, o1b);
        }
    }
    #pragma unroll
    for (int m = 1; m <= 2; m <<= 1) {
        o0a += __shfl_xor_sync(0xffffffffu, o0a, m);
        o1a += __shfl_xor_sync(0xffffffffu, o1a, m);
        o0b += __shfl_xor_sync(0xffffffffu, o0b, m);
        o1b += __shfl_xor_sync(0xffffffffu, o1b, m);
    }
    if (t == 0) {
        size_t pix0 = (size_t)blockIdx.x * 128 + w * 16 + g;
        float2 f0 = ((const float2*)flow)[pix0];
        float2 f1 = ((const float2*)flow)[pix0 + 8];
        ((float2*)flowch)[pix0]     = make_float2(f0.x + o0a + sb4[0], f0.y + o1a + sb4[1]);
        ((float2*)flowch)[pix0 + 8] = make_float2(f1.x + o0b + sb4[0], f1.y + o1b + sb4[1]);
    }
}

// ---------------- 2x bilinear upsample (jax.image.resize semantics) -------
__global__ __launch_bounds__(256) void upsample_kernel(
    const float* __restrict__ src, float* __restrict__ out)
{
    int idx = blockIdx.x * blockDim.x + threadIdx.x;
    int x = idx & 511;
    int y = (idx >> 9) & 511;
    int b = idx >> 18;
    float sy = 0.5f * (float)y - 0.25f;
    float sx = 0.5f * (float)x - 0.25f;
    float y0f = floorf(sy), x0f = floorf(sx);
    float wy = sy - y0f,    wx = sx - x0f;
    int y0 = (int)y0f, x0 = (int)x0f;
    int ya = max(y0, 0), yb = min(y0 + 1, HH - 1);
    int xa = max(x0, 0), xb = min(x0 + 1, WW - 1);
    const float2* s = (const float2*)src;
    float2 v00 = s[(b * HH + ya) * WW + xa];
    float2 v01 = s[(b * HH + ya) * WW + xb];
    float2 v10 = s[(b * HH + yb) * WW + xa];
    float2 v11 = s[(b * HH + yb) * WW + xb];
    float2 r;
    r.x = (1.f - wy) * ((1.f - wx) * v00.x + wx * v01.x)
        +        wy  * ((1.f - wx) * v10.x + wx * v11.x);
    r.y = (1.f - wy) * ((1.f - wx) * v00.y + wx * v01.y)
        +        wy  * ((1.f - wx) * v10.y + wx * v11.y);
    ((float2*)out)[idx] = r;
}

// ---------------- launch ---------------------------------------------------
extern "C" void kernel_launch(void* const* d_in, const int* in_sizes, int n_in,
                              void* d_out, int out_size)
{
    (void)in_sizes; (void)n_in; (void)out_size;
    const float* input_1 = (const float*)d_in[0];
    const float* input_2 = (const float*)d_in[1];
    const float* flow12  = (const float*)d_in[2];
    const float* flow21  = (const float*)d_in[3];
    float* out = (float*)d_out;

    float *cat, *c0, *flowch;
    unsigned* wpack;
    cudaGetSymbolAddress((void**)&cat,    g_cat);
    cudaGetSymbolAddress((void**)&c0,     g_c0);
    cudaGetSymbolAddress((void**)&flowch, g_flowch);
    cudaGetSymbolAddress((void**)&wpack,  g_wpack);

    const int SM_CONV0 = (18 * 18 * PW0 + WPW_N0 + 32) * 4;   // ~95.8 KB
    const int SM_CONV1 = (34 * 18 * PW1 + WPW_N1 + 64) * 4;   // ~111.6 KB
    const int SM_F1    = (128 * 68 + 64 * 68 + 16 * 68 + 64 + 16 + 32 + 2) * 4;
    cudaFuncSetAttribute(conv0_tc_kernel,
                         cudaFuncAttributeMaxDynamicSharedMemorySize, SM_CONV0);
    cudaFuncSetAttribute(conv1_tc_kernel,
                         cudaFuncAttributeMaxDynamicSharedMemorySize, SM_CONV1);
    cudaFuncSetAttribute(fused1x1_tc_kernel,
                         cudaFuncAttributeMaxDynamicSharedMemorySize, SM_F1);

    const float* w[2][5];
    const float* bw[2][5];
    for (int dir = 0; dir < 2; dir++)
        for (int i = 0; i < 5; i++) {
            w[dir][i]  = (const float*)d_in[4 + 4 * i + 2 * dir];
            bw[dir][i] = (const float*)d_in[4 + 4 * i + 2 * dir + 1];
        }

    {
        const int total = 2 * (WPW_N0 + WPW_N1);
        prepack_kernel<<<(total + 255) / 256, 256>>>(
            w[0][0], w[0][1], w[1][0], w[1][1], wpack);
    }

    const size_t off64 = (size_t)NPIXTOT * 64;
    const size_t off32 = (size_t)NPIXTOT * 32;
    const size_t off2  = (size_t)NPIXTOT * 2;
    const size_t warpOutSz = (size_t)NPIXTOT * 32;
    const size_t upOutSz   = (size_t)BB * 512 * 512 * 2;

    dim3 grid0(WW / 16, HH / 16, BB);
    dim3 grid1(WW / 16, HH / 32, BB);

    for (int dir = 0; dir < 2; dir++) {
        const float* src   = dir ? input_2 : input_1;
        const float* other = dir ? input_1 : input_2;
        const float* flow  = dir ? flow21  : flow12;

        float* catD = cat + (size_t)dir * off64;
        float* c0D  = c0  + (size_t)dir * off32;
        float* fcD  = flowch + (size_t)dir * off2;
        const unsigned* wp0 = wpack + (size_t)dir * (WPW_N0 + WPW_N1);
        const unsigned* wp1 = wp0 + WPW_N0;

        // conv0 with fused warp+concat staging (no separate warp kernel)
        conv0_tc_kernel<<<grid0, 512, SM_CONV0>>>(
            other, src, flow, wp0, bw[dir][0], c0D);
        conv1_tc_kernel<<<grid1, 512, SM_CONV1>>>(c0D, wp1, bw[dir][1], catD);
        fused1x1_tc_kernel<<<NPIXTOT / 128, 256, SM_F1>>>(
            catD, flow, w[dir][2], bw[dir][2], w[dir][3], bw[dir][3],
            w[dir][4], bw[dir][4], fcD);
        warp_kernel<<<NPIXTOT * 8 / 256, 256>>>(src, fcD, out + (size_t)dir * warpOutSz);
        upsample_kernel<<<BB * 512 * 512 / 256, 256>>>(
            fcD, out + 2 * warpOutSz + (size_t)dir * upOutSz);
    }
}

// round 9
// speedup vs baseline: 7.0442x; 1.2044x over previous
#include <cuda_runtime.h>
#include <cuda_bf16.h>

#define BB 8
#define HH 256
#define WW 256
#define NPIXTOT (BB*HH*WW)

// ---------------- bf16 helpers ---------------------------------------------
__device__ __forceinline__ unsigned bf2(float lo, float hi) {
    __nv_bfloat162 h = __floats2bfloat162_rn(lo, hi);
    return *(unsigned*)&h;
}
__device__ __forceinline__ void mma_bf16(float* c,
    unsigned a0, unsigned a1, unsigned a2, unsigned a3,
    unsigned b0, unsigned b1)
{
    asm("mma.sync.aligned.m16n8k16.row.col.f32.bf16.bf16.f32 "
        "{%0,%1,%2,%3}, {%4,%5,%6,%7}, {%8,%9}, {%0,%1,%2,%3};"
        : "+f"(c[0]), "+f"(c[1]), "+f"(c[2]), "+f"(c[3])
        : "r"(a0), "r"(a1), "r"(a2), "r"(a3), "r"(b0), "r"(b1));
}

// Pair-interleaved k layout: within each 16-channel block, word w (0..7)
// holds channel pair q = (w>>1) + (w&1)*4, i.e. channels (2q, 2q+1).
// For pair index q: word = (q&3)*2 + (q>>2).

// ---------------- scratch (device globals; no allocation allowed) ----------
__device__ unsigned g_cat_w[2ull * NPIXTOT * 32];  // conv1 out, bf16 pairs (64ch)
__device__ unsigned g_c0_w[2ull * NPIXTOT * 16];   // conv0 out, bf16 pairs (32ch)
__device__ float    g_flowch[2ull * NPIXTOT * 2];

// prepacked bf16 weights (pair-interleaved k, conflict-free pitches)
#define PW0 40
#define PW1 24
#define PWF 40
#define WPW_N0 (9*32*PW0)
#define WPW_N1 (9*64*PW1)
#define WPW_F2 (64*PWF)
#define WPW_F3 (16*PWF)
#define WPW_PER (WPW_N0 + WPW_N1 + WPW_F2 + WPW_F3)
__device__ unsigned g_wpack[2 * WPW_PER];

// ---------------- weight prepack (bf16 pairs, final smem images) -----------
__global__ void prepack_kernel(
    const float* __restrict__ c0d0, const float* __restrict__ c1d0,
    const float* __restrict__ w2d0, const float* __restrict__ w3d0,
    const float* __restrict__ c0d1, const float* __restrict__ c1d1,
    const float* __restrict__ w2d1, const float* __restrict__ w3d1,
    unsigned* __restrict__ dst)
{
    int i = blockIdx.x * blockDim.x + threadIdx.x;
    if (i >= 2 * WPW_PER) return;
    int dir = (i >= WPW_PER);
    int j = i - dir * WPW_PER;
    const float* w;
    int CIN, COUT, PW;
    if (j < WPW_N0) {
        w = dir ? c0d1 : c0d0; CIN = 64; COUT = 32; PW = PW0;
    } else if (j < WPW_N0 + WPW_N1) {
        j -= WPW_N0; w = dir ? c1d1 : c1d0; CIN = 32; COUT = 64; PW = PW1;
    } else if (j < WPW_N0 + WPW_N1 + WPW_F2) {
        j -= WPW_N0 + WPW_N1; w = dir ? w2d1 : w2d0; CIN = 64; COUT = 64; PW = PWF;
    } else {
        j -= WPW_N0 + WPW_N1 + WPW_F2; w = dir ? w3d1 : w3d0; CIN = 64; COUT = 16; PW = PWF;
    }
    int word = j % PW;
    int r    = j / PW;
    int oc   = r % COUT;
    int tap  = r / COUT;       // 0 for fc layers
    float lo = 0.f, hi = 0.f;
    int block = word >> 3, ww = word & 7;
    int q  = (ww >> 1) + (ww & 1) * 4;
    int ch = block * 16 + 2 * q;
    if (ch < CIN) {
        lo = w[(tap * CIN + ch) * COUT + oc];
        hi = w[(tap * CIN + ch + 1) * COUT + oc];
    }
    dst[i] = bf2(lo, hi);
}

// ---------------- warp (32 ch bilinear sample) — final output only ---------
__global__ __launch_bounds__(256) void warp_kernel(
    const float* __restrict__ src, const float* __restrict__ flow,
    float* __restrict__ out)
{
    int idx = blockIdx.x * blockDim.x + threadIdx.x;   // NPIXTOT*8 threads
    int c4  = idx & 7;
    int pix = idx >> 3;
    int x = pix & (WW - 1);
    int y = (pix >> 8) & (HH - 1);
    int b = pix >> 16;
    float2 f = ((const float2*)flow)[pix];
    float qy = (float)y - f.x;
    float qx = (float)x - f.y;
    float fy = fminf(fmaxf(floorf(qy), 0.f), (float)(HH - 2));
    float fx = fminf(fmaxf(floorf(qx), 0.f), (float)(WW - 2));
    float ay = fminf(fmaxf(qy - fy, 0.f), 1.f);
    float ax = fminf(fmaxf(qx - fx, 0.f), 1.f);
    int iy = (int)fy, ix = (int)fx;
    const float4* s4 = (const float4*)src;
    int base = ((b * HH + iy) * WW + ix) * 8 + c4;
    float4 tl = s4[base];
    float4 tr = s4[base + 8];
    float4 bl = s4[base + WW * 8];
    float4 br = s4[base + WW * 8 + 8];
    float4 top, bot, r;
    top.x = tl.x + ax * (tr.x - tl.x); top.y = tl.y + ax * (tr.y - tl.y);
    top.z = tl.z + ax * (tr.z - tl.z); top.w = tl.w + ax * (tr.w - tl.w);
    bot.x = bl.x + ax * (br.x - bl.x); bot.y = bl.y + ax * (br.y - bl.y);
    bot.z = bl.z + ax * (br.z - bl.z); bot.w = bl.w + ax * (br.w - bl.w);
    r.x = top.x + ay * (bot.x - top.x); r.y = top.y + ay * (bot.y - top.y);
    r.z = top.z + ay * (bot.z - top.z); r.w = top.w + ay * (bot.w - top.w);
    ((float4*)out)[pix * 8 + c4] = r;
}

// ---------------- conv0: 64->32, tile 16x16, fused warp+concat staging -----
__global__ __launch_bounds__(512) void conv0_tc_kernel(
    const float* __restrict__ other, const float* __restrict__ srcimg,
    const float* __restrict__ flow,
    const unsigned* __restrict__ wpack, const float* __restrict__ bias,
    unsigned* __restrict__ outw)
{
    constexpr int COUT = 32;
    constexpr int TX = 16, TY = 16;
    constexpr int TW = TX + 2, TH = TY + 2;
    constexpr int PW = PW0;
    constexpr int NT = COUT / 8;     // 4
    constexpr int KC = 4;            // 64ch / 16
    constexpr int TILE_W = TH * TW * PW;
    constexpr int WN = WPW_N0;

    extern __shared__ unsigned smw[];
    unsigned* tile = smw;
    unsigned* sw   = smw + TILE_W;
    float*    sb   = (float*)(sw + WN);

    const int bx = blockIdx.x * TX;
    const int by = blockIdx.y * TY;
    const int b  = blockIdx.z;
    const int tid = threadIdx.x;

    {
        const uint4* s4 = (const uint4*)wpack;
        uint4* d4 = (uint4*)sw;
        #pragma unroll 4
        for (int i = tid; i < WN / 4; i += 512) d4[i] = s4[i];
        if (tid < COUT) sb[tid] = bias[tid];
    }
    // staging: kb<2 copies 'other', kb>=2 bilinear-samples src
    for (int i = tid; i < TH * TW * KC; i += 512) {
        int kb = i & 3;
        int p  = i >> 2;
        int xx = p % TW;
        int yy = p / TW;
        int gx = bx + xx - 1;
        int gy = by + yy - 1;
        float4 v[4];
        v[0] = v[1] = v[2] = v[3] = make_float4(0.f, 0.f, 0.f, 0.f);
        if (gx >= 0 && gx < WW && gy >= 0 && gy < HH) {
            int pix = (b * HH + gy) * WW + gx;
            if (kb < 2) {
                const float4* s = (const float4*)other + (size_t)pix * 8 + kb * 4;
                v[0] = s[0]; v[1] = s[1]; v[2] = s[2]; v[3] = s[3];
            } else {
                float2 f = ((const float2*)flow)[pix];
                float qy = (float)gy - f.x;
                float qx = (float)gx - f.y;
                float fy = fminf(fmaxf(floorf(qy), 0.f), (float)(HH - 2));
                float fx = fminf(fmaxf(floorf(qx), 0.f), (float)(WW - 2));
                float ay = fminf(fmaxf(qy - fy, 0.f), 1.f);
                float ax = fminf(fmaxf(qx - fx, 0.f), 1.f);
                int iy = (int)fy, ix = (int)fx;
                const float4* s4 = (const float4*)srcimg;
                int base = ((b * HH + iy) * WW + ix) * 8 + (kb - 2) * 4;
                #pragma unroll
                for (int j = 0; j < 4; j++) {
                    float4 tl = s4[base + j];
                    float4 tr = s4[base + 8 + j];
                    float4 bl = s4[base + WW * 8 + j];
                    float4 br = s4[base + WW * 8 + 8 + j];
                    float4 top, bot, r;
                    top.x = tl.x + ax * (tr.x - tl.x); top.y = tl.y + ax * (tr.y - tl.y);
                    top.z = tl.z + ax * (tr.z - tl.z); top.w = tl.w + ax * (tr.w - tl.w);
                    bot.x = bl.x + ax * (br.x - bl.x); bot.y = bl.y + ax * (br.y - bl.y);
                    bot.z = bl.z + ax * (br.z - bl.z); bot.w = bl.w + ax * (br.w - bl.w);
                    r.x = top.x + ay * (bot.x - top.x); r.y = top.y + ay * (bot.y - top.y);
                    r.z = top.z + ay * (bot.z - top.z); r.w = top.w + ay * (bot.w - top.w);
                    v[j] = r;
                }
            }
        }
        uint4 wlo, whi;
        wlo.x = bf2(v[0].x, v[0].y);
        wlo.y = bf2(v[2].x, v[2].y);
        wlo.z = bf2(v[0].z, v[0].w);
        wlo.w = bf2(v[2].z, v[2].w);
        whi.x = bf2(v[1].x, v[1].y);
        whi.y = bf2(v[3].x, v[3].y);
        whi.z = bf2(v[1].z, v[1].w);
        whi.w = bf2(v[3].z, v[3].w);
        uint4* d = (uint4*)(tile + p * PW + kb * 8);
        d[0] = wlo;
        d[1] = whi;
    }
    __syncthreads();

    const int lane = tid & 31;
    const int w    = tid >> 5;
    const int g = lane >> 2;
    const int t = lane & 3;

    float acc[NT][4];
    #pragma unroll
    for (int nt = 0; nt < NT; nt++)
        #pragma unroll
        for (int k = 0; k < 4; k++) acc[nt][k] = 0.f;

    #pragma unroll 1
    for (int tap = 0; tap < 9; tap++) {
        const int dy = tap / 3, dx = tap % 3;
        const unsigned* ab = tile + ((w + dy) * TW + dx) * PW;
        const unsigned* wb = sw + tap * COUT * PW;
        #pragma unroll
        for (int kb = 0; kb < KC; kb++) {
            const int ko = kb * 8 + 2 * t;
            uint2 ra = *(const uint2*)(ab + g * PW + ko);
            uint2 rb = *(const uint2*)(ab + (g + 8) * PW + ko);
            #pragma unroll
            for (int nt = 0; nt < NT; nt++) {
                uint2 wv = *(const uint2*)(wb + (nt * 8 + g) * PW + ko);
                mma_bf16(acc[nt], ra.x, rb.x, ra.y, rb.y, wv.x, wv.y);
            }
        }
    }

    // epilogue -> bf16 pair-interleaved (16 words / pixel)
    const int gy = by + w;
    size_t pix0 = (size_t)((b * HH + gy) * WW + bx + g);
    unsigned* o0 = outw + pix0 * 16;
    unsigned* o1 = o0 + 8 * 16;
    #pragma unroll
    for (int nt = 0; nt < NT; nt++) {
        int oc = nt * 8 + 2 * t;
        int pairidx = nt * 4 + t;
        int word = (pairidx >> 3) * 8 + ((pairidx & 7) & 3) * 2 + ((pairidx & 7) >> 2);
        float bi0 = sb[oc], bi1 = sb[oc + 1];
        o0[word] = bf2(fmaxf(acc[nt][0] + bi0, 0.f), fmaxf(acc[nt][1] + bi1, 0.f));
        o1[word] = bf2(fmaxf(acc[nt][2] + bi0, 0.f), fmaxf(acc[nt][3] + bi1, 0.f));
    }
}

// ---------------- conv1: 32->64, tile 16x32, bf16 in/out -------------------
__global__ __launch_bounds__(512) void conv1_tc_kernel(
    const unsigned* __restrict__ in,
    const unsigned* __restrict__ wpack, const float* __restrict__ bias,
    unsigned* __restrict__ outw)
{
    constexpr int COUT = 64;
    constexpr int TX = 16, TY = 32;
    constexpr int TW = TX + 2, TH = TY + 2;
    constexpr int PW = PW1;
    constexpr int NT = COUT / 8;     // 8
    constexpr int KC = 2;            // 32ch / 16
    constexpr int TILE_W = TH * TW * PW;
    constexpr int WN = WPW_N1;

    extern __shared__ unsigned smw[];
    unsigned* tile = smw;
    unsigned* sw   = smw + TILE_W;
    float*    sb   = (float*)(sw + WN);

    const int bx = blockIdx.x * TX;
    const int by = blockIdx.y * TY;
    const int b  = blockIdx.z;
    const int tid = threadIdx.x;

    {
        const uint4* s4 = (const uint4*)wpack;
        uint4* d4 = (uint4*)sw;
        #pragma unroll 4
        for (int i = tid; i < WN / 4; i += 512) d4[i] = s4[i];
        if (tid < COUT) sb[tid] = bias[tid];
    }
    // staging: pure copy (input already bf16 pair-interleaved)
    for (int i = tid; i < TH * TW * KC; i += 512) {
        int kb = i & 1;
        int p  = i >> 1;
        int xx = p % TW;
        int yy = p / TW;
        int gx = bx + xx - 1;
        int gy = by + yy - 1;
        uint4 w0 = make_uint4(0, 0, 0, 0), w1 = w0;
        if (gx >= 0 && gx < WW && gy >= 0 && gy < HH) {
            size_t pix = (size_t)((b * HH + gy) * WW + gx);
            const uint4* s = (const uint4*)(in + pix * 16 + kb * 8);
            w0 = s[0]; w1 = s[1];
        }
        uint4* d = (uint4*)(tile + p * PW + kb * 8);
        d[0] = w0;
        d[1] = w1;
    }
    __syncthreads();

    const int lane = tid & 31;
    const int w    = tid >> 5;
    const int g = lane >> 2;
    const int t = lane & 3;

    float acc0[NT][4], acc1[NT][4];
    #pragma unroll
    for (int nt = 0; nt < NT; nt++)
        #pragma unroll
        for (int k = 0; k < 4; k++) { acc0[nt][k] = 0.f; acc1[nt][k] = 0.f; }

    #pragma unroll 1
    for (int tap = 0; tap < 9; tap++) {
        const int dy = tap / 3, dx = tap % 3;
        const unsigned* a0b = tile + ((2 * w + dy) * TW + dx) * PW;
        const unsigned* a1b = a0b + TW * PW;
        const unsigned* wb  = sw + tap * COUT * PW;
        #pragma unroll
        for (int kb = 0; kb < KC; kb++) {
            const int ko = kb * 8 + 2 * t;
            uint2 ra0 = *(const uint2*)(a0b + g * PW + ko);
            uint2 rb0 = *(const uint2*)(a0b + (g + 8) * PW + ko);
            uint2 ra1 = *(const uint2*)(a1b + g * PW + ko);
            uint2 rb1 = *(const uint2*)(a1b + (g + 8) * PW + ko);
            #pragma unroll
            for (int nt = 0; nt < NT; nt++) {
                uint2 wv = *(const uint2*)(wb + (nt * 8 + g) * PW + ko);
                mma_bf16(acc0[nt], ra0.x, rb0.x, ra0.y, rb0.y, wv.x, wv.y);
                mma_bf16(acc1[nt], ra1.x, rb1.x, ra1.y, rb1.y, wv.x, wv.y);
            }
        }
    }

    // epilogue -> bf16 pair-interleaved (32 words / pixel)
    #pragma unroll
    for (int rr = 0; rr < 2; rr++) {
        const int gy = by + 2 * w + rr;
        float (*acc)[4] = rr ? acc1 : acc0;
        size_t pix0 = (size_t)((b * HH + gy) * WW + bx + g);
        unsigned* o0 = outw + pix0 * 32;
        unsigned* o1 = o0 + 8 * 32;
        #pragma unroll
        for (int nt = 0; nt < NT; nt++) {
            int oc = nt * 8 + 2 * t;
            int pairidx = nt * 4 + t;
            int word = (pairidx >> 3) * 8 + ((pairidx & 7) & 3) * 2 + ((pairidx & 7) >> 2);
            float bi0 = sb[oc], bi1 = sb[oc + 1];
            o0[word] = bf2(fmaxf(acc[nt][0] + bi0, 0.f), fmaxf(acc[nt][1] + bi1, 0.f));
            o1[word] = bf2(fmaxf(acc[nt][2] + bi0, 0.f), fmaxf(acc[nt][3] + bi1, 0.f));
        }
    }
}

// ---------------- fused 1x1 chain via bf16 MMA -----------------------------
// 64 ->(relu) 64 ->(relu) 16 -> 2, + flow add. Input bf16 pair-interleaved.
__global__ __launch_bounds__(256) void fused1x1_bf_kernel(
    const unsigned* __restrict__ in, const float* __restrict__ flow,
    const unsigned* __restrict__ wf2, const unsigned* __restrict__ wf3,
    const float* __restrict__ b2, const float* __restrict__ b3,
    const float* __restrict__ w4, const float* __restrict__ b4,
    float* __restrict__ flowch)
{
    extern __shared__ unsigned smw[];
    unsigned* sin = smw;                   // 128*PWF
    unsigned* sw2 = sin + 128 * PWF;       // 64*PWF
    unsigned* sw3 = sw2 + 64 * PWF;        // 16*PWF
    float* sb2 = (float*)(sw3 + 16 * PWF); // 64
    float* sb3 = sb2 + 64;                 // 16
    float* sw4 = sb3 + 16;                 // 32
    float* sb4 = sw4 + 32;                 // 2

    const int tid = threadIdx.x;

    {
        const uint4* g4 = (const uint4*)(in + (size_t)blockIdx.x * 128 * 32);
        #pragma unroll 4
        for (int i = tid; i < 1024; i += 256) {
            int pix = i >> 3, off = (i & 7) * 4;
            *(uint4*)(sin + pix * PWF + off) = g4[i];
        }
    }
    {
        const uint4* s2 = (const uint4*)wf2;
        for (int i = tid; i < WPW_F2 / 4; i += 256) ((uint4*)sw2)[i] = s2[i];
        const uint4* s3 = (const uint4*)wf3;
        if (tid < WPW_F3 / 4) ((uint4*)sw3)[tid] = s3[tid];
    }
    if (tid < 64) sb2[tid] = b2[tid];
    if (tid < 16) sb3[tid] = b3[tid];
    if (tid < 32) sw4[tid] = w4[tid];
    if (tid < 2)  sb4[tid] = b4[tid];
    __syncthreads();

    const int lane = tid & 31;
    const int w = tid >> 5;
    const int g = lane >> 2;
    const int t = lane & 3;
    unsigned* arow = sin + (w * 16) * PWF;

    // ---- layer2: K=64 (4 blocks), N=64 ---------------------------------
    float acc[8][4];
    #pragma unroll
    for (int nt = 0; nt < 8; nt++)
        #pragma unroll
        for (int k = 0; k < 4; k++) acc[nt][k] = 0.f;

    #pragma unroll
    for (int kb = 0; kb < 4; kb++) {
        const int ko = kb * 8 + 2 * t;
        uint2 ra = *(const uint2*)(arow + g * PWF + ko);
        uint2 rb = *(const uint2*)(arow + (g + 8) * PWF + ko);
        #pragma unroll
        for (int nt = 0; nt < 8; nt++) {
            uint2 wv = *(const uint2*)(sw2 + (nt * 8 + g) * PWF + ko);
            mma_bf16(acc[nt], ra.x, rb.x, ra.y, rb.y, wv.x, wv.y);
        }
    }
    // bias + relu, write h back in-place as bf16 pairs (warp owns its rows)
    #pragma unroll
    for (int nt = 0; nt < 8; nt++) {
        int oc = nt * 8 + 2 * t;
        int pairidx = nt * 4 + t;
        int word = (pairidx >> 3) * 8 + ((pairidx & 7) & 3) * 2 + ((pairidx & 7) >> 2);
        float bi0 = sb2[oc], bi1 = sb2[oc + 1];
        arow[g * PWF + word] =
            bf2(fmaxf(acc[nt][0] + bi0, 0.f), fmaxf(acc[nt][1] + bi1, 0.f));
        arow[(g + 8) * PWF + word] =
            bf2(fmaxf(acc[nt][2] + bi0, 0.f), fmaxf(acc[nt][3] + bi1, 0.f));
    }
    __syncwarp();

    // ---- layer3: K=64, N=16 ---------------------------------------------
    float acc3[2][4];
    #pragma unroll
    for (int nt = 0; nt < 2; nt++)
        #pragma unroll
        for (int k = 0; k < 4; k++) acc3[nt][k] = 0.f;

    #pragma unroll
    for (int kb = 0; kb < 4; kb++) {
        const int ko = kb * 8 + 2 * t;
        uint2 ra = *(const uint2*)(arow + g * PWF + ko);
        uint2 rb = *(const uint2*)(arow + (g + 8) * PWF + ko);
        #pragma unroll
        for (int nt = 0; nt < 2; nt++) {
            uint2 wv = *(const uint2*)(sw3 + (nt * 8 + g) * PWF + ko);
            mma_bf16(acc3[nt], ra.x, rb.x, ra.y, rb.y, wv.x, wv.y);
        }
    }

    // ---- layer4: 16 -> 2 (relu(g)·w4, reduce across t-group) ------------
    float o0a = 0.f, o1a = 0.f, o0b = 0.f, o1b = 0.f;
    #pragma unroll
    for (int nt = 0; nt < 2; nt++) {
        #pragma unroll
        for (int p = 0; p < 2; p++) {
            int col = nt * 8 + 2 * t + p;
            float bi = sb3[col];
            float w0 = sw4[col * 2], w1 = sw4[col * 2 + 1];
            float va = fmaxf(acc3[nt][p] + bi, 0.f);
            float vb = fmaxf(acc3[nt][2 + p] + bi, 0.f);
            o0a = fmaf(va, w0, o0a); o1a = fmaf(va, w1, o1a);
            o0b = fmaf(vb, w0, o0b); o1b = fmaf(vb, w1, o1b);
        }
    }
    #pragma unroll
    for (int m = 1; m <= 2; m <<= 1) {
        o0a += __shfl_xor_sync(0xffffffffu, o0a, m);
        o1a += __shfl_xor_sync(0xffffffffu, o1a, m);
        o0b += __shfl_xor_sync(0xffffffffu, o0b, m);
        o1b += __shfl_xor_sync(0xffffffffu, o1b, m);
    }
    if (t == 0) {
        size_t pix0 = (size_t)blockIdx.x * 128 + w * 16 + g;
        float2 f0 = ((const float2*)flow)[pix0];
        float2 f1 = ((const float2*)flow)[pix0 + 8];
        ((float2*)flowch)[pix0]     = make_float2(f0.x + o0a + sb4[0], f0.y + o1a + sb4[1]);
        ((float2*)flowch)[pix0 + 8] = make_float2(f1.x + o0b + sb4[0], f1.y + o1b + sb4[1]);
    }
}

// ---------------- 2x bilinear upsample (jax.image.resize semantics) -------
__global__ __launch_bounds__(256) void upsample_kernel(
    const float* __restrict__ src, float* __restrict__ out)
{
    int idx = blockIdx.x * blockDim.x + threadIdx.x;
    int x = idx & 511;
    int y = (idx >> 9) & 511;
    int b = idx >> 18;
    float sy = 0.5f * (float)y - 0.25f;
    float sx = 0.5f * (float)x - 0.25f;
    float y0f = floorf(sy), x0f = floorf(sx);
    float wy = sy - y0f,    wx = sx - x0f;
    int y0 = (int)y0f, x0 = (int)x0f;
    int ya = max(y0, 0), yb = min(y0 + 1, HH - 1);
    int xa = max(x0, 0), xb = min(x0 + 1, WW - 1);
    const float2* s = (const float2*)src;
    float2 v00 = s[(b * HH + ya) * WW + xa];
    float2 v01 = s[(b * HH + ya) * WW + xb];
    float2 v10 = s[(b * HH + yb) * WW + xa];
    float2 v11 = s[(b * HH + yb) * WW + xb];
    float2 r;
    r.x = (1.f - wy) * ((1.f - wx) * v00.x + wx * v01.x)
        +        wy  * ((1.f - wx) * v10.x + wx * v11.x);
    r.y = (1.f - wy) * ((1.f - wx) * v00.y + wx * v01.y)
        +        wy  * ((1.f - wx) * v10.y + wx * v11.y);
    ((float2*)out)[idx] = r;
}

// ---------------- launch ---------------------------------------------------
extern "C" void kernel_launch(void* const* d_in, const int* in_sizes, int n_in,
                              void* d_out, int out_size)
{
    (void)in_sizes; (void)n_in; (void)out_size;
    const float* input_1 = (const float*)d_in[0];
    const float* input_2 = (const float*)d_in[1];
    const float* flow12  = (const float*)d_in[2];
    const float* flow21  = (const float*)d_in[3];
    float* out = (float*)d_out;

    unsigned *catw, *c0w, *wpack;
    float *flowch;
    cudaGetSymbolAddress((void**)&catw,   g_cat_w);
    cudaGetSymbolAddress((void**)&c0w,    g_c0_w);
    cudaGetSymbolAddress((void**)&flowch, g_flowch);
    cudaGetSymbolAddress((void**)&wpack,  g_wpack);

    const int SM_CONV0 = (18 * 18 * PW0 + WPW_N0) * 4 + 32 * 4;
    const int SM_CONV1 = (34 * 18 * PW1 + WPW_N1) * 4 + 64 * 4;
    const int SM_F1    = (128 * PWF + 64 * PWF + 16 * PWF) * 4 + (64 + 16 + 32 + 2) * 4;
    cudaFuncSetAttribute(conv0_tc_kernel,
                         cudaFuncAttributeMaxDynamicSharedMemorySize, SM_CONV0);
    cudaFuncSetAttribute(conv1_tc_kernel,
                         cudaFuncAttributeMaxDynamicSharedMemorySize, SM_CONV1);
    cudaFuncSetAttribute(fused1x1_bf_kernel,
                         cudaFuncAttributeMaxDynamicSharedMemorySize, SM_F1);

    const float* w[2][5];
    const float* bw[2][5];
    for (int dir = 0; dir < 2; dir++)
        for (int i = 0; i < 5; i++) {
            w[dir][i]  = (const float*)d_in[4 + 4 * i + 2 * dir];
            bw[dir][i] = (const float*)d_in[4 + 4 * i + 2 * dir + 1];
        }

    {
        const int total = 2 * WPW_PER;
        prepack_kernel<<<(total + 255) / 256, 256>>>(
            w[0][0], w[0][1], w[0][2], w[0][3],
            w[1][0], w[1][1], w[1][2], w[1][3], wpack);
    }

    const size_t catOff = (size_t)NPIXTOT * 32;   // words per dir
    const size_t c0Off  = (size_t)NPIXTOT * 16;
    const size_t off2   = (size_t)NPIXTOT * 2;
    const size_t warpOutSz = (size_t)NPIXTOT * 32;
    const size_t upOutSz   = (size_t)BB * 512 * 512 * 2;

    dim3 grid0(WW / 16, HH / 16, BB);
    dim3 grid1(WW / 16, HH / 32, BB);

    for (int dir = 0; dir < 2; dir++) {
        const float* src   = dir ? input_2 : input_1;
        const float* other = dir ? input_1 : input_2;
        const float* flow  = dir ? flow21  : flow12;

        unsigned* catD = catw + (size_t)dir * catOff;
        unsigned* c0D  = c0w  + (size_t)dir * c0Off;
        float*    fcD  = flowch + (size_t)dir * off2;
        const unsigned* wp0 = wpack + (size_t)dir * WPW_PER;
        const unsigned* wp1 = wp0 + WPW_N0;
        const unsigned* wf2 = wp1 + WPW_N1;
        const unsigned* wf3 = wf2 + WPW_F2;

        conv0_tc_kernel<<<grid0, 512, SM_CONV0>>>(
            other, src, flow, wp0, bw[dir][0], c0D);
        conv1_tc_kernel<<<grid1, 512, SM_CONV1>>>(c0D, wp1, bw[dir][1], catD);
        fused1x1_bf_kernel<<<NPIXTOT / 128, 256, SM_F1>>>(
            catD, flow, wf2, wf3, bw[dir][2], bw[dir][3],
            w[dir][4], bw[dir][4], fcD);
        warp_kernel<<<NPIXTOT * 8 / 256, 256>>>(src, fcD, out + (size_t)dir * warpOutSz);
        upsample_kernel<<<BB * 512 * 512 / 256, 256>>>(
            fcD, out + 2 * warpOutSz + (size_t)dir * upOutSz);
    }
}

// round 10
// speedup vs baseline: 7.8037x; 1.1078x over previous
#include <cuda_runtime.h>
#include <cuda_bf16.h>

#define BB 8
#define HH 256
#define WW 256
#define NPIXTOT (BB*HH*WW)

// ---------------- bf16 helpers ---------------------------------------------
__device__ __forceinline__ unsigned bf2(float lo, float hi) {
    __nv_bfloat162 h = __floats2bfloat162_rn(lo, hi);
    return *(unsigned*)&h;
}
__device__ __forceinline__ void mma_bf16(float* c,
    unsigned a0, unsigned a1, unsigned a2, unsigned a3,
    unsigned b0, unsigned b1)
{
    asm("mma.sync.aligned.m16n8k16.row.col.f32.bf16.bf16.f32 "
        "{%0,%1,%2,%3}, {%4,%5,%6,%7}, {%8,%9}, {%0,%1,%2,%3};"
        : "+f"(c[0]), "+f"(c[1]), "+f"(c[2]), "+f"(c[3])
        : "r"(a0), "r"(a1), "r"(a2), "r"(a3), "r"(b0), "r"(b1));
}

// Pair-interleaved k layout: within each 16-channel block, word w (0..7)
// holds channel pair q = (w>>1) + (w&1)*4. Pair q -> word (q&3)*2 + (q>>2).
// Lane t's uint2 at word 2t = pairs (t, t+4) = channels {2t,2t+1, 8+2t,8+2t+1}.

// ---------------- scratch (device globals; no allocation allowed) ----------
__device__ unsigned g_c0_w[2ull * NPIXTOT * 16];   // conv0 out, bf16 pairs (32ch)
__device__ float    g_flowch[2ull * NPIXTOT * 2];

// prepacked bf16 weights (pair-interleaved k, conflict-free pitches)
#define PW0 40
#define PW1 24
#define PWF 40
#define WPW_N0 (9*32*PW0)
#define WPW_N1 (9*64*PW1)
#define WPW_F2 (64*PWF)
#define WPW_F3 (16*PWF)
#define WPW_PER (WPW_N0 + WPW_N1 + WPW_F2 + WPW_F3)
__device__ unsigned g_wpack[2 * WPW_PER];

// ---------------- weight prepack (bf16 pairs, final smem images) -----------
__global__ void prepack_kernel(
    const float* __restrict__ c0d0, const float* __restrict__ c1d0,
    const float* __restrict__ w2d0, const float* __restrict__ w3d0,
    const float* __restrict__ c0d1, const float* __restrict__ c1d1,
    const float* __restrict__ w2d1, const float* __restrict__ w3d1,
    unsigned* __restrict__ dst)
{
    int i = blockIdx.x * blockDim.x + threadIdx.x;
    if (i >= 2 * WPW_PER) return;
    int dir = (i >= WPW_PER);
    int j = i - dir * WPW_PER;
    const float* w;
    int CIN, COUT, PW;
    if (j < WPW_N0) {
        w = dir ? c0d1 : c0d0; CIN = 64; COUT = 32; PW = PW0;
    } else if (j < WPW_N0 + WPW_N1) {
        j -= WPW_N0; w = dir ? c1d1 : c1d0; CIN = 32; COUT = 64; PW = PW1;
    } else if (j < WPW_N0 + WPW_N1 + WPW_F2) {
        j -= WPW_N0 + WPW_N1; w = dir ? w2d1 : w2d0; CIN = 64; COUT = 64; PW = PWF;
    } else {
        j -= WPW_N0 + WPW_N1 + WPW_F2; w = dir ? w3d1 : w3d0; CIN = 64; COUT = 16; PW = PWF;
    }
    int word = j % PW;
    int r    = j / PW;
    int oc   = r % COUT;
    int tap  = r / COUT;       // 0 for fc layers
    float lo = 0.f, hi = 0.f;
    int block = word >> 3, ww = word & 7;
    int q  = (ww >> 1) + (ww & 1) * 4;
    int ch = block * 16 + 2 * q;
    if (ch < CIN) {
        lo = w[(tap * CIN + ch) * COUT + oc];
        hi = w[(tap * CIN + ch + 1) * COUT + oc];
    }
    dst[i] = bf2(lo, hi);
}

// ---------------- bilinear 4-channel gather helper --------------------------
__device__ __forceinline__ float4 bilin4(const float4* s4, int base,
                                         float ay, float ax)
{
    float4 tl = s4[base];
    float4 tr = s4[base + 8];
    float4 bl = s4[base + WW * 8];
    float4 br = s4[base + WW * 8 + 8];
    float4 top, bot, r;
    top.x = tl.x + ax * (tr.x - tl.x); top.y = tl.y + ax * (tr.y - tl.y);
    top.z = tl.z + ax * (tr.z - tl.z); top.w = tl.w + ax * (tr.w - tl.w);
    bot.x = bl.x + ax * (br.x - bl.x); bot.y = bl.y + ax * (br.y - bl.y);
    bot.z = bl.z + ax * (br.z - bl.z); bot.w = bl.w + ax * (br.w - bl.w);
    r.x = top.x + ay * (bot.x - top.x); r.y = top.y + ay * (bot.y - top.y);
    r.z = top.z + ay * (bot.z - top.z); r.w = top.w + ay * (bot.w - top.w);
    return r;
}

// ---------------- conv0: 64->32, tile 16x16, fused warp+concat staging -----
__global__ __launch_bounds__(512) void conv0_tc_kernel(
    const float* __restrict__ other, const float* __restrict__ srcimg,
    const float* __restrict__ flow,
    const unsigned* __restrict__ wpack, const float* __restrict__ bias,
    unsigned* __restrict__ outw)
{
    constexpr int COUT = 32;
    constexpr int TX = 16, TY = 16;
    constexpr int TW = TX + 2, TH = TY + 2;
    constexpr int PW = PW0;
    constexpr int NT = COUT / 8;
    constexpr int KC = 4;
    constexpr int TILE_W = TH * TW * PW;
    constexpr int WN = WPW_N0;

    extern __shared__ unsigned smw[];
    unsigned* tile = smw;
    unsigned* sw   = smw + TILE_W;
    float*    sb   = (float*)(sw + WN);

    const int bx = blockIdx.x * TX;
    const int by = blockIdx.y * TY;
    const int b  = blockIdx.z;
    const int tid = threadIdx.x;

    {
        const uint4* s4 = (const uint4*)wpack;
        uint4* d4 = (uint4*)sw;
        #pragma unroll 4
        for (int i = tid; i < WN / 4; i += 512) d4[i] = s4[i];
        if (tid < COUT) sb[tid] = bias[tid];
    }
    for (int i = tid; i < TH * TW * KC; i += 512) {
        int kb = i & 3;
        int p  = i >> 2;
        int xx = p % TW;
        int yy = p / TW;
        int gx = bx + xx - 1;
        int gy = by + yy - 1;
        float4 v[4];
        v[0] = v[1] = v[2] = v[3] = make_float4(0.f, 0.f, 0.f, 0.f);
        if (gx >= 0 && gx < WW && gy >= 0 && gy < HH) {
            int pix = (b * HH + gy) * WW + gx;
            if (kb < 2) {
                const float4* s = (const float4*)other + (size_t)pix * 8 + kb * 4;
                v[0] = s[0]; v[1] = s[1]; v[2] = s[2]; v[3] = s[3];
            } else {
                float2 f = ((const float2*)flow)[pix];
                float qy = (float)gy - f.x;
                float qx = (float)gx - f.y;
                float fy = fminf(fmaxf(floorf(qy), 0.f), (float)(HH - 2));
                float fx = fminf(fmaxf(floorf(qx), 0.f), (float)(WW - 2));
                float ay = fminf(fmaxf(qy - fy, 0.f), 1.f);
                float ax = fminf(fmaxf(qx - fx, 0.f), 1.f);
                int iy = (int)fy, ix = (int)fx;
                const float4* s4 = (const float4*)srcimg;
                int base = ((b * HH + iy) * WW + ix) * 8 + (kb - 2) * 4;
                #pragma unroll
                for (int j = 0; j < 4; j++)
                    v[j] = bilin4(s4, base + j, ay, ax);
            }
        }
        uint4 wlo, whi;
        wlo.x = bf2(v[0].x, v[0].y);
        wlo.y = bf2(v[2].x, v[2].y);
        wlo.z = bf2(v[0].z, v[0].w);
        wlo.w = bf2(v[2].z, v[2].w);
        whi.x = bf2(v[1].x, v[1].y);
        whi.y = bf2(v[3].x, v[3].y);
        whi.z = bf2(v[1].z, v[1].w);
        whi.w = bf2(v[3].z, v[3].w);
        uint4* d = (uint4*)(tile + p * PW + kb * 8);
        d[0] = wlo;
        d[1] = whi;
    }
    __syncthreads();

    const int lane = tid & 31;
    const int w    = tid >> 5;
    const int g = lane >> 2;
    const int t = lane & 3;

    float acc[NT][4];
    #pragma unroll
    for (int nt = 0; nt < NT; nt++)
        #pragma unroll
        for (int k = 0; k < 4; k++) acc[nt][k] = 0.f;

    #pragma unroll 1
    for (int tap = 0; tap < 9; tap++) {
        const int dy = tap / 3, dx = tap % 3;
        const unsigned* ab = tile + ((w + dy) * TW + dx) * PW;
        const unsigned* wb = sw + tap * COUT * PW;
        #pragma unroll
        for (int kb = 0; kb < KC; kb++) {
            const int ko = kb * 8 + 2 * t;
            uint2 ra = *(const uint2*)(ab + g * PW + ko);
            uint2 rb = *(const uint2*)(ab + (g + 8) * PW + ko);
            #pragma unroll
            for (int nt = 0; nt < NT; nt++) {
                uint2 wv = *(const uint2*)(wb + (nt * 8 + g) * PW + ko);
                mma_bf16(acc[nt], ra.x, rb.x, ra.y, rb.y, wv.x, wv.y);
            }
        }
    }

    const int gy = by + w;
    size_t pix0 = (size_t)((b * HH + gy) * WW + bx + g);
    unsigned* o0 = outw + pix0 * 16;
    unsigned* o1 = o0 + 8 * 16;
    #pragma unroll
    for (int nt = 0; nt < NT; nt++) {
        int oc = nt * 8 + 2 * t;
        int pairidx = nt * 4 + t;
        int word = (pairidx >> 3) * 8 + ((pairidx & 7) & 3) * 2 + ((pairidx & 7) >> 2);
        float bi0 = sb[oc], bi1 = sb[oc + 1];
        o0[word] = bf2(fmaxf(acc[nt][0] + bi0, 0.f), fmaxf(acc[nt][1] + bi1, 0.f));
        o1[word] = bf2(fmaxf(acc[nt][2] + bi0, 0.f), fmaxf(acc[nt][3] + bi1, 0.f));
    }
}

// ---------------- MEGA kernel: conv1 + 1x1 chain + flow add + final warp ---
// conv1 (32->64) via bf16 MMA; its D-fragments chain directly (registers) into
// layer2 (64->64), layer3 (64->16), layer4 (16->2); then flowch write and the
// final 32-ch bilinear warp, all per-warp in one pass.
__global__ __launch_bounds__(512) void conv1_mega_kernel(
    const unsigned* __restrict__ in,          // c0, bf16 pair-interleaved
    const float* __restrict__ flow,
    const float* __restrict__ srcimg,
    const unsigned* __restrict__ wp1,
    const unsigned* __restrict__ wf2, const unsigned* __restrict__ wf3,
    const float* __restrict__ b1, const float* __restrict__ b2,
    const float* __restrict__ b3,
    const float* __restrict__ w4, const float* __restrict__ b4,
    float* __restrict__ outWarped, float* __restrict__ flowch)
{
    constexpr int COUT = 64;
    constexpr int TX = 16, TY = 32;
    constexpr int TW = TX + 2, TH = TY + 2;
    constexpr int PW = PW1;
    constexpr int NT = COUT / 8;     // 8
    constexpr int KC = 2;
    constexpr int TILE_W = TH * TW * PW;   // 14688 words

    extern __shared__ unsigned smw[];
    unsigned* tile = smw;
    unsigned* sw1  = smw + TILE_W;               // WPW_N1
    unsigned* sw2  = sw1 + WPW_N1;               // WPW_F2
    unsigned* sw3  = sw2 + WPW_F2;               // WPW_F3
    float*    sb1  = (float*)(sw3 + WPW_F3);     // 64
    float*    sb2  = sb1 + 64;                   // 64
    float*    sb3  = sb2 + 64;                   // 16
    float*    sw4f = sb3 + 16;                   // 32
    float*    sb4  = sw4f + 32;                  // 2

    const int bx = blockIdx.x * TX;
    const int by = blockIdx.y * TY;
    const int b  = blockIdx.z;
    const int tid = threadIdx.x;

    {
        const uint4* s4 = (const uint4*)wp1;
        uint4* d4 = (uint4*)sw1;
        #pragma unroll 4
        for (int i = tid; i < WPW_N1 / 4; i += 512) d4[i] = s4[i];
        const uint4* f2 = (const uint4*)wf2;
        uint4* e2 = (uint4*)sw2;
        for (int i = tid; i < WPW_F2 / 4; i += 512) e2[i] = f2[i];
        const uint4* f3 = (const uint4*)wf3;
        uint4* e3 = (uint4*)sw3;
        if (tid < WPW_F3 / 4) e3[tid] = f3[tid];
        if (tid < 64) sb1[tid] = b1[tid];
        if (tid < 64) sb2[tid] = b2[tid];
        if (tid < 16) sb3[tid] = b3[tid];
        if (tid < 32) sw4f[tid] = w4[tid];
        if (tid < 2)  sb4[tid] = b4[tid];
    }
    // tile staging: pure copy (input already bf16 pair-interleaved)
    for (int i = tid; i < TH * TW * KC; i += 512) {
        int kb = i & 1;
        int p  = i >> 1;
        int xx = p % TW;
        int yy = p / TW;
        int gx = bx + xx - 1;
        int gy = by + yy - 1;
        uint4 w0 = make_uint4(0, 0, 0, 0), w1 = w0;
        if (gx >= 0 && gx < WW && gy >= 0 && gy < HH) {
            size_t pix = (size_t)((b * HH + gy) * WW + gx);
            const uint4* s = (const uint4*)(in + pix * 16 + kb * 8);
            w0 = s[0]; w1 = s[1];
        }
        uint4* d = (uint4*)(tile + p * PW + kb * 8);
        d[0] = w0;
        d[1] = w1;
    }
    __syncthreads();

    const int lane = tid & 31;
    const int w    = tid >> 5;     // warp = rows 2w, 2w+1
    const int g = lane >> 2;
    const int t = lane & 3;

    float acc0[NT][4], acc1[NT][4];
    #pragma unroll
    for (int nt = 0; nt < NT; nt++)
        #pragma unroll
        for (int k = 0; k < 4; k++) { acc0[nt][k] = 0.f; acc1[nt][k] = 0.f; }

    #pragma unroll 1
    for (int tap = 0; tap < 9; tap++) {
        const int dy = tap / 3, dx = tap % 3;
        const unsigned* a0b = tile + ((2 * w + dy) * TW + dx) * PW;
        const unsigned* a1b = a0b + TW * PW;
        const unsigned* wb  = sw1 + tap * COUT * PW;
        #pragma unroll
        for (int kb = 0; kb < KC; kb++) {
            const int ko = kb * 8 + 2 * t;
            uint2 ra0 = *(const uint2*)(a0b + g * PW + ko);
            uint2 rb0 = *(const uint2*)(a0b + (g + 8) * PW + ko);
            uint2 ra1 = *(const uint2*)(a1b + g * PW + ko);
            uint2 rb1 = *(const uint2*)(a1b + (g + 8) * PW + ko);
            #pragma unroll
            for (int nt = 0; nt < NT; nt++) {
                uint2 wv = *(const uint2*)(wb + (nt * 8 + g) * PW + ko);
                mma_bf16(acc0[nt], ra0.x, rb0.x, ra0.y, rb0.y, wv.x, wv.y);
                mma_bf16(acc1[nt], ra1.x, rb1.x, ra1.y, rb1.y, wv.x, wv.y);
            }
        }
    }

    // ---- chain: per row-tile, D-fragments -> A-fragments in registers ----
    #pragma unroll
    for (int rr = 0; rr < 2; rr++) {
        float (*acc)[4] = rr ? acc1 : acc0;

        // layer2 A fragments: bias+relu+bf16 (conv1 output, never hits memory)
        unsigned afr[4][4];
        #pragma unroll
        for (int kb = 0; kb < 4; kb++) {
            int oc0 = kb * 16 + 2 * t;
            int oc1 = oc0 + 8;
            float b00 = sb1[oc0], b01 = sb1[oc0 + 1];
            float b10 = sb1[oc1], b11 = sb1[oc1 + 1];
            afr[kb][0] = bf2(fmaxf(acc[2*kb][0]+b00, 0.f), fmaxf(acc[2*kb][1]+b01, 0.f));
            afr[kb][1] = bf2(fmaxf(acc[2*kb][2]+b00, 0.f), fmaxf(acc[2*kb][3]+b01, 0.f));
            afr[kb][2] = bf2(fmaxf(acc[2*kb+1][0]+b10, 0.f), fmaxf(acc[2*kb+1][1]+b11, 0.f));
            afr[kb][3] = bf2(fmaxf(acc[2*kb+1][2]+b10, 0.f), fmaxf(acc[2*kb+1][3]+b11, 0.f));
        }
        // layer2: K=64, N=64
        float hacc[8][4];
        #pragma unroll
        for (int nt = 0; nt < 8; nt++)
            #pragma unroll
            for (int k = 0; k < 4; k++) hacc[nt][k] = 0.f;
        #pragma unroll
        for (int kb = 0; kb < 4; kb++) {
            const int ko = kb * 8 + 2 * t;
            #pragma unroll
            for (int nt = 0; nt < 8; nt++) {
                uint2 wv = *(const uint2*)(sw2 + (nt * 8 + g) * PWF + ko);
                mma_bf16(hacc[nt], afr[kb][0], afr[kb][1], afr[kb][2], afr[kb][3],
                         wv.x, wv.y);
            }
        }
        // layer3 A fragments
        unsigned hfr[4][4];
        #pragma unroll
        for (int kb = 0; kb < 4; kb++) {
            int oc0 = kb * 16 + 2 * t;
            int oc1 = oc0 + 8;
            float b00 = sb2[oc0], b01 = sb2[oc0 + 1];
            float b10 = sb2[oc1], b11 = sb2[oc1 + 1];
            hfr[kb][0] = bf2(fmaxf(hacc[2*kb][0]+b00, 0.f), fmaxf(hacc[2*kb][1]+b01, 0.f));
            hfr[kb][1] = bf2(fmaxf(hacc[2*kb][2]+b00, 0.f), fmaxf(hacc[2*kb][3]+b01, 0.f));
            hfr[kb][2] = bf2(fmaxf(hacc[2*kb+1][0]+b10, 0.f), fmaxf(hacc[2*kb+1][1]+b11, 0.f));
            hfr[kb][3] = bf2(fmaxf(hacc[2*kb+1][2]+b10, 0.f), fmaxf(hacc[2*kb+1][3]+b11, 0.f));
        }
        // layer3: K=64, N=16
        float g3[2][4];
        #pragma unroll
        for (int nt = 0; nt < 2; nt++)
            #pragma unroll
            for (int k = 0; k < 4; k++) g3[nt][k] = 0.f;
        #pragma unroll
        for (int kb = 0; kb < 4; kb++) {
            const int ko = kb * 8 + 2 * t;
            #pragma unroll
            for (int nt = 0; nt < 2; nt++) {
                uint2 wv = *(const uint2*)(sw3 + (nt * 8 + g) * PWF + ko);
                mma_bf16(g3[nt], hfr[kb][0], hfr[kb][1], hfr[kb][2], hfr[kb][3],
                         wv.x, wv.y);
            }
        }
        // layer4: 16 -> 2 with xor-reduce (all 4 t-lanes end with the sums)
        float o0a = 0.f, o1a = 0.f, o0b = 0.f, o1b = 0.f;
        #pragma unroll
        for (int nt = 0; nt < 2; nt++) {
            #pragma unroll
            for (int p = 0; p < 2; p++) {
                int col = nt * 8 + 2 * t + p;
                float bi = sb3[col];
                float w0 = sw4f[col * 2], w1 = sw4f[col * 2 + 1];
                float va = fmaxf(g3[nt][p] + bi, 0.f);
                float vb = fmaxf(g3[nt][2 + p] + bi, 0.f);
                o0a = fmaf(va, w0, o0a); o1a = fmaf(va, w1, o1a);
                o0b = fmaf(vb, w0, o0b); o1b = fmaf(vb, w1, o1b);
            }
        }
        #pragma unroll
        for (int m = 1; m <= 2; m <<= 1) {
            o0a += __shfl_xor_sync(0xffffffffu, o0a, m);
            o1a += __shfl_xor_sync(0xffffffffu, o1a, m);
            o0b += __shfl_xor_sync(0xffffffffu, o0b, m);
            o1b += __shfl_xor_sync(0xffffffffu, o1b, m);
        }

        // flowch + inline final warp
        const int gy = by + 2 * w + rr;
        const int xA = bx + g, xB = xA + 8;
        size_t pixA = (size_t)((b * HH + gy) * WW + xA);
        size_t pixB = pixA + 8;
        float2 fA = ((const float2*)flow)[pixA];
        float2 fB = ((const float2*)flow)[pixB];
        float fcAx = fA.x + o0a + sb4[0], fcAy = fA.y + o1a + sb4[1];
        float fcBx = fB.x + o0b + sb4[0], fcBy = fB.y + o1b + sb4[1];
        if (t == 0) {
            ((float2*)flowch)[pixA] = make_float2(fcAx, fcAy);
            ((float2*)flowch)[pixB] = make_float2(fcBx, fcBy);
        }
        // bilinear sample params for both pixels
        float qyA = (float)gy - fcAx, qxA = (float)xA - fcAy;
        float fyA = fminf(fmaxf(floorf(qyA), 0.f), (float)(HH - 2));
        float fxA = fminf(fmaxf(floorf(qxA), 0.f), (float)(WW - 2));
        float ayA = fminf(fmaxf(qyA - fyA, 0.f), 1.f);
        float axA = fminf(fmaxf(qxA - fxA, 0.f), 1.f);
        int baseA = ((b * HH + (int)fyA) * WW + (int)fxA) * 8;

        float qyB = (float)gy - fcBx, qxB = (float)xB - fcBy;
        float fyB = fminf(fmaxf(floorf(qyB), 0.f), (float)(HH - 2));
        float fxB = fminf(fmaxf(floorf(qxB), 0.f), (float)(WW - 2));
        float ayB = fminf(fmaxf(qyB - fyB, 0.f), 1.f);
        float axB = fminf(fmaxf(qxB - fxB, 0.f), 1.f);
        int baseB = ((b * HH + (int)fyB) * WW + (int)fxB) * 8;

        const float4* s4 = (const float4*)srcimg;
        float4* oA = (float4*)outWarped + pixA * 8;
        float4* oB = (float4*)outWarped + pixB * 8;
        #pragma unroll
        for (int cc = 0; cc < 2; cc++) {
            int c4 = t * 2 + cc;
            oA[c4] = bilin4(s4, baseA + c4, ayA, axA);
            oB[c4] = bilin4(s4, baseB + c4, ayB, axB);
        }
    }
}

// ---------------- 2x bilinear upsample (jax.image.resize semantics) -------
__global__ __launch_bounds__(256) void upsample_kernel(
    const float* __restrict__ src, float* __restrict__ out)
{
    int idx = blockIdx.x * blockDim.x + threadIdx.x;
    int x = idx & 511;
    int y = (idx >> 9) & 511;
    int b = idx >> 18;
    float sy = 0.5f * (float)y - 0.25f;
    float sx = 0.5f * (float)x - 0.25f;
    float y0f = floorf(sy), x0f = floorf(sx);
    float wy = sy - y0f,    wx = sx - x0f;
    int y0 = (int)y0f, x0 = (int)x0f;
    int ya = max(y0, 0), yb = min(y0 + 1, HH - 1);
    int xa = max(x0, 0), xb = min(x0 + 1, WW - 1);
    const float2* s = (const float2*)src;
    float2 v00 = s[(b * HH + ya) * WW + xa];
    float2 v01 = s[(b * HH + ya) * WW + xb];
    float2 v10 = s[(b * HH + yb) * WW + xa];
    float2 v11 = s[(b * HH + yb) * WW + xb];
    float2 r;
    r.x = (1.f - wy) * ((1.f - wx) * v00.x + wx * v01.x)
        +        wy  * ((1.f - wx) * v10.x + wx * v11.x);
    r.y = (1.f - wy) * ((1.f - wx) * v00.y + wx * v01.y)
        +        wy  * ((1.f - wx) * v10.y + wx * v11.y);
    ((float2*)out)[idx] = r;
}

// ---------------- launch ---------------------------------------------------
extern "C" void kernel_launch(void* const* d_in, const int* in_sizes, int n_in,
                              void* d_out, int out_size)
{
    (void)in_sizes; (void)n_in; (void)out_size;
    const float* input_1 = (const float*)d_in[0];
    const float* input_2 = (const float*)d_in[1];
    const float* flow12  = (const float*)d_in[2];
    const float* flow21  = (const float*)d_in[3];
    float* out = (float*)d_out;

    unsigned *c0w, *wpack;
    float *flowch;
    cudaGetSymbolAddress((void**)&c0w,    g_c0_w);
    cudaGetSymbolAddress((void**)&flowch, g_flowch);
    cudaGetSymbolAddress((void**)&wpack,  g_wpack);

    const int SM_CONV0 = (18 * 18 * PW0 + WPW_N0) * 4 + 32 * 4;
    const int SM_MEGA  = (34 * 18 * PW1 + WPW_N1 + WPW_F2 + WPW_F3) * 4
                         + (64 + 64 + 16 + 32 + 2) * 4;
    cudaFuncSetAttribute(conv0_tc_kernel,
                         cudaFuncAttributeMaxDynamicSharedMemorySize, SM_CONV0);
    cudaFuncSetAttribute(conv1_mega_kernel,
                         cudaFuncAttributeMaxDynamicSharedMemorySize, SM_MEGA);

    const float* w[2][5];
    const float* bw[2][5];
    for (int dir = 0; dir < 2; dir++)
        for (int i = 0; i < 5; i++) {
            w[dir][i]  = (const float*)d_in[4 + 4 * i + 2 * dir];
            bw[dir][i] = (const float*)d_in[4 + 4 * i + 2 * dir + 1];
        }

    {
        const int total = 2 * WPW_PER;
        prepack_kernel<<<(total + 255) / 256, 256>>>(
            w[0][0], w[0][1], w[0][2], w[0][3],
            w[1][0], w[1][1], w[1][2], w[1][3], wpack);
    }

    const size_t c0Off = (size_t)NPIXTOT * 16;
    const size_t off2  = (size_t)NPIXTOT * 2;
    const size_t warpOutSz = (size_t)NPIXTOT * 32;
    const size_t upOutSz   = (size_t)BB * 512 * 512 * 2;

    dim3 grid0(WW / 16, HH / 16, BB);
    dim3 grid1(WW / 16, HH / 32, BB);

    for (int dir = 0; dir < 2; dir++) {
        const float* src   = dir ? input_2 : input_1;
        const float* other = dir ? input_1 : input_2;
        const float* flow  = dir ? flow21  : flow12;

        unsigned* c0D = c0w + (size_t)dir * c0Off;
        float*    fcD = flowch + (size_t)dir * off2;
        const unsigned* wp0 = wpack + (size_t)dir * WPW_PER;
        const unsigned* wp1 = wp0 + WPW_N0;
        const unsigned* wf2 = wp1 + WPW_N1;
        const unsigned* wf3 = wf2 + WPW_F2;

        conv0_tc_kernel<<<grid0, 512, SM_CONV0>>>(
            other, src, flow, wp0, bw[dir][0], c0D);
        conv1_mega_kernel<<<grid1, 512, SM_MEGA>>>(
            c0D, flow, src, wp1, wf2, wf3,
            bw[dir][1], bw[dir][2], bw[dir][3], w[dir][4], bw[dir][4],
            out + (size_t)dir * warpOutSz, fcD);
        upsample_kernel<<<BB * 512 * 512 / 256, 256>>>(
            fcD, out + 2 * warpOutSz + (size_t)dir * upOutSz);
    }
}

// round 11
// speedup vs baseline: 8.3563x; 1.0708x over previous
#include <cuda_runtime.h>
#include <cuda_bf16.h>

#define BB 8
#define HH 256
#define WW 256
#define NPIXTOT (BB*HH*WW)

// ---------------- bf16 helpers ---------------------------------------------
__device__ __forceinline__ unsigned bf2(float lo, float hi) {
    __nv_bfloat162 h = __floats2bfloat162_rn(lo, hi);
    return *(unsigned*)&h;
}
__device__ __forceinline__ void mma_bf16(float* c,
    unsigned a0, unsigned a1, unsigned a2, unsigned a3,
    unsigned b0, unsigned b1)
{
    asm("mma.sync.aligned.m16n8k16.row.col.f32.bf16.bf16.f32 "
        "{%0,%1,%2,%3}, {%4,%5,%6,%7}, {%8,%9}, {%0,%1,%2,%3};"
        : "+f"(c[0]), "+f"(c[1]), "+f"(c[2]), "+f"(c[3])
        : "r"(a0), "r"(a1), "r"(a2), "r"(a3), "r"(b0), "r"(b1));
}

// Pair-interleaved k layout: within each 16-channel block, word w (0..7)
// holds channel pair q = (w>>1) + (w&1)*4. Pair q -> word (q&3)*2 + (q>>2).

// ---------------- scratch (device globals; no allocation allowed) ----------
__device__ unsigned g_c0_w[2ull * NPIXTOT * 16];   // conv0 out, bf16 pairs
__device__ float    g_flowch[2ull * NPIXTOT * 2];

#define PW0 40
#define PW1 24
#define PWF 40
#define WPW_N0 (9*32*PW0)
#define WPW_N1 (9*64*PW1)
#define WPW_F2 (64*PWF)
#define WPW_F3 (16*PWF)
#define WPW_PER (WPW_N0 + WPW_N1 + WPW_F2 + WPW_F3)
__device__ unsigned g_wpack[2 * WPW_PER];
// biases per dir: [b0 32][b1 64][b2 64][b3 16][w4 32][b4 2] -> 256-pad
#define BP_PER 256
__device__ float g_bpack[2 * BP_PER];

// ---------------- weight prepack (bf16 pairs, final smem images) -----------
__global__ void prepack_kernel(
    const float* __restrict__ c0d0, const float* __restrict__ c1d0,
    const float* __restrict__ w2d0, const float* __restrict__ w3d0,
    const float* __restrict__ c0d1, const float* __restrict__ c1d1,
    const float* __restrict__ w2d1, const float* __restrict__ w3d1,
    unsigned* __restrict__ dst)
{
    int i = blockIdx.x * blockDim.x + threadIdx.x;
    if (i >= 2 * WPW_PER) return;
    int dir = (i >= WPW_PER);
    int j = i - dir * WPW_PER;
    const float* w;
    int CIN, COUT, PW;
    if (j < WPW_N0) {
        w = dir ? c0d1 : c0d0; CIN = 64; COUT = 32; PW = PW0;
    } else if (j < WPW_N0 + WPW_N1) {
        j -= WPW_N0; w = dir ? c1d1 : c1d0; CIN = 32; COUT = 64; PW = PW1;
    } else if (j < WPW_N0 + WPW_N1 + WPW_F2) {
        j -= WPW_N0 + WPW_N1; w = dir ? w2d1 : w2d0; CIN = 64; COUT = 64; PW = PWF;
    } else {
        j -= WPW_N0 + WPW_N1 + WPW_F2; w = dir ? w3d1 : w3d0; CIN = 64; COUT = 16; PW = PWF;
    }
    int word = j % PW;
    int r    = j / PW;
    int oc   = r % COUT;
    int tap  = r / COUT;
    float lo = 0.f, hi = 0.f;
    int block = word >> 3, ww = word & 7;
    int q  = (ww >> 1) + (ww & 1) * 4;
    int ch = block * 16 + 2 * q;
    if (ch < CIN) {
        lo = w[(tap * CIN + ch) * COUT + oc];
        hi = w[(tap * CIN + ch + 1) * COUT + oc];
    }
    dst[i] = bf2(lo, hi);
}

__global__ void biaspack_kernel(
    const float* __restrict__ b0d0, const float* __restrict__ b1d0,
    const float* __restrict__ b2d0, const float* __restrict__ b3d0,
    const float* __restrict__ w4d0, const float* __restrict__ b4d0,
    const float* __restrict__ b0d1, const float* __restrict__ b1d1,
    const float* __restrict__ b2d1, const float* __restrict__ b3d1,
    const float* __restrict__ w4d1, const float* __restrict__ b4d1,
    float* __restrict__ dst)
{
    int i = threadIdx.x;                 // 0..255
    int dir = blockIdx.x;                // 0..1
    const float* srcs[6] = {
        dir ? b0d1 : b0d0, dir ? b1d1 : b1d0, dir ? b2d1 : b2d0,
        dir ? b3d1 : b3d0, dir ? w4d1 : w4d0, dir ? b4d1 : b4d0 };
    const int offs[7] = {0, 32, 96, 160, 176, 208, 210};
    float v = 0.f;
    #pragma unroll
    for (int s = 0; s < 6; s++)
        if (i >= offs[s] && i < offs[s + 1]) v = srcs[s][i - offs[s]];
    dst[dir * BP_PER + i] = v;
}

// ---------------- bilinear 4-channel gather helper --------------------------
__device__ __forceinline__ float4 bilin4(const float4* s4, int base,
                                         float ay, float ax)
{
    float4 tl = s4[base];
    float4 tr = s4[base + 8];
    float4 bl = s4[base + WW * 8];
    float4 br = s4[base + WW * 8 + 8];
    float4 top, bot, r;
    top.x = tl.x + ax * (tr.x - tl.x); top.y = tl.y + ax * (tr.y - tl.y);
    top.z = tl.z + ax * (tr.z - tl.z); top.w = tl.w + ax * (tr.w - tl.w);
    bot.x = bl.x + ax * (br.x - bl.x); bot.y = bl.y + ax * (br.y - bl.y);
    bot.z = bl.z + ax * (br.z - bl.z); bot.w = bl.w + ax * (br.w - bl.w);
    r.x = top.x + ay * (bot.x - top.x); r.y = top.y + ay * (bot.y - top.y);
    r.z = top.z + ay * (bot.z - top.z); r.w = top.w + ay * (bot.w - top.w);
    return r;
}

// ---------------- conv0: 64->32, tile 16x16, 256 thr, M=32/warp ------------
__global__ __launch_bounds__(256, 2) void conv0_tc_kernel(
    const float* __restrict__ input_1, const float* __restrict__ input_2,
    const float* __restrict__ flow12, const float* __restrict__ flow21,
    const unsigned* __restrict__ wpackg, const float* __restrict__ bpackg,
    unsigned* __restrict__ c0wg)
{
    constexpr int COUT = 32;
    constexpr int TX = 16, TY = 16;
    constexpr int TW = TX + 2, TH = TY + 2;
    constexpr int PW = PW0;
    constexpr int NT = COUT / 8;     // 4
    constexpr int KC = 4;
    constexpr int TILE_W = TH * TW * PW;
    constexpr int WN = WPW_N0;

    extern __shared__ unsigned smw[];
    unsigned* tile = smw;
    unsigned* sw   = smw + TILE_W;
    float*    sb   = (float*)(sw + WN);

    const int dir = blockIdx.z >> 3;
    const int b   = blockIdx.z & 7;
    const float* other = dir ? input_1 : input_2;
    const float* srcimg = dir ? input_2 : input_1;
    const float* flow = dir ? flow21 : flow12;
    const unsigned* wpack = wpackg + (size_t)dir * WPW_PER;
    const float* bias = bpackg + dir * BP_PER;
    unsigned* outw = c0wg + (size_t)dir * NPIXTOT * 16;

    const int bx = blockIdx.x * TX;
    const int by = blockIdx.y * TY;
    const int tid = threadIdx.x;

    {
        const uint4* s4 = (const uint4*)wpack;
        uint4* d4 = (uint4*)sw;
        #pragma unroll 4
        for (int i = tid; i < WN / 4; i += 256) d4[i] = s4[i];
        if (tid < COUT) sb[tid] = bias[tid];
    }
    for (int i = tid; i < TH * TW * KC; i += 256) {
        int kb = i & 3;
        int p  = i >> 2;
        int xx = p % TW;
        int yy = p / TW;
        int gx = bx + xx - 1;
        int gy = by + yy - 1;
        float4 v[4];
        v[0] = v[1] = v[2] = v[3] = make_float4(0.f, 0.f, 0.f, 0.f);
        if (gx >= 0 && gx < WW && gy >= 0 && gy < HH) {
            int pix = (b * HH + gy) * WW + gx;
            if (kb < 2) {
                const float4* s = (const float4*)other + (size_t)pix * 8 + kb * 4;
                v[0] = s[0]; v[1] = s[1]; v[2] = s[2]; v[3] = s[3];
            } else {
                float2 f = ((const float2*)flow)[pix];
                float qy = (float)gy - f.x;
                float qx = (float)gx - f.y;
                float fy = fminf(fmaxf(floorf(qy), 0.f), (float)(HH - 2));
                float fx = fminf(fmaxf(floorf(qx), 0.f), (float)(WW - 2));
                float ay = fminf(fmaxf(qy - fy, 0.f), 1.f);
                float ax = fminf(fmaxf(qx - fx, 0.f), 1.f);
                int iy = (int)fy, ix = (int)fx;
                const float4* s4 = (const float4*)srcimg;
                int base = ((b * HH + iy) * WW + ix) * 8 + (kb - 2) * 4;
                #pragma unroll
                for (int j = 0; j < 4; j++)
                    v[j] = bilin4(s4, base + j, ay, ax);
            }
        }
        uint4 wlo, whi;
        wlo.x = bf2(v[0].x, v[0].y);
        wlo.y = bf2(v[2].x, v[2].y);
        wlo.z = bf2(v[0].z, v[0].w);
        wlo.w = bf2(v[2].z, v[2].w);
        whi.x = bf2(v[1].x, v[1].y);
        whi.y = bf2(v[3].x, v[3].y);
        whi.z = bf2(v[1].z, v[1].w);
        whi.w = bf2(v[3].z, v[3].w);
        uint4* d = (uint4*)(tile + p * PW + kb * 8);
        d[0] = wlo;
        d[1] = whi;
    }
    __syncthreads();

    const int lane = tid & 31;
    const int w    = tid >> 5;     // warp = rows 2w, 2w+1
    const int g = lane >> 2;
    const int t = lane & 3;

    float acc0[NT][4], acc1[NT][4];
    #pragma unroll
    for (int nt = 0; nt < NT; nt++)
        #pragma unroll
        for (int k = 0; k < 4; k++) { acc0[nt][k] = 0.f; acc1[nt][k] = 0.f; }

    #pragma unroll 1
    for (int tap = 0; tap < 9; tap++) {
        const int dy = tap / 3, dx = tap % 3;
        const unsigned* a0b = tile + ((2 * w + dy) * TW + dx) * PW;
        const unsigned* a1b = a0b + TW * PW;
        const unsigned* wb = sw + tap * COUT * PW;
        #pragma unroll
        for (int kb = 0; kb < KC; kb++) {
            const int ko = kb * 8 + 2 * t;
            uint2 ra0 = *(const uint2*)(a0b + g * PW + ko);
            uint2 rb0 = *(const uint2*)(a0b + (g + 8) * PW + ko);
            uint2 ra1 = *(const uint2*)(a1b + g * PW + ko);
            uint2 rb1 = *(const uint2*)(a1b + (g + 8) * PW + ko);
            #pragma unroll
            for (int nt = 0; nt < NT; nt++) {
                uint2 wv = *(const uint2*)(wb + (nt * 8 + g) * PW + ko);
                mma_bf16(acc0[nt], ra0.x, rb0.x, ra0.y, rb0.y, wv.x, wv.y);
                mma_bf16(acc1[nt], ra1.x, rb1.x, ra1.y, rb1.y, wv.x, wv.y);
            }
        }
    }

    #pragma unroll
    for (int rr = 0; rr < 2; rr++) {
        const int gy = by + 2 * w + rr;
        float (*acc)[4] = rr ? acc1 : acc0;
        size_t pix0 = (size_t)((b * HH + gy) * WW + bx + g);
        unsigned* o0 = outw + pix0 * 16;
        unsigned* o1 = o0 + 8 * 16;
        #pragma unroll
        for (int nt = 0; nt < NT; nt++) {
            int oc = nt * 8 + 2 * t;
            int pairidx = nt * 4 + t;
            int word = (pairidx >> 3) * 8 + ((pairidx & 7) & 3) * 2 + ((pairidx & 7) >> 2);
            float bi0 = sb[oc], bi1 = sb[oc + 1];
            o0[word] = bf2(fmaxf(acc[nt][0] + bi0, 0.f), fmaxf(acc[nt][1] + bi1, 0.f));
            o1[word] = bf2(fmaxf(acc[nt][2] + bi0, 0.f), fmaxf(acc[nt][3] + bi1, 0.f));
        }
    }
}

// ---------------- MEGA: conv1 + 1x1 chain + flow add + final warp ----------
// 256 threads, 16x16 tile, warp = rows 2w,2w+1; 2 blocks/SM.
__global__ __launch_bounds__(256, 2) void conv1_mega_kernel(
    const unsigned* __restrict__ c0wg,
    const float* __restrict__ input_1, const float* __restrict__ input_2,
    const float* __restrict__ flow12, const float* __restrict__ flow21,
    const unsigned* __restrict__ wpackg, const float* __restrict__ bpackg,
    float* __restrict__ outAll, float* __restrict__ flowchg)
{
    constexpr int COUT = 64;
    constexpr int TX = 16, TY = 16;
    constexpr int TW = TX + 2, TH = TY + 2;
    constexpr int PW = PW1;
    constexpr int NT = COUT / 8;     // 8
    constexpr int KC = 2;
    constexpr int TILE_W = TH * TW * PW;   // 7776 words

    extern __shared__ unsigned smw[];
    unsigned* tile = smw;
    unsigned* sw1  = smw + TILE_W;
    unsigned* sw2  = sw1 + WPW_N1;
    unsigned* sw3  = sw2 + WPW_F2;
    float*    sbf  = (float*)(sw3 + WPW_F3);   // 256 floats (bias pack image)

    const int dir = blockIdx.z >> 3;
    const int b   = blockIdx.z & 7;
    const float* srcimg = dir ? input_2 : input_1;
    const float* flow = dir ? flow21 : flow12;
    const unsigned* wbase = wpackg + (size_t)dir * WPW_PER;
    const unsigned* wp1 = wbase + WPW_N0;
    const unsigned* wf2 = wp1 + WPW_N1;
    const unsigned* wf3 = wf2 + WPW_F2;
    const unsigned* in = c0wg + (size_t)dir * NPIXTOT * 16;
    float* flowch = flowchg + (size_t)dir * NPIXTOT * 2;
    float* outWarped = outAll + (size_t)dir * NPIXTOT * 32;

    float* sb1  = sbf + 32;    // b1 (64)
    float* sb2  = sbf + 96;    // b2 (64)
    float* sb3  = sbf + 160;   // b3 (16)
    float* sw4f = sbf + 176;   // w4 (32)
    float* sb4  = sbf + 208;   // b4 (2)

    const int bx = blockIdx.x * TX;
    const int by = blockIdx.y * TY;
    const int tid = threadIdx.x;

    {
        const uint4* s4 = (const uint4*)wp1;
        uint4* d4 = (uint4*)sw1;
        #pragma unroll 4
        for (int i = tid; i < WPW_N1 / 4; i += 256) d4[i] = s4[i];
        const uint4* f2 = (const uint4*)wf2;
        uint4* e2 = (uint4*)sw2;
        for (int i = tid; i < WPW_F2 / 4; i += 256) e2[i] = f2[i];
        const uint4* f3 = (const uint4*)wf3;
        uint4* e3 = (uint4*)sw3;
        if (tid < WPW_F3 / 4) e3[tid] = f3[tid];
        sbf[tid] = bpackg[dir * BP_PER + tid];
    }
    for (int i = tid; i < TH * TW * KC; i += 256) {
        int kb = i & 1;
        int p  = i >> 1;
        int xx = p % TW;
        int yy = p / TW;
        int gx = bx + xx - 1;
        int gy = by + yy - 1;
        uint4 w0 = make_uint4(0, 0, 0, 0), w1 = w0;
        if (gx >= 0 && gx < WW && gy >= 0 && gy < HH) {
            size_t pix = (size_t)((b * HH + gy) * WW + gx);
            const uint4* s = (const uint4*)(in + pix * 16 + kb * 8);
            w0 = s[0]; w1 = s[1];
        }
        uint4* d = (uint4*)(tile + p * PW + kb * 8);
        d[0] = w0;
        d[1] = w1;
    }
    __syncthreads();

    const int lane = tid & 31;
    const int w    = tid >> 5;     // warp = rows 2w, 2w+1
    const int g = lane >> 2;
    const int t = lane & 3;

    float acc0[NT][4], acc1[NT][4];
    #pragma unroll
    for (int nt = 0; nt < NT; nt++)
        #pragma unroll
        for (int k = 0; k < 4; k++) { acc0[nt][k] = 0.f; acc1[nt][k] = 0.f; }

    #pragma unroll 1
    for (int tap = 0; tap < 9; tap++) {
        const int dy = tap / 3, dx = tap % 3;
        const unsigned* a0b = tile + ((2 * w + dy) * TW + dx) * PW;
        const unsigned* a1b = a0b + TW * PW;
        const unsigned* wb  = sw1 + tap * COUT * PW;
        #pragma unroll
        for (int kb = 0; kb < KC; kb++) {
            const int ko = kb * 8 + 2 * t;
            uint2 ra0 = *(const uint2*)(a0b + g * PW + ko);
            uint2 rb0 = *(const uint2*)(a0b + (g + 8) * PW + ko);
            uint2 ra1 = *(const uint2*)(a1b + g * PW + ko);
            uint2 rb1 = *(const uint2*)(a1b + (g + 8) * PW + ko);
            #pragma unroll
            for (int nt = 0; nt < NT; nt++) {
                uint2 wv = *(const uint2*)(wb + (nt * 8 + g) * PW + ko);
                mma_bf16(acc0[nt], ra0.x, rb0.x, ra0.y, rb0.y, wv.x, wv.y);
                mma_bf16(acc1[nt], ra1.x, rb1.x, ra1.y, rb1.y, wv.x, wv.y);
            }
        }
    }

    // ---- chain: D fragments -> A fragments in registers -------------------
    #pragma unroll
    for (int rr = 0; rr < 2; rr++) {
        float (*acc)[4] = rr ? acc1 : acc0;

        unsigned afr[4][4];
        #pragma unroll
        for (int kb = 0; kb < 4; kb++) {
            int oc0 = kb * 16 + 2 * t;
            int oc1 = oc0 + 8;
            float b00 = sb1[oc0], b01 = sb1[oc0 + 1];
            float b10 = sb1[oc1], b11 = sb1[oc1 + 1];
            afr[kb][0] = bf2(fmaxf(acc[2*kb][0]+b00, 0.f), fmaxf(acc[2*kb][1]+b01, 0.f));
            afr[kb][1] = bf2(fmaxf(acc[2*kb][2]+b00, 0.f), fmaxf(acc[2*kb][3]+b01, 0.f));
            afr[kb][2] = bf2(fmaxf(acc[2*kb+1][0]+b10, 0.f), fmaxf(acc[2*kb+1][1]+b11, 0.f));
            afr[kb][3] = bf2(fmaxf(acc[2*kb+1][2]+b10, 0.f), fmaxf(acc[2*kb+1][3]+b11, 0.f));
        }
        float hacc[8][4];
        #pragma unroll
        for (int nt = 0; nt < 8; nt++)
            #pragma unroll
            for (int k = 0; k < 4; k++) hacc[nt][k] = 0.f;
        #pragma unroll
        for (int kb = 0; kb < 4; kb++) {
            const int ko = kb * 8 + 2 * t;
            #pragma unroll
            for (int nt = 0; nt < 8; nt++) {
                uint2 wv = *(const uint2*)(sw2 + (nt * 8 + g) * PWF + ko);
                mma_bf16(hacc[nt], afr[kb][0], afr[kb][1], afr[kb][2], afr[kb][3],
                         wv.x, wv.y);
            }
        }
        unsigned hfr[4][4];
        #pragma unroll
        for (int kb = 0; kb < 4; kb++) {
            int oc0 = kb * 16 + 2 * t;
            int oc1 = oc0 + 8;
            float b00 = sb2[oc0], b01 = sb2[oc0 + 1];
            float b10 = sb2[oc1], b11 = sb2[oc1 + 1];
            hfr[kb][0] = bf2(fmaxf(hacc[2*kb][0]+b00, 0.f), fmaxf(hacc[2*kb][1]+b01, 0.f));
            hfr[kb][1] = bf2(fmaxf(hacc[2*kb][2]+b00, 0.f), fmaxf(hacc[2*kb][3]+b01, 0.f));
            hfr[kb][2] = bf2(fmaxf(hacc[2*kb+1][0]+b10, 0.f), fmaxf(hacc[2*kb+1][1]+b11, 0.f));
            hfr[kb][3] = bf2(fmaxf(hacc[2*kb+1][2]+b10, 0.f), fmaxf(hacc[2*kb+1][3]+b11, 0.f));
        }
        float g3[2][4];
        #pragma unroll
        for (int nt = 0; nt < 2; nt++)
            #pragma unroll
            for (int k = 0; k < 4; k++) g3[nt][k] = 0.f;
        #pragma unroll
        for (int kb = 0; kb < 4; kb++) {
            const int ko = kb * 8 + 2 * t;
            #pragma unroll
            for (int nt = 0; nt < 2; nt++) {
                uint2 wv = *(const uint2*)(sw3 + (nt * 8 + g) * PWF + ko);
                mma_bf16(g3[nt], hfr[kb][0], hfr[kb][1], hfr[kb][2], hfr[kb][3],
                         wv.x, wv.y);
            }
        }
        float o0a = 0.f, o1a = 0.f, o0b = 0.f, o1b = 0.f;
        #pragma unroll
        for (int nt = 0; nt < 2; nt++) {
            #pragma unroll
            for (int p = 0; p < 2; p++) {
                int col = nt * 8 + 2 * t + p;
                float bi = sb3[col];
                float w0 = sw4f[col * 2], w1 = sw4f[col * 2 + 1];
                float va = fmaxf(g3[nt][p] + bi, 0.f);
                float vb = fmaxf(g3[nt][2 + p] + bi, 0.f);
                o0a = fmaf(va, w0, o0a); o1a = fmaf(va, w1, o1a);
                o0b = fmaf(vb, w0, o0b); o1b = fmaf(vb, w1, o1b);
            }
        }
        #pragma unroll
        for (int m = 1; m <= 2; m <<= 1) {
            o0a += __shfl_xor_sync(0xffffffffu, o0a, m);
            o1a += __shfl_xor_sync(0xffffffffu, o1a, m);
            o0b += __shfl_xor_sync(0xffffffffu, o0b, m);
            o1b += __shfl_xor_sync(0xffffffffu, o1b, m);
        }

        const int gy = by + 2 * w + rr;
        const int xA = bx + g, xB = xA + 8;
        size_t pixA = (size_t)((b * HH + gy) * WW + xA);
        size_t pixB = pixA + 8;
        float2 fA = ((const float2*)flow)[pixA];
        float2 fB = ((const float2*)flow)[pixB];
        float fcAx = fA.x + o0a + sb4[0], fcAy = fA.y + o1a + sb4[1];
        float fcBx = fB.x + o0b + sb4[0], fcBy = fB.y + o1b + sb4[1];
        if (t == 0) {
            ((float2*)flowch)[pixA] = make_float2(fcAx, fcAy);
            ((float2*)flowch)[pixB] = make_float2(fcBx, fcBy);
        }
        float qyA = (float)gy - fcAx, qxA = (float)xA - fcAy;
        float fyA = fminf(fmaxf(floorf(qyA), 0.f), (float)(HH - 2));
        float fxA = fminf(fmaxf(floorf(qxA), 0.f), (float)(WW - 2));
        float ayA = fminf(fmaxf(qyA - fyA, 0.f), 1.f);
        float axA = fminf(fmaxf(qxA - fxA, 0.f), 1.f);
        int baseA = ((b * HH + (int)fyA) * WW + (int)fxA) * 8;

        float qyB = (float)gy - fcBx, qxB = (float)xB - fcBy;
        float fyB = fminf(fmaxf(floorf(qyB), 0.f), (float)(HH - 2));
        float fxB = fminf(fmaxf(floorf(qxB), 0.f), (float)(WW - 2));
        float ayB = fminf(fmaxf(qyB - fyB, 0.f), 1.f);
        float axB = fminf(fmaxf(qxB - fxB, 0.f), 1.f);
        int baseB = ((b * HH + (int)fyB) * WW + (int)fxB) * 8;

        const float4* s4 = (const float4*)srcimg;
        float4* oA = (float4*)outWarped + pixA * 8;
        float4* oB = (float4*)outWarped + pixB * 8;
        #pragma unroll
        for (int cc = 0; cc < 2; cc++) {
            int c4 = t * 2 + cc;
            oA[c4] = bilin4(s4, baseA + c4, ayA, axA);
            oB[c4] = bilin4(s4, baseB + c4, ayB, axB);
        }
    }
}

// ---------------- 2x bilinear upsample — both dirs in one launch ----------
__global__ __launch_bounds__(256) void upsample_kernel(
    const float* __restrict__ src, float* __restrict__ out)
{
    int idx = blockIdx.x * blockDim.x + threadIdx.x;   // 2*B*512*512
    int x = idx & 511;
    int y = (idx >> 9) & 511;
    int b = idx >> 18;          // 0..15 across both dirs (flowch contiguous)
    float sy = 0.5f * (float)y - 0.25f;
    float sx = 0.5f * (float)x - 0.25f;
    float y0f = floorf(sy), x0f = floorf(sx);
    float wy = sy - y0f,    wx = sx - x0f;
    int y0 = (int)y0f, x0 = (int)x0f;
    int ya = max(y0, 0), yb = min(y0 + 1, HH - 1);
    int xa = max(x0, 0), xb = min(x0 + 1, WW - 1);
    const float2* s = (const float2*)src;
    float2 v00 = s[(b * HH + ya) * WW + xa];
    float2 v01 = s[(b * HH + ya) * WW + xb];
    float2 v10 = s[(b * HH + yb) * WW + xa];
    float2 v11 = s[(b * HH + yb) * WW + xb];
    float2 r;
    r.x = (1.f - wy) * ((1.f - wx) * v00.x + wx * v01.x)
        +        wy  * ((1.f - wx) * v10.x + wx * v11.x);
    r.y = (1.f - wy) * ((1.f - wx) * v00.y + wx * v01.y)
        +        wy  * ((1.f - wx) * v10.y + wx * v11.y);
    ((float2*)out)[idx] = r;
}

// ---------------- launch ---------------------------------------------------
extern "C" void kernel_launch(void* const* d_in, const int* in_sizes, int n_in,
                              void* d_out, int out_size)
{
    (void)in_sizes; (void)n_in; (void)out_size;
    const float* input_1 = (const float*)d_in[0];
    const float* input_2 = (const float*)d_in[1];
    const float* flow12  = (const float*)d_in[2];
    const float* flow21  = (const float*)d_in[3];
    float* out = (float*)d_out;

    unsigned *c0w, *wpack;
    float *flowch, *bpack;
    cudaGetSymbolAddress((void**)&c0w,    g_c0_w);
    cudaGetSymbolAddress((void**)&flowch, g_flowch);
    cudaGetSymbolAddress((void**)&wpack,  g_wpack);
    cudaGetSymbolAddress((void**)&bpack,  g_bpack);

    const int SM_CONV0 = (18 * 18 * PW0 + WPW_N0) * 4 + 32 * 4;
    const int SM_MEGA  = (18 * 18 * PW1 + WPW_N1 + WPW_F2 + WPW_F3) * 4 + 256 * 4;
    cudaFuncSetAttribute(conv0_tc_kernel,
                         cudaFuncAttributeMaxDynamicSharedMemorySize, SM_CONV0);
    cudaFuncSetAttribute(conv1_mega_kernel,
                         cudaFuncAttributeMaxDynamicSharedMemorySize, SM_MEGA);

    const float* w[2][5];
    const float* bw[2][5];
    for (int dir = 0; dir < 2; dir++)
        for (int i = 0; i < 5; i++) {
            w[dir][i]  = (const float*)d_in[4 + 4 * i + 2 * dir];
            bw[dir][i] = (const float*)d_in[4 + 4 * i + 2 * dir + 1];
        }

    {
        const int total = 2 * WPW_PER;
        prepack_kernel<<<(total + 255) / 256, 256>>>(
            w[0][0], w[0][1], w[0][2], w[0][3],
            w[1][0], w[1][1], w[1][2], w[1][3], wpack);
        biaspack_kernel<<<2, 256>>>(
            bw[0][0], bw[0][1], bw[0][2], bw[0][3], w[0][4], bw[0][4],
            bw[1][0], bw[1][1], bw[1][2], bw[1][3], w[1][4], bw[1][4], bpack);
    }

    dim3 grid0(WW / 16, HH / 16, 2 * BB);
    dim3 grid1(WW / 16, HH / 16, 2 * BB);

    conv0_tc_kernel<<<grid0, 256, SM_CONV0>>>(
        input_1, input_2, flow12, flow21, wpack, bpack, c0w);
    conv1_mega_kernel<<<grid1, 256, SM_MEGA>>>(
        c0w, input_1, input_2, flow12, flow21, wpack, bpack, out, flowch);
    upsample_kernel<<<2 * BB * 512 * 512 / 256, 256>>>(
        flowch, out + 2ull * NPIXTOT * 32);
}